// round 1
// baseline (speedup 1.0000x reference)
#include <cuda_runtime.h>

#define BB 4
#define TT 4096
#define EE 1024
#define HH 128
#define MTOT (BB*TT)

#define BQ 64
#define BKV 64
#define FTHREADS 256

// fp32 scratch for projected q/k/v  (8 MB each; __device__ globals = allocation-free)
__device__ float g_kp[(size_t)MTOT*HH];
__device__ float g_qp[(size_t)MTOT*HH];
__device__ float g_vp[(size_t)MTOT*HH];

// ---------------------------------------------------------------------------
// Projection GEMM:  Y[M,128] = X[M,1024] @ W[1024,128]
// M = B*T = 16384. Tile: BM=128, BN=128, BK=16. 256 threads, 8x8 micro-tile.
// gridDim.y selects which of (k,q,v) projection this CTA computes.
// ---------------------------------------------------------------------------
__global__ __launch_bounds__(256) void proj_kernel(
    const float* __restrict__ k_in, const float* __restrict__ q_in,
    const float* __restrict__ v_in,
    const float* __restrict__ Wk, const float* __restrict__ Wq,
    const float* __restrict__ Wv)
{
    __shared__ float As[16][132];   // A^T tile: As[k][m]
    __shared__ float Bs[16][132];   // B tile:   Bs[k][n]

    const float* X; const float* W; float* Y;
    if (blockIdx.y == 0)      { X = k_in; W = Wk; Y = g_kp; }
    else if (blockIdx.y == 1) { X = q_in; W = Wq; Y = g_qp; }
    else                      { X = v_in; W = Wv; Y = g_vp; }

    const int t  = threadIdx.x;
    const int m0 = blockIdx.x * 128;
    const int tx = t & 15;
    const int ty = t >> 4;

    float acc[8][8];
    #pragma unroll
    for (int i = 0; i < 8; i++)
        #pragma unroll
        for (int j = 0; j < 8; j++) acc[i][j] = 0.f;

    for (int kt = 0; kt < EE / 16; kt++) {
        // A tile: 128 rows x 16 cols, stored transposed As[k][m]
        #pragma unroll
        for (int i = 0; i < 2; i++) {
            int linear = i * 256 + t;
            int k4 = linear & 3;          // which float4 within the 16-wide k slab
            int m  = linear >> 2;         // row
            float4 f = *(const float4*)&X[(size_t)(m0 + m) * EE + kt * 16 + k4 * 4];
            As[k4 * 4 + 0][m] = f.x;
            As[k4 * 4 + 1][m] = f.y;
            As[k4 * 4 + 2][m] = f.z;
            As[k4 * 4 + 3][m] = f.w;
        }
        // B tile: 16 rows x 128 cols
        #pragma unroll
        for (int i = 0; i < 2; i++) {
            int linear = i * 256 + t;
            int n4 = linear & 31;
            int kk = linear >> 5;
            *(float4*)&Bs[kk][n4 * 4] =
                *(const float4*)&W[(size_t)(kt * 16 + kk) * HH + n4 * 4];
        }
        __syncthreads();

        #pragma unroll
        for (int kk = 0; kk < 16; kk++) {
            float a[8], b[8];
            *(float4*)&a[0] = *(float4*)&As[kk][ty * 8];
            *(float4*)&a[4] = *(float4*)&As[kk][ty * 8 + 4];
            *(float4*)&b[0] = *(float4*)&Bs[kk][tx * 8];
            *(float4*)&b[4] = *(float4*)&Bs[kk][tx * 8 + 4];
            #pragma unroll
            for (int i = 0; i < 8; i++)
                #pragma unroll
                for (int j = 0; j < 8; j++)
                    acc[i][j] += a[i] * b[j];
        }
        __syncthreads();
    }

    #pragma unroll
    for (int i = 0; i < 8; i++) {
        #pragma unroll
        for (int j4 = 0; j4 < 2; j4++) {
            float4 o;
            o.x = acc[i][j4 * 4 + 0];
            o.y = acc[i][j4 * 4 + 1];
            o.z = acc[i][j4 * 4 + 2];
            o.w = acc[i][j4 * 4 + 3];
            *(float4*)&Y[(size_t)(m0 + ty * 8 + i) * HH + tx * 8 + j4 * 4] = o;
        }
    }
}

// ---------------------------------------------------------------------------
// Flash attention (causal, online softmax), fp32.
// One CTA = (batch b, 64-query block). Loop over kv blocks of 64.
// 256 threads. S phase: 4x4 micro-tile. PV phase: 4 rows x 8 cols per thread.
// ---------------------------------------------------------------------------
__global__ __launch_bounds__(FTHREADS) void flash_kernel(float* __restrict__ out)
{
    extern __shared__ float sm[];
    float* Qs  = sm;                         // [64][132]
    float* Ks  = sm + 64 * 132;              // [64][132]
    float* Vs  = sm + 2 * 64 * 132;          // [64][132]
    float* Ss  = sm + 3 * 64 * 132;          // [64][68]  scores -> probs
    float* m_s  = Ss + 64 * 68;              // [64]
    float* l_s  = m_s + 64;                  // [64]
    float* al_s = l_s + 64;                  // [64]

    const int t  = threadIdx.x;
    const int b  = blockIdx.y;
    const int qb = (gridDim.x - 1) - blockIdx.x;   // schedule big-work CTAs first
    const int q0 = qb * BQ;
    const int tx = t & 15;
    const int ty = t >> 4;

    const float* Qg = g_qp + (size_t)b * TT * HH;
    const float* Kg = g_kp + (size_t)b * TT * HH;
    const float* Vg = g_vp + (size_t)b * TT * HH;

    // load Q tile (64 x 128), coalesced
    #pragma unroll
    for (int i = 0; i < 8; i++) {
        int linear = i * 256 + t;
        int e4 = linear & 31;
        int r  = linear >> 5;
        *(float4*)&Qs[r * 132 + e4 * 4] =
            *(const float4*)&Qg[(size_t)(q0 + r) * HH + e4 * 4];
    }
    if (t < 64) { m_s[t] = -1e30f; l_s[t] = 0.f; }

    float o_acc[4][8];
    #pragma unroll
    for (int i = 0; i < 4; i++)
        #pragma unroll
        for (int j = 0; j < 8; j++) o_acc[i][j] = 0.f;

    const float scale = 0.088388347648318447f;  // 128^-0.5

    for (int kb = 0; kb <= qb; kb++) {
        const int k0 = kb * BKV;
        __syncthreads();   // prev PV done reading Vs/Ss (and covers Q load on iter 0)

        // load K and V tiles (64 x 128 each), coalesced
        #pragma unroll
        for (int i = 0; i < 8; i++) {
            int linear = i * 256 + t;
            int e4 = linear & 31;
            int r  = linear >> 5;
            *(float4*)&Ks[r * 132 + e4 * 4] =
                *(const float4*)&Kg[(size_t)(k0 + r) * HH + e4 * 4];
            *(float4*)&Vs[r * 132 + e4 * 4] =
                *(const float4*)&Vg[(size_t)(k0 + r) * HH + e4 * 4];
        }
        __syncthreads();

        // ---- S = Q K^T  (rows ty+16i, cols tx+16j) ----
        float s_acc[4][4];
        #pragma unroll
        for (int i = 0; i < 4; i++)
            #pragma unroll
            for (int j = 0; j < 4; j++) s_acc[i][j] = 0.f;

        #pragma unroll 8
        for (int e4 = 0; e4 < 32; e4++) {
            float4 a[4], bb[4];
            #pragma unroll
            for (int i = 0; i < 4; i++)
                a[i] = *(float4*)&Qs[(ty + 16 * i) * 132 + e4 * 4];
            #pragma unroll
            for (int j = 0; j < 4; j++)
                bb[j] = *(float4*)&Ks[(tx + 16 * j) * 132 + e4 * 4];
            #pragma unroll
            for (int i = 0; i < 4; i++)
                #pragma unroll
                for (int j = 0; j < 4; j++)
                    s_acc[i][j] += a[i].x * bb[j].x + a[i].y * bb[j].y
                                 + a[i].z * bb[j].z + a[i].w * bb[j].w;
        }

        const bool diag = (kb == qb);
        #pragma unroll
        for (int i = 0; i < 4; i++) {
            #pragma unroll
            for (int j = 0; j < 4; j++) {
                int r = ty + 16 * i;
                int c = tx + 16 * j;
                float s = s_acc[i][j] * scale;
                if (diag && (c > r)) s = -1e30f;     // causal mask
                Ss[r * 68 + c] = s;
            }
        }
        __syncthreads();

        // ---- online softmax: row r = t/4, 16-col segment per thread ----
        {
            int r  = t >> 2;
            int c0 = (t & 3) * 16;
            float vals[16];
            float mx = -1e30f;
            #pragma unroll
            for (int c = 0; c < 16; c++) {
                vals[c] = Ss[r * 68 + c0 + c];
                mx = fmaxf(mx, vals[c]);
            }
            mx = fmaxf(mx, __shfl_xor_sync(0xffffffffu, mx, 1));
            mx = fmaxf(mx, __shfl_xor_sync(0xffffffffu, mx, 2));
            float m_old = m_s[r];
            float m_new = fmaxf(m_old, mx);
            float ssum = 0.f;
            #pragma unroll
            for (int c = 0; c < 16; c++) {
                float p = __expf(vals[c] - m_new);
                Ss[r * 68 + c0 + c] = p;
                ssum += p;
            }
            ssum += __shfl_xor_sync(0xffffffffu, ssum, 1);
            ssum += __shfl_xor_sync(0xffffffffu, ssum, 2);
            if ((t & 3) == 0) {
                float alpha = __expf(m_old - m_new);
                m_s[r]  = m_new;
                l_s[r]  = l_s[r] * alpha + ssum;
                al_s[r] = alpha;
            }
        }
        __syncthreads();

        // ---- O = alpha*O + P V  (rows ty+16i, cols tx*8 .. +7) ----
        #pragma unroll
        for (int i = 0; i < 4; i++) {
            float alpha = al_s[ty + 16 * i];
            #pragma unroll
            for (int j = 0; j < 8; j++) o_acc[i][j] *= alpha;
        }
        #pragma unroll 16
        for (int kk = 0; kk < BKV; kk++) {
            float p[4];
            #pragma unroll
            for (int i = 0; i < 4; i++)
                p[i] = Ss[(ty + 16 * i) * 68 + kk];
            float4 v0 = *(float4*)&Vs[kk * 132 + tx * 8];
            float4 v1 = *(float4*)&Vs[kk * 132 + tx * 8 + 4];
            #pragma unroll
            for (int i = 0; i < 4; i++) {
                o_acc[i][0] += p[i] * v0.x;
                o_acc[i][1] += p[i] * v0.y;
                o_acc[i][2] += p[i] * v0.z;
                o_acc[i][3] += p[i] * v0.w;
                o_acc[i][4] += p[i] * v1.x;
                o_acc[i][5] += p[i] * v1.y;
                o_acc[i][6] += p[i] * v1.z;
                o_acc[i][7] += p[i] * v1.w;
            }
        }
    }

    // ---- normalize and store (l_s last written before the pre-PV sync) ----
    #pragma unroll
    for (int i = 0; i < 4; i++) {
        int r = ty + 16 * i;
        float inv = 1.f / l_s[r];
        float4 o0, o1;
        o0.x = o_acc[i][0] * inv; o0.y = o_acc[i][1] * inv;
        o0.z = o_acc[i][2] * inv; o0.w = o_acc[i][3] * inv;
        o1.x = o_acc[i][4] * inv; o1.y = o_acc[i][5] * inv;
        o1.z = o_acc[i][6] * inv; o1.w = o_acc[i][7] * inv;
        size_t base = ((size_t)b * TT + q0 + r) * HH + tx * 8;
        *(float4*)&out[base]     = o0;
        *(float4*)&out[base + 4] = o1;
    }
}

// ---------------------------------------------------------------------------
extern "C" void kernel_launch(void* const* d_in, const int* in_sizes, int n_in,
                              void* d_out, int out_size)
{
    const float* k  = (const float*)d_in[0];
    const float* q  = (const float*)d_in[1];
    const float* v  = (const float*)d_in[2];
    const float* Wk = (const float*)d_in[3];
    const float* Wq = (const float*)d_in[4];
    const float* Wv = (const float*)d_in[5];
    float* out = (float*)d_out;

    proj_kernel<<<dim3(MTOT / 128, 3), 256>>>(k, q, v, Wk, Wq, Wv);

    const size_t FLASH_SMEM = (size_t)(3 * 64 * 132 + 64 * 68 + 3 * 64) * sizeof(float);
    cudaFuncSetAttribute(flash_kernel,
                         cudaFuncAttributeMaxDynamicSharedMemorySize,
                         (int)FLASH_SMEM);
    flash_kernel<<<dim3(TT / BQ, BB), FTHREADS, FLASH_SMEM>>>(out);
}

// round 3
// speedup vs baseline: 2.8297x; 2.8297x over previous
#include <cuda_runtime.h>
#include <cuda_bf16.h>
#include <cstdint>

#define BB 4
#define TT 4096
#define EE 1024
#define HH 128
#define MTOT (BB*TT)

// split-bf16 scratch (device globals = allocation-free)
__device__ __align__(16) __nv_bfloat16 g_qh[(size_t)MTOT*HH];
__device__ __align__(16) __nv_bfloat16 g_ql[(size_t)MTOT*HH];
__device__ __align__(16) __nv_bfloat16 g_kh[(size_t)MTOT*HH];
__device__ __align__(16) __nv_bfloat16 g_kl[(size_t)MTOT*HH];
__device__ __align__(16) __nv_bfloat16 g_vh[(size_t)MTOT*HH];
__device__ __align__(16) __nv_bfloat16 g_vl[(size_t)MTOT*HH];
__device__ __align__(16) __nv_bfloat16 g_wt_hi[3*(size_t)HH*EE];   // W^T split, [p][h][e]
__device__ __align__(16) __nv_bfloat16 g_wt_lo[3*(size_t)HH*EE];

// ---------------------------------------------------------------------------
// helpers
// ---------------------------------------------------------------------------
__device__ __forceinline__ uint32_t smem_u32(const void* p) {
    uint32_t a;
    asm("{ .reg .u64 t; cvta.to.shared.u64 t, %1; cvt.u32.u64 %0, t; }" : "=r"(a) : "l"(p));
    return a;
}
__device__ __forceinline__ void ldsm4(uint32_t* r, uint32_t a) {
    asm volatile("ldmatrix.sync.aligned.m8n8.x4.shared.b16 {%0,%1,%2,%3}, [%4];"
        : "=r"(r[0]), "=r"(r[1]), "=r"(r[2]), "=r"(r[3]) : "r"(a));
}
__device__ __forceinline__ void ldsm4t(uint32_t* r, uint32_t a) {
    asm volatile("ldmatrix.sync.aligned.m8n8.x4.trans.shared.b16 {%0,%1,%2,%3}, [%4];"
        : "=r"(r[0]), "=r"(r[1]), "=r"(r[2]), "=r"(r[3]) : "r"(a));
}
__device__ __forceinline__ void mma16816(float* c, const uint32_t* a, uint32_t b0, uint32_t b1) {
    asm volatile("mma.sync.aligned.m16n8k16.row.col.f32.bf16.bf16.f32 "
        "{%0,%1,%2,%3}, {%4,%5,%6,%7}, {%8,%9}, {%0,%1,%2,%3};"
        : "+f"(c[0]), "+f"(c[1]), "+f"(c[2]), "+f"(c[3])
        : "r"(a[0]), "r"(a[1]), "r"(a[2]), "r"(a[3]), "r"(b0), "r"(b1));
}
__device__ __forceinline__ uint32_t pack_bf16(float a, float b) {
    __nv_bfloat162 h = __floats2bfloat162_rn(a, b);
    return *(uint32_t*)&h;
}

// ---------------------------------------------------------------------------
// prep_w: transpose W [E,H] -> Wt [H,E], split fp32 into bf16 hi/lo
// ---------------------------------------------------------------------------
__global__ __launch_bounds__(256) void prep_w(
    const float* __restrict__ Wk, const float* __restrict__ Wq,
    const float* __restrict__ Wv)
{
    const int p = blockIdx.y;
    const float* W = (p == 0) ? Wk : (p == 1) ? Wq : Wv;
    __nv_bfloat16* oh = g_wt_hi + (size_t)p * HH * EE;
    __nv_bfloat16* ol = g_wt_lo + (size_t)p * HH * EE;
    #pragma unroll
    for (int i = 0; i < 8; i++) {
        int idx = blockIdx.x * 2048 + i * 256 + threadIdx.x;
        int e = idx >> 7;
        int h = idx & 127;
        float w = W[idx];
        __nv_bfloat16 hi = __float2bfloat16_rn(w);
        __nv_bfloat16 lo = __float2bfloat16_rn(w - __bfloat162float(hi));
        oh[(size_t)h * EE + e] = hi;
        ol[(size_t)h * EE + e] = lo;
    }
}

// ---------------------------------------------------------------------------
// proj_hmma: Y = X[16384,1024] @ W[1024,128], split-bf16, HMMA m16n8k16.
// CTA tile 128x128, 8 warps (4 m-groups x 2 n-groups), warp tile 32x64.
// Epilogue writes Y as bf16 hi/lo pairs directly (no fp32 scratch).
// smem: A hi/lo [128][40] bf16, B hi/lo [128][40] bf16 (pad for ldmatrix).
// ---------------------------------------------------------------------------
#define PA_H 0
#define PA_L 10240
#define PB_H 20480
#define PB_L 30720
#define PROJ_SMEM 40960

__global__ __launch_bounds__(256, 2) void proj_hmma(
    const float* __restrict__ k_in, const float* __restrict__ q_in,
    const float* __restrict__ v_in)
{
    extern __shared__ char sm[];
    const uint32_t sbase = smem_u32(sm);
    const int t    = threadIdx.x;
    const int lane = t & 31;
    const int wid  = t >> 5;
    const int wm   = wid & 3;     // m group (32 rows each)
    const int wn   = wid >> 2;    // n group (64 cols each)
    const int p    = blockIdx.y;
    const int m0   = blockIdx.x * 128;

    const float* X = (p == 0) ? k_in : (p == 1) ? q_in : v_in;
    __nv_bfloat16* Yh = (p == 0) ? g_kh : (p == 1) ? g_qh : g_vh;
    __nv_bfloat16* Yl = (p == 0) ? g_kl : (p == 1) ? g_ql : g_vl;
    const __nv_bfloat16* WtH = g_wt_hi + (size_t)p * HH * EE;
    const __nv_bfloat16* WtL = g_wt_lo + (size_t)p * HH * EE;

    // per-lane ldmatrix byte offsets (row stride 80B)
    const uint32_t aoff = (uint32_t)((lane & 15) * 80 + (lane >> 4) * 16);
    const uint32_t boff = (uint32_t)((((lane & 7) | ((lane & 16) >> 1)) * 80) + (((lane >> 3) & 1) * 16));

    float acc[2][8][4];
    #pragma unroll
    for (int mb = 0; mb < 2; mb++)
        #pragma unroll
        for (int j = 0; j < 8; j++)
            #pragma unroll
            for (int i = 0; i < 4; i++) acc[mb][j][i] = 0.f;

    for (int kt = 0; kt < 32; kt++) {       // BK = 32
        __syncthreads();
        // A: 128 rows x 32 fp32 -> bf16 hi/lo
        #pragma unroll
        for (int i = 0; i < 4; i++) {
            int linear = i * 256 + t;
            int c4  = linear & 7;
            int row = linear >> 3;
            float4 f = *(const float4*)&X[(size_t)(m0 + row) * EE + kt * 32 + c4 * 4];
            __nv_bfloat162 h0 = __floats2bfloat162_rn(f.x, f.y);
            __nv_bfloat162 h1 = __floats2bfloat162_rn(f.z, f.w);
            __nv_bfloat162 l0 = __floats2bfloat162_rn(f.x - __bfloat162float(h0.x),
                                                      f.y - __bfloat162float(h0.y));
            __nv_bfloat162 l1 = __floats2bfloat162_rn(f.z - __bfloat162float(h1.x),
                                                      f.w - __bfloat162float(h1.y));
            uint2 uh; uh.x = *(uint32_t*)&h0; uh.y = *(uint32_t*)&h1;
            uint2 ul; ul.x = *(uint32_t*)&l0; ul.y = *(uint32_t*)&l1;
            *(uint2*)(sm + PA_H + row * 80 + c4 * 8) = uh;
            *(uint2*)(sm + PA_L + row * 80 + c4 * 8) = ul;
        }
        // B: Wt 128 rows x 32 bf16 (hi, lo)
        #pragma unroll
        for (int i = 0; i < 2; i++) {
            int linear = i * 256 + t;
            int c4  = linear & 3;
            int row = linear >> 2;
            *(uint4*)(sm + PB_H + row * 80 + c4 * 16) =
                *(const uint4*)&WtH[(size_t)row * EE + kt * 32 + c4 * 8];
            *(uint4*)(sm + PB_L + row * 80 + c4 * 16) =
                *(const uint4*)&WtL[(size_t)row * EE + kt * 32 + c4 * 8];
        }
        __syncthreads();

        #pragma unroll
        for (int h = 0; h < 2; h++) {       // two k16 steps
            const uint32_t kb = h * 32;     // k0*2 bytes
            uint32_t ah[2][4], al[2][4];
            #pragma unroll
            for (int mb = 0; mb < 2; mb++) {
                uint32_t ra = (wm * 32 + mb * 16) * 80 + aoff + kb;
                ldsm4(ah[mb], sbase + PA_H + ra);
                ldsm4(al[mb], sbase + PA_L + ra);
            }
            #pragma unroll
            for (int jp = 0; jp < 4; jp++) {
                uint32_t bh4[4], bl4[4];
                uint32_t rb = (wn * 64 + jp * 16) * 80 + boff + kb;
                ldsm4(bh4, sbase + PB_H + rb);
                ldsm4(bl4, sbase + PB_L + rb);
                #pragma unroll
                for (int mb = 0; mb < 2; mb++) {
                    mma16816(acc[mb][2*jp],   ah[mb], bh4[0], bh4[1]);
                    mma16816(acc[mb][2*jp],   ah[mb], bl4[0], bl4[1]);
                    mma16816(acc[mb][2*jp],   al[mb], bh4[0], bh4[1]);
                    mma16816(acc[mb][2*jp+1], ah[mb], bh4[2], bh4[3]);
                    mma16816(acc[mb][2*jp+1], ah[mb], bl4[2], bl4[3]);
                    mma16816(acc[mb][2*jp+1], al[mb], bh4[2], bh4[3]);
                }
            }
        }
    }

    // epilogue: acc -> bf16 hi/lo pairs
    const int g  = lane >> 2;
    const int q4 = lane & 3;
    #pragma unroll
    for (int mb = 0; mb < 2; mb++) {
        #pragma unroll
        for (int j = 0; j < 8; j++) {
            int gr  = m0 + wm * 32 + mb * 16 + g;
            int col = wn * 64 + j * 8 + q4 * 2;
            float c0 = acc[mb][j][0], c1 = acc[mb][j][1];
            float c2 = acc[mb][j][2], c3 = acc[mb][j][3];
            __nv_bfloat162 h01 = __floats2bfloat162_rn(c0, c1);
            __nv_bfloat162 h23 = __floats2bfloat162_rn(c2, c3);
            __nv_bfloat162 l01 = __floats2bfloat162_rn(c0 - __bfloat162float(h01.x),
                                                       c1 - __bfloat162float(h01.y));
            __nv_bfloat162 l23 = __floats2bfloat162_rn(c2 - __bfloat162float(h23.x),
                                                       c3 - __bfloat162float(h23.y));
            *(uint32_t*)&Yh[(size_t)gr * HH + col]       = *(uint32_t*)&h01;
            *(uint32_t*)&Yl[(size_t)gr * HH + col]       = *(uint32_t*)&l01;
            *(uint32_t*)&Yh[(size_t)(gr + 8) * HH + col] = *(uint32_t*)&h23;
            *(uint32_t*)&Yl[(size_t)(gr + 8) * HH + col] = *(uint32_t*)&l23;
        }
    }
}

// ---------------------------------------------------------------------------
// flash_hmma: causal flash attention, split-bf16 HMMA, register-resident P.
// CTA = (batch, 64-query block); 4 warps; warp = 16 rows x full width.
// smem: Q/K/V hi+lo tiles [64][136] bf16 (row stride 272B).
// ---------------------------------------------------------------------------
#define FS_QH 0
#define FS_QL 17408
#define FS_KH 34816
#define FS_KL 52224
#define FS_VH 69632
#define FS_VL 87040
#define FLASH_SMEM 104448

__global__ __launch_bounds__(128, 2) void flash_hmma(float* __restrict__ out)
{
    extern __shared__ char sm[];
    const uint32_t sbase = smem_u32(sm);
    const int t    = threadIdx.x;
    const int lane = t & 31;
    const int w    = t >> 5;
    const int b    = blockIdx.y;
    const int qb   = (gridDim.x - 1) - blockIdx.x;   // big-work CTAs first
    const int q0   = qb * 64;
    const size_t bT = (size_t)b * TT;

    const uint32_t aoff = (uint32_t)((lane & 15) * 272 + (lane >> 4) * 16);
    const uint32_t boff = (uint32_t)((((lane & 7) | ((lane & 16) >> 1)) * 272) + (((lane >> 3) & 1) * 16));

    // load Q hi/lo tiles once
    {
        const __nv_bfloat16* qh = g_qh + (bT + q0) * HH;
        const __nv_bfloat16* ql = g_ql + (bT + q0) * HH;
        #pragma unroll
        for (int i = 0; i < 8; i++) {
            int linear = i * 128 + t;
            int col = linear & 15;
            int row = linear >> 4;
            uint32_t so = row * 272 + col * 16;
            *(uint4*)(sm + FS_QH + so) = *(const uint4*)&qh[(size_t)row * HH + col * 8];
            *(uint4*)(sm + FS_QL + so) = *(const uint4*)&ql[(size_t)row * HH + col * 8];
        }
    }

    float o[16][4];
    #pragma unroll
    for (int j = 0; j < 16; j++)
        #pragma unroll
        for (int i = 0; i < 4; i++) o[j][i] = 0.f;
    float m0 = -1e30f, m1 = -1e30f, l0 = 0.f, l1 = 0.f;

    const float scale = 0.088388347648318447f;   // 128^-0.5
    const int g   = lane >> 2;
    const int q4  = lane & 3;
    const int rg0 = q0 + w * 16 + g;             // global row (first half)

    for (int kb = 0; kb <= qb; kb++) {
        __syncthreads();    // previous iter's ldmatrix done (also orders Q stores, iter 0)
        {
            const size_t krow = bT + (size_t)kb * 64;
            #pragma unroll
            for (int i = 0; i < 8; i++) {
                int linear = i * 128 + t;
                int col = linear & 15;
                int row = linear >> 4;
                size_t gidx = (krow + row) * HH + col * 8;
                uint32_t so = row * 272 + col * 16;
                *(uint4*)(sm + FS_KH + so) = *(const uint4*)&g_kh[gidx];
                *(uint4*)(sm + FS_KL + so) = *(const uint4*)&g_kl[gidx];
                *(uint4*)(sm + FS_VH + so) = *(const uint4*)&g_vh[gidx];
                *(uint4*)(sm + FS_VL + so) = *(const uint4*)&g_vl[gidx];
            }
        }
        __syncthreads();

        // ---- S = Q K^T (split, 3 terms) ----
        float s[8][4];
        #pragma unroll
        for (int j = 0; j < 8; j++)
            #pragma unroll
            for (int i = 0; i < 4; i++) s[j][i] = 0.f;

        #pragma unroll
        for (int k16 = 0; k16 < 8; k16++) {
            uint32_t qa_h[4], qa_l[4];
            uint32_t qr = w * 16 * 272 + aoff + k16 * 32;
            ldsm4(qa_h, sbase + FS_QH + qr);
            ldsm4(qa_l, sbase + FS_QL + qr);
            #pragma unroll
            for (int jp = 0; jp < 4; jp++) {
                uint32_t kh4[4], kl4[4];
                uint32_t kr = jp * 16 * 272 + boff + k16 * 32;
                ldsm4(kh4, sbase + FS_KH + kr);
                ldsm4(kl4, sbase + FS_KL + kr);
                mma16816(s[2*jp],   qa_h, kh4[0], kh4[1]);
                mma16816(s[2*jp],   qa_h, kl4[0], kl4[1]);
                mma16816(s[2*jp],   qa_l, kh4[0], kh4[1]);
                mma16816(s[2*jp+1], qa_h, kh4[2], kh4[3]);
                mma16816(s[2*jp+1], qa_h, kl4[2], kl4[3]);
                mma16816(s[2*jp+1], qa_l, kh4[2], kh4[3]);
            }
        }

        // ---- scale + causal mask ----
        #pragma unroll
        for (int j = 0; j < 8; j++)
            #pragma unroll
            for (int i = 0; i < 4; i++) s[j][i] *= scale;
        if (kb == qb) {
            int cbase = kb * 64 + q4 * 2;
            #pragma unroll
            for (int j = 0; j < 8; j++) {
                int c0 = cbase + j * 8;
                if (c0     > rg0)     s[j][0] = -1e30f;
                if (c0 + 1 > rg0)     s[j][1] = -1e30f;
                if (c0     > rg0 + 8) s[j][2] = -1e30f;
                if (c0 + 1 > rg0 + 8) s[j][3] = -1e30f;
            }
        }

        // ---- online softmax (rows g, g+8) ----
        float mx0 = -1e30f, mx1 = -1e30f;
        #pragma unroll
        for (int j = 0; j < 8; j++) {
            mx0 = fmaxf(mx0, fmaxf(s[j][0], s[j][1]));
            mx1 = fmaxf(mx1, fmaxf(s[j][2], s[j][3]));
        }
        mx0 = fmaxf(mx0, __shfl_xor_sync(0xffffffffu, mx0, 1));
        mx0 = fmaxf(mx0, __shfl_xor_sync(0xffffffffu, mx0, 2));
        mx1 = fmaxf(mx1, __shfl_xor_sync(0xffffffffu, mx1, 1));
        mx1 = fmaxf(mx1, __shfl_xor_sync(0xffffffffu, mx1, 2));
        float m0n = fmaxf(m0, mx0), m1n = fmaxf(m1, mx1);
        float a0 = __expf(m0 - m0n), a1 = __expf(m1 - m1n);
        m0 = m0n; m1 = m1n;

        uint32_t ph01[8], ph23[8], pl01[8], pl23[8];
        float sum0 = 0.f, sum1 = 0.f;
        #pragma unroll
        for (int j = 0; j < 8; j++) {
            float p0 = __expf(s[j][0] - m0n);
            float p1 = __expf(s[j][1] - m0n);
            float p2 = __expf(s[j][2] - m1n);
            float p3 = __expf(s[j][3] - m1n);
            sum0 += p0 + p1; sum1 += p2 + p3;
            __nv_bfloat162 h01 = __floats2bfloat162_rn(p0, p1);
            __nv_bfloat162 h23 = __floats2bfloat162_rn(p2, p3);
            ph01[j] = *(uint32_t*)&h01;
            ph23[j] = *(uint32_t*)&h23;
            pl01[j] = pack_bf16(p0 - __bfloat162float(h01.x), p1 - __bfloat162float(h01.y));
            pl23[j] = pack_bf16(p2 - __bfloat162float(h23.x), p3 - __bfloat162float(h23.y));
        }
        sum0 += __shfl_xor_sync(0xffffffffu, sum0, 1);
        sum0 += __shfl_xor_sync(0xffffffffu, sum0, 2);
        sum1 += __shfl_xor_sync(0xffffffffu, sum1, 1);
        sum1 += __shfl_xor_sync(0xffffffffu, sum1, 2);
        l0 = l0 * a0 + sum0;
        l1 = l1 * a1 + sum1;

        #pragma unroll
        for (int j = 0; j < 16; j++) {
            o[j][0] *= a0; o[j][1] *= a0;
            o[j][2] *= a1; o[j][3] *= a1;
        }

        // ---- O += P V (split, 3 terms) ----
        #pragma unroll
        for (int ks = 0; ks < 4; ks++) {
            uint32_t pah[4] = { ph01[2*ks], ph23[2*ks], ph01[2*ks+1], ph23[2*ks+1] };
            uint32_t pal[4] = { pl01[2*ks], pl23[2*ks], pl01[2*ks+1], pl23[2*ks+1] };
            #pragma unroll
            for (int hp = 0; hp < 8; hp++) {
                uint32_t vh4[4], vl4[4];
                uint32_t vr = ks * 16 * 272 + aoff + hp * 32;
                ldsm4t(vh4, sbase + FS_VH + vr);
                ldsm4t(vl4, sbase + FS_VL + vr);
                mma16816(o[2*hp],   pah, vh4[0], vh4[1]);
                mma16816(o[2*hp],   pah, vl4[0], vl4[1]);
                mma16816(o[2*hp],   pal, vh4[0], vh4[1]);
                mma16816(o[2*hp+1], pah, vh4[2], vh4[3]);
                mma16816(o[2*hp+1], pah, vl4[2], vl4[3]);
                mma16816(o[2*hp+1], pal, vh4[2], vh4[3]);
            }
        }
    }

    // ---- normalize and store ----
    float inv0 = 1.f / l0, inv1 = 1.f / l1;
    #pragma unroll
    for (int j = 0; j < 16; j++) {
        int col = j * 8 + q4 * 2;
        float2 v0 = { o[j][0] * inv0, o[j][1] * inv0 };
        float2 v1 = { o[j][2] * inv1, o[j][3] * inv1 };
        *(float2*)&out[(bT + rg0) * HH + col]     = v0;
        *(float2*)&out[(bT + rg0 + 8) * HH + col] = v1;
    }
}

// ---------------------------------------------------------------------------
extern "C" void kernel_launch(void* const* d_in, const int* in_sizes, int n_in,
                              void* d_out, int out_size)
{
    const float* k  = (const float*)d_in[0];
    const float* q  = (const float*)d_in[1];
    const float* v  = (const float*)d_in[2];
    const float* Wk = (const float*)d_in[3];
    const float* Wq = (const float*)d_in[4];
    const float* Wv = (const float*)d_in[5];
    float* out = (float*)d_out;

    prep_w<<<dim3(64, 3), 256>>>(Wk, Wq, Wv);

    proj_hmma<<<dim3(MTOT / 128, 3), 256, PROJ_SMEM>>>(k, q, v);

    cudaFuncSetAttribute(flash_hmma, cudaFuncAttributeMaxDynamicSharedMemorySize, FLASH_SMEM);
    flash_hmma<<<dim3(TT / 64, BB), 128, FLASH_SMEM>>>(out);
}

// round 4
// speedup vs baseline: 2.8406x; 1.0038x over previous
#include <cuda_runtime.h>
#include <cuda_bf16.h>
#include <cstdint>

#define BB 4
#define TT 4096
#define EE 1024
#define HH 128
#define MTOT (BB*TT)

// split-bf16 scratch (device globals = allocation-free)
__device__ __align__(16) __nv_bfloat16 g_qh[(size_t)MTOT*HH];
__device__ __align__(16) __nv_bfloat16 g_ql[(size_t)MTOT*HH];
__device__ __align__(16) __nv_bfloat16 g_kh[(size_t)MTOT*HH];
__device__ __align__(16) __nv_bfloat16 g_kl[(size_t)MTOT*HH];
__device__ __align__(16) __nv_bfloat16 g_vh[(size_t)MTOT*HH];
__device__ __align__(16) __nv_bfloat16 g_vl[(size_t)MTOT*HH];
__device__ __align__(16) __nv_bfloat16 g_wt_hi[3*(size_t)HH*EE];   // W^T split, [p][h][e]
__device__ __align__(16) __nv_bfloat16 g_wt_lo[3*(size_t)HH*EE];

// ---------------------------------------------------------------------------
// helpers
// ---------------------------------------------------------------------------
__device__ __forceinline__ uint32_t smem_u32(const void* p) {
    uint32_t a;
    asm("{ .reg .u64 t; cvta.to.shared.u64 t, %1; cvt.u32.u64 %0, t; }" : "=r"(a) : "l"(p));
    return a;
}
__device__ __forceinline__ void ldsm4(uint32_t* r, uint32_t a) {
    asm volatile("ldmatrix.sync.aligned.m8n8.x4.shared.b16 {%0,%1,%2,%3}, [%4];"
        : "=r"(r[0]), "=r"(r[1]), "=r"(r[2]), "=r"(r[3]) : "r"(a));
}
__device__ __forceinline__ void ldsm4t(uint32_t* r, uint32_t a) {
    asm volatile("ldmatrix.sync.aligned.m8n8.x4.trans.shared.b16 {%0,%1,%2,%3}, [%4];"
        : "=r"(r[0]), "=r"(r[1]), "=r"(r[2]), "=r"(r[3]) : "r"(a));
}
__device__ __forceinline__ void mma16816(float* c, const uint32_t* a, uint32_t b0, uint32_t b1) {
    asm volatile("mma.sync.aligned.m16n8k16.row.col.f32.bf16.bf16.f32 "
        "{%0,%1,%2,%3}, {%4,%5,%6,%7}, {%8,%9}, {%0,%1,%2,%3};"
        : "+f"(c[0]), "+f"(c[1]), "+f"(c[2]), "+f"(c[3])
        : "r"(a[0]), "r"(a[1]), "r"(a[2]), "r"(a[3]), "r"(b0), "r"(b1));
}
__device__ __forceinline__ uint32_t pack_bf16(float a, float b) {
    __nv_bfloat162 h = __floats2bfloat162_rn(a, b);
    return *(uint32_t*)&h;
}

// ---------------------------------------------------------------------------
// prep_w: W [E,H] -> Wt [H,E] split hi/lo, via smem tile transpose (coalesced)
// ---------------------------------------------------------------------------
__global__ __launch_bounds__(256) void prep_w(
    const float* __restrict__ Wk, const float* __restrict__ Wq,
    const float* __restrict__ Wv)
{
    __shared__ float tile[32][129];
    const int p = blockIdx.y;
    const float* W = (p == 0) ? Wk : (p == 1) ? Wq : Wv;
    __nv_bfloat16* oh = g_wt_hi + (size_t)p * HH * EE;
    __nv_bfloat16* ol = g_wt_lo + (size_t)p * HH * EE;
    const int e0 = blockIdx.x * 32;

    #pragma unroll
    for (int i = 0; i < 16; i++) {
        int linear = i * 256 + threadIdx.x;
        int row = linear >> 7;          // e within tile
        int col = linear & 127;         // h
        tile[row][col] = W[(size_t)(e0 + row) * HH + col];
    }
    __syncthreads();

    #pragma unroll
    for (int i = 0; i < 4; i++) {
        int linear = i * 256 + threadIdx.x;
        int h  = linear >> 3;
        int ec = linear & 7;
        __nv_bfloat16 hi4[4], lo4[4];
        #pragma unroll
        for (int r = 0; r < 4; r++) {
            float w = tile[ec * 4 + r][h];
            hi4[r] = __float2bfloat16_rn(w);
            lo4[r] = __float2bfloat16_rn(w - __bfloat162float(hi4[r]));
        }
        *(uint2*)&oh[(size_t)h * EE + e0 + ec * 4] = *(uint2*)hi4;
        *(uint2*)&ol[(size_t)h * EE + e0 + ec * 4] = *(uint2*)lo4;
    }
}

// ---------------------------------------------------------------------------
// proj_hmma: Y = X[16384,1024] @ W[1024,128], split-bf16 HMMA, double-buffered.
// CTA tile 128x128, 8 warps, BK=32, 1 sync/iter.
// ---------------------------------------------------------------------------
#define PA_H 0
#define PA_L 10240
#define PB_H 20480
#define PB_L 30720
#define P_BUF 40960
#define PROJ_SMEM 81920

__global__ __launch_bounds__(256, 2) void proj_hmma(
    const float* __restrict__ k_in, const float* __restrict__ q_in,
    const float* __restrict__ v_in)
{
    extern __shared__ char sm[];
    const uint32_t sbase = smem_u32(sm);
    const int t    = threadIdx.x;
    const int lane = t & 31;
    const int wid  = t >> 5;
    const int wm   = wid & 3;
    const int wn   = wid >> 2;
    const int p    = blockIdx.y;
    const int m0   = blockIdx.x * 128;

    const float* X = (p == 0) ? k_in : (p == 1) ? q_in : v_in;
    __nv_bfloat16* Yh = (p == 0) ? g_kh : (p == 1) ? g_qh : g_vh;
    __nv_bfloat16* Yl = (p == 0) ? g_kl : (p == 1) ? g_ql : g_vl;
    const __nv_bfloat16* WtH = g_wt_hi + (size_t)p * HH * EE;
    const __nv_bfloat16* WtL = g_wt_lo + (size_t)p * HH * EE;

    const uint32_t aoff = (uint32_t)((lane & 15) * 80 + (lane >> 4) * 16);
    const uint32_t boff = (uint32_t)((((lane & 7) | ((lane & 16) >> 1)) * 80) + (((lane >> 3) & 1) * 16));

    float acc[2][8][4];
    #pragma unroll
    for (int mb = 0; mb < 2; mb++)
        #pragma unroll
        for (int j = 0; j < 8; j++)
            #pragma unroll
            for (int i = 0; i < 4; i++) acc[mb][j][i] = 0.f;

    // tile loader: gmem -> (cvt) -> smem buffer
    auto load_tile = [&](int kt, int buf) {
        char* base = sm + buf * P_BUF;
        #pragma unroll
        for (int i = 0; i < 4; i++) {
            int linear = i * 256 + t;
            int c4  = linear & 7;
            int row = linear >> 3;
            float4 f = *(const float4*)&X[(size_t)(m0 + row) * EE + kt * 32 + c4 * 4];
            __nv_bfloat162 h0 = __floats2bfloat162_rn(f.x, f.y);
            __nv_bfloat162 h1 = __floats2bfloat162_rn(f.z, f.w);
            __nv_bfloat162 l0 = __floats2bfloat162_rn(f.x - __bfloat162float(h0.x),
                                                      f.y - __bfloat162float(h0.y));
            __nv_bfloat162 l1 = __floats2bfloat162_rn(f.z - __bfloat162float(h1.x),
                                                      f.w - __bfloat162float(h1.y));
            uint2 uh; uh.x = *(uint32_t*)&h0; uh.y = *(uint32_t*)&h1;
            uint2 ul; ul.x = *(uint32_t*)&l0; ul.y = *(uint32_t*)&l1;
            *(uint2*)(base + PA_H + row * 80 + c4 * 8) = uh;
            *(uint2*)(base + PA_L + row * 80 + c4 * 8) = ul;
        }
        #pragma unroll
        for (int i = 0; i < 2; i++) {
            int linear = i * 256 + t;
            int c4  = linear & 3;
            int row = linear >> 2;
            *(uint4*)(base + PB_H + row * 80 + c4 * 16) =
                *(const uint4*)&WtH[(size_t)row * EE + kt * 32 + c4 * 8];
            *(uint4*)(base + PB_L + row * 80 + c4 * 16) =
                *(const uint4*)&WtL[(size_t)row * EE + kt * 32 + c4 * 8];
        }
    };

    load_tile(0, 0);
    __syncthreads();

    for (int kt = 0; kt < 32; kt++) {
        const int cur = kt & 1;
        const uint32_t sb = sbase + cur * P_BUF;

        #pragma unroll
        for (int h = 0; h < 2; h++) {
            const uint32_t kb = h * 32;
            uint32_t ah[2][4], al[2][4];
            #pragma unroll
            for (int mb = 0; mb < 2; mb++) {
                uint32_t ra = (wm * 32 + mb * 16) * 80 + aoff + kb;
                ldsm4(ah[mb], sb + PA_H + ra);
                ldsm4(al[mb], sb + PA_L + ra);
            }
            #pragma unroll
            for (int jp = 0; jp < 4; jp++) {
                uint32_t bh4[4], bl4[4];
                uint32_t rb = (wn * 64 + jp * 16) * 80 + boff + kb;
                ldsm4(bh4, sb + PB_H + rb);
                ldsm4(bl4, sb + PB_L + rb);
                #pragma unroll
                for (int mb = 0; mb < 2; mb++) {
                    mma16816(acc[mb][2*jp],   ah[mb], bh4[0], bh4[1]);
                    mma16816(acc[mb][2*jp],   ah[mb], bl4[0], bl4[1]);
                    mma16816(acc[mb][2*jp],   al[mb], bh4[0], bh4[1]);
                    mma16816(acc[mb][2*jp+1], ah[mb], bh4[2], bh4[3]);
                    mma16816(acc[mb][2*jp+1], ah[mb], bl4[2], bl4[3]);
                    mma16816(acc[mb][2*jp+1], al[mb], bh4[2], bh4[3]);
                }
            }
        }
        if (kt < 31) load_tile(kt + 1, cur ^ 1);
        __syncthreads();
    }

    // epilogue: acc -> bf16 hi/lo pairs
    const int g  = lane >> 2;
    const int q4 = lane & 3;
    #pragma unroll
    for (int mb = 0; mb < 2; mb++) {
        #pragma unroll
        for (int j = 0; j < 8; j++) {
            int gr  = m0 + wm * 32 + mb * 16 + g;
            int col = wn * 64 + j * 8 + q4 * 2;
            float c0 = acc[mb][j][0], c1 = acc[mb][j][1];
            float c2 = acc[mb][j][2], c3 = acc[mb][j][3];
            __nv_bfloat162 h01 = __floats2bfloat162_rn(c0, c1);
            __nv_bfloat162 h23 = __floats2bfloat162_rn(c2, c3);
            __nv_bfloat162 l01 = __floats2bfloat162_rn(c0 - __bfloat162float(h01.x),
                                                       c1 - __bfloat162float(h01.y));
            __nv_bfloat162 l23 = __floats2bfloat162_rn(c2 - __bfloat162float(h23.x),
                                                       c3 - __bfloat162float(h23.y));
            *(uint32_t*)&Yh[(size_t)gr * HH + col]       = *(uint32_t*)&h01;
            *(uint32_t*)&Yl[(size_t)gr * HH + col]       = *(uint32_t*)&l01;
            *(uint32_t*)&Yh[(size_t)(gr + 8) * HH + col] = *(uint32_t*)&h23;
            *(uint32_t*)&Yl[(size_t)(gr + 8) * HH + col] = *(uint32_t*)&l23;
        }
    }
}

// ---------------------------------------------------------------------------
// flash_hmma: causal flash attention, split-bf16 HMMA.
// BQ=64 (4 warps x 16 rows), BKV=32, K/V double-buffered, Q frags in regs.
// smem: Q hi/lo [64][136], 2 x (K hi/lo + V hi/lo) [32][136] each.
// ---------------------------------------------------------------------------
#define FQ_H 0
#define FQ_L 17408
#define FKV  34816          // + buf*34816
#define KH_O 0
#define KL_O 8704
#define VH_O 17408
#define VL_O 26112
#define FLASH_SMEM 104448

__global__ __launch_bounds__(128, 2) void flash_hmma(float* __restrict__ out)
{
    extern __shared__ char sm[];
    const uint32_t sbase = smem_u32(sm);
    const int t    = threadIdx.x;
    const int lane = t & 31;
    const int w    = t >> 5;
    const int b    = blockIdx.y;
    const int qb   = (gridDim.x - 1) - blockIdx.x;   // big-work CTAs first
    const int q0   = qb * 64;
    const size_t bT = (size_t)b * TT;

    const uint32_t aoff = (uint32_t)((lane & 15) * 272 + (lane >> 4) * 16);
    const uint32_t boff = (uint32_t)((((lane & 7) | ((lane & 16) >> 1)) * 272) + (((lane >> 3) & 1) * 16));

    // ---- load Q tile, hoist fragments to registers ----
    {
        const __nv_bfloat16* qh = g_qh + (bT + q0) * HH;
        const __nv_bfloat16* ql = g_ql + (bT + q0) * HH;
        #pragma unroll
        for (int i = 0; i < 8; i++) {
            int linear = i * 128 + t;
            int col = linear & 15;
            int row = linear >> 4;
            uint32_t so = row * 272 + col * 16;
            *(uint4*)(sm + FQ_H + so) = *(const uint4*)&qh[(size_t)row * HH + col * 8];
            *(uint4*)(sm + FQ_L + so) = *(const uint4*)&ql[(size_t)row * HH + col * 8];
        }
    }
    __syncthreads();

    uint32_t qa_h[8][4], qa_l[8][4];
    #pragma unroll
    for (int k16 = 0; k16 < 8; k16++) {
        uint32_t qr = w * 16 * 272 + aoff + k16 * 32;
        ldsm4(qa_h[k16], sbase + FQ_H + qr);
        ldsm4(qa_l[k16], sbase + FQ_L + qr);
    }

    // K/V block loader into buffer (kb&1)
    auto load_kv = [&](int kb) {
        const size_t krow = bT + (size_t)kb * 32;
        char* kv = sm + FKV + (kb & 1) * 34816;
        #pragma unroll
        for (int i = 0; i < 4; i++) {
            int linear = i * 128 + t;
            int col = linear & 15;
            int row = linear >> 4;
            size_t gidx = (krow + row) * HH + col * 8;
            uint32_t so = row * 272 + col * 16;
            *(uint4*)(kv + KH_O + so) = *(const uint4*)&g_kh[gidx];
            *(uint4*)(kv + KL_O + so) = *(const uint4*)&g_kl[gidx];
            *(uint4*)(kv + VH_O + so) = *(const uint4*)&g_vh[gidx];
            *(uint4*)(kv + VL_O + so) = *(const uint4*)&g_vl[gidx];
        }
    };

    load_kv(0);
    __syncthreads();

    float o[16][4];
    #pragma unroll
    for (int j = 0; j < 16; j++)
        #pragma unroll
        for (int i = 0; i < 4; i++) o[j][i] = 0.f;
    float m0 = -1e30f, m1 = -1e30f, l0 = 0.f, l1 = 0.f;

    // exp2 domain: fold log2(e) into the score scale
    const float scale_l2 = 0.088388347648318447f * 1.4426950408889634f;
    const int g   = lane >> 2;
    const int q4  = lane & 3;
    const int rg0 = q0 + w * 16 + g;

    const int nkb = 2 * qb + 2;
    for (int kb = 0; kb < nkb; kb++) {
        const uint32_t kvb = sbase + FKV + (kb & 1) * 34816;

        // ---- S = Q K^T (split, 3 terms), 32 KV cols ----
        float s[4][4];
        #pragma unroll
        for (int j = 0; j < 4; j++)
            #pragma unroll
            for (int i = 0; i < 4; i++) s[j][i] = 0.f;

        #pragma unroll
        for (int k16 = 0; k16 < 8; k16++) {
            #pragma unroll
            for (int jp = 0; jp < 2; jp++) {
                uint32_t kh4[4], kl4[4];
                uint32_t kr = jp * 16 * 272 + boff + k16 * 32;
                ldsm4(kh4, kvb + KH_O + kr);
                ldsm4(kl4, kvb + KL_O + kr);
                mma16816(s[2*jp],   qa_h[k16], kh4[0], kh4[1]);
                mma16816(s[2*jp],   qa_h[k16], kl4[0], kl4[1]);
                mma16816(s[2*jp],   qa_l[k16], kh4[0], kh4[1]);
                mma16816(s[2*jp+1], qa_h[k16], kh4[2], kh4[3]);
                mma16816(s[2*jp+1], qa_h[k16], kl4[2], kl4[3]);
                mma16816(s[2*jp+1], qa_l[k16], kh4[2], kh4[3]);
            }
        }

        // ---- scale (log2 domain) + causal mask ----
        #pragma unroll
        for (int j = 0; j < 4; j++)
            #pragma unroll
            for (int i = 0; i < 4; i++) s[j][i] *= scale_l2;
        const int kv0 = kb * 32;
        if (kv0 + 31 > rg0) {
            int cbase = kv0 + q4 * 2;
            #pragma unroll
            for (int j = 0; j < 4; j++) {
                int c0 = cbase + j * 8;
                if (c0     > rg0)     s[j][0] = -1e30f;
                if (c0 + 1 > rg0)     s[j][1] = -1e30f;
                if (c0     > rg0 + 8) s[j][2] = -1e30f;
                if (c0 + 1 > rg0 + 8) s[j][3] = -1e30f;
            }
        }

        // ---- online softmax (rows g, g+8), exp2 ----
        float mx0 = -1e30f, mx1 = -1e30f;
        #pragma unroll
        for (int j = 0; j < 4; j++) {
            mx0 = fmaxf(mx0, fmaxf(s[j][0], s[j][1]));
            mx1 = fmaxf(mx1, fmaxf(s[j][2], s[j][3]));
        }
        mx0 = fmaxf(mx0, __shfl_xor_sync(0xffffffffu, mx0, 1));
        mx0 = fmaxf(mx0, __shfl_xor_sync(0xffffffffu, mx0, 2));
        mx1 = fmaxf(mx1, __shfl_xor_sync(0xffffffffu, mx1, 1));
        mx1 = fmaxf(mx1, __shfl_xor_sync(0xffffffffu, mx1, 2));
        float m0n = fmaxf(m0, mx0), m1n = fmaxf(m1, mx1);
        float a0 = exp2f(m0 - m0n), a1 = exp2f(m1 - m1n);
        m0 = m0n; m1 = m1n;

        uint32_t ph01[4], ph23[4], pl01[4], pl23[4];
        float sum0 = 0.f, sum1 = 0.f;
        #pragma unroll
        for (int j = 0; j < 4; j++) {
            float p0 = exp2f(s[j][0] - m0n);
            float p1 = exp2f(s[j][1] - m0n);
            float p2 = exp2f(s[j][2] - m1n);
            float p3 = exp2f(s[j][3] - m1n);
            sum0 += p0 + p1; sum1 += p2 + p3;
            __nv_bfloat162 h01 = __floats2bfloat162_rn(p0, p1);
            __nv_bfloat162 h23 = __floats2bfloat162_rn(p2, p3);
            ph01[j] = *(uint32_t*)&h01;
            ph23[j] = *(uint32_t*)&h23;
            pl01[j] = pack_bf16(p0 - __bfloat162float(h01.x), p1 - __bfloat162float(h01.y));
            pl23[j] = pack_bf16(p2 - __bfloat162float(h23.x), p3 - __bfloat162float(h23.y));
        }
        sum0 += __shfl_xor_sync(0xffffffffu, sum0, 1);
        sum0 += __shfl_xor_sync(0xffffffffu, sum0, 2);
        sum1 += __shfl_xor_sync(0xffffffffu, sum1, 1);
        sum1 += __shfl_xor_sync(0xffffffffu, sum1, 2);
        l0 = l0 * a0 + sum0;
        l1 = l1 * a1 + sum1;

        #pragma unroll
        for (int j = 0; j < 16; j++) {
            o[j][0] *= a0; o[j][1] *= a0;
            o[j][2] *= a1; o[j][3] *= a1;
        }

        // ---- O += P V (split, 3 terms) ----
        #pragma unroll
        for (int ks = 0; ks < 2; ks++) {
            uint32_t pah[4] = { ph01[2*ks], ph23[2*ks], ph01[2*ks+1], ph23[2*ks+1] };
            uint32_t pal[4] = { pl01[2*ks], pl23[2*ks], pl01[2*ks+1], pl23[2*ks+1] };
            #pragma unroll
            for (int hp = 0; hp < 8; hp++) {
                uint32_t vh4[4], vl4[4];
                uint32_t vr = ks * 16 * 272 + aoff + hp * 32;
                ldsm4t(vh4, kvb + VH_O + vr);
                ldsm4t(vl4, kvb + VL_O + vr);
                mma16816(o[2*hp],   pah, vh4[0], vh4[1]);
                mma16816(o[2*hp],   pah, vl4[0], vl4[1]);
                mma16816(o[2*hp],   pal, vh4[0], vh4[1]);
                mma16816(o[2*hp+1], pah, vh4[2], vh4[3]);
                mma16816(o[2*hp+1], pah, vl4[2], vl4[3]);
                mma16816(o[2*hp+1], pal, vh4[2], vh4[3]);
            }
        }

        // ---- prefetch next K/V block into the other buffer ----
        if (kb + 1 < nkb) load_kv(kb + 1);
        __syncthreads();
    }

    // ---- normalize and store ----
    float inv0 = 1.f / l0, inv1 = 1.f / l1;
    #pragma unroll
    for (int j = 0; j < 16; j++) {
        int col = j * 8 + q4 * 2;
        float2 v0 = { o[j][0] * inv0, o[j][1] * inv0 };
        float2 v1 = { o[j][2] * inv1, o[j][3] * inv1 };
        *(float2*)&out[(bT + rg0) * HH + col]     = v0;
        *(float2*)&out[(bT + rg0 + 8) * HH + col] = v1;
    }
}

// ---------------------------------------------------------------------------
extern "C" void kernel_launch(void* const* d_in, const int* in_sizes, int n_in,
                              void* d_out, int out_size)
{
    const float* k  = (const float*)d_in[0];
    const float* q  = (const float*)d_in[1];
    const float* v  = (const float*)d_in[2];
    const float* Wk = (const float*)d_in[3];
    const float* Wq = (const float*)d_in[4];
    const float* Wv = (const float*)d_in[5];
    float* out = (float*)d_out;

    prep_w<<<dim3(EE / 32, 3), 256>>>(Wk, Wq, Wv);

    cudaFuncSetAttribute(proj_hmma, cudaFuncAttributeMaxDynamicSharedMemorySize, PROJ_SMEM);
    proj_hmma<<<dim3(MTOT / 128, 3), 256, PROJ_SMEM>>>(k, q, v);

    cudaFuncSetAttribute(flash_hmma, cudaFuncAttributeMaxDynamicSharedMemorySize, FLASH_SMEM);
    flash_hmma<<<dim3(TT / 64, BB), 128, FLASH_SMEM>>>(out);
}

// round 6
// speedup vs baseline: 3.0947x; 1.0895x over previous
#include <cuda_runtime.h>
#include <cuda_bf16.h>
#include <cstdint>

#define BB 4
#define TT 4096
#define EE 1024
#define HH 128
#define MTOT (BB*TT)

// split-bf16 scratch (device globals = allocation-free)
__device__ __align__(16) __nv_bfloat16 g_qh[(size_t)MTOT*HH];
__device__ __align__(16) __nv_bfloat16 g_ql[(size_t)MTOT*HH];
__device__ __align__(16) __nv_bfloat16 g_kh[(size_t)MTOT*HH];
__device__ __align__(16) __nv_bfloat16 g_kl[(size_t)MTOT*HH];
__device__ __align__(16) __nv_bfloat16 g_vh[(size_t)MTOT*HH];
__device__ __align__(16) __nv_bfloat16 g_vl[(size_t)MTOT*HH];
__device__ __align__(16) __nv_bfloat16 g_wt_hi[3*(size_t)HH*EE];   // W^T split, [p][h][e]
__device__ __align__(16) __nv_bfloat16 g_wt_lo[3*(size_t)HH*EE];

// ---------------------------------------------------------------------------
// helpers
// ---------------------------------------------------------------------------
__device__ __forceinline__ uint32_t smem_u32(const void* p) {
    uint32_t a;
    asm("{ .reg .u64 t; cvta.to.shared.u64 t, %1; cvt.u32.u64 %0, t; }" : "=r"(a) : "l"(p));
    return a;
}
__device__ __forceinline__ void ldsm4(uint32_t* r, uint32_t a) {
    asm volatile("ldmatrix.sync.aligned.m8n8.x4.shared.b16 {%0,%1,%2,%3}, [%4];"
        : "=r"(r[0]), "=r"(r[1]), "=r"(r[2]), "=r"(r[3]) : "r"(a));
}
__device__ __forceinline__ void ldsm4t(uint32_t* r, uint32_t a) {
    asm volatile("ldmatrix.sync.aligned.m8n8.x4.trans.shared.b16 {%0,%1,%2,%3}, [%4];"
        : "=r"(r[0]), "=r"(r[1]), "=r"(r[2]), "=r"(r[3]) : "r"(a));
}
__device__ __forceinline__ void mma16816(float* c, const uint32_t* a, uint32_t b0, uint32_t b1) {
    asm volatile("mma.sync.aligned.m16n8k16.row.col.f32.bf16.bf16.f32 "
        "{%0,%1,%2,%3}, {%4,%5,%6,%7}, {%8,%9}, {%0,%1,%2,%3};"
        : "+f"(c[0]), "+f"(c[1]), "+f"(c[2]), "+f"(c[3])
        : "r"(a[0]), "r"(a[1]), "r"(a[2]), "r"(a[3]), "r"(b0), "r"(b1));
}
__device__ __forceinline__ uint32_t pack_bf16(float a, float b) {
    __nv_bfloat162 h = __floats2bfloat162_rn(a, b);
    return *(uint32_t*)&h;
}
__device__ __forceinline__ void cp16(uint32_t saddr, const void* gptr) {
    asm volatile("cp.async.cg.shared.global [%0], [%1], 16;"
        :: "r"(saddr), "l"(__cvta_generic_to_global(gptr)) : "memory");
}
#define CP_COMMIT() asm volatile("cp.async.commit_group;" ::: "memory")
#define CP_WAIT0()  asm volatile("cp.async.wait_group 0;" ::: "memory")
#define BAR_GRP(id) asm volatile("bar.sync %0, 128;" :: "r"(id) : "memory")

// ---------------------------------------------------------------------------
// prep_w: W [E,H] -> Wt [H,E] split hi/lo, via smem tile transpose (coalesced)
// ---------------------------------------------------------------------------
__global__ __launch_bounds__(256) void prep_w(
    const float* __restrict__ Wk, const float* __restrict__ Wq,
    const float* __restrict__ Wv)
{
    __shared__ float tile[32][129];
    const int p = blockIdx.y;
    const float* W = (p == 0) ? Wk : (p == 1) ? Wq : Wv;
    __nv_bfloat16* oh = g_wt_hi + (size_t)p * HH * EE;
    __nv_bfloat16* ol = g_wt_lo + (size_t)p * HH * EE;
    const int e0 = blockIdx.x * 32;

    #pragma unroll
    for (int i = 0; i < 16; i++) {
        int linear = i * 256 + threadIdx.x;
        int row = linear >> 7;
        int col = linear & 127;
        tile[row][col] = W[(size_t)(e0 + row) * HH + col];
    }
    __syncthreads();

    #pragma unroll
    for (int i = 0; i < 4; i++) {
        int linear = i * 256 + threadIdx.x;
        int h  = linear >> 3;
        int ec = linear & 7;
        __nv_bfloat16 hi4[4], lo4[4];
        #pragma unroll
        for (int r = 0; r < 4; r++) {
            float w = tile[ec * 4 + r][h];
            hi4[r] = __float2bfloat16_rn(w);
            lo4[r] = __float2bfloat16_rn(w - __bfloat162float(hi4[r]));
        }
        *(uint2*)&oh[(size_t)h * EE + e0 + ec * 4] = *(uint2*)hi4;
        *(uint2*)&ol[(size_t)h * EE + e0 + ec * 4] = *(uint2*)lo4;
    }
}

// ---------------------------------------------------------------------------
// proj_hmma: Y = X[16384,1024] @ W[1024,128], split-bf16 HMMA, double-buffered
// with cp.async B-tile prefetch. CTA tile 128x128, 8 warps, BK=32.
// ---------------------------------------------------------------------------
#define PA_H 0
#define PA_L 10240
#define PB_H 20480
#define PB_L 30720
#define P_BUF 40960
#define PROJ_SMEM 81920

__global__ __launch_bounds__(256, 2) void proj_hmma(
    const float* __restrict__ k_in, const float* __restrict__ q_in,
    const float* __restrict__ v_in)
{
    extern __shared__ char sm[];
    const uint32_t sbase = smem_u32(sm);
    const int t    = threadIdx.x;
    const int lane = t & 31;
    const int wid  = t >> 5;
    const int wm   = wid & 3;
    const int wn   = wid >> 2;
    const int p    = blockIdx.y;
    const int m0   = blockIdx.x * 128;

    const float* X = (p == 0) ? k_in : (p == 1) ? q_in : v_in;
    __nv_bfloat16* Yh = (p == 0) ? g_kh : (p == 1) ? g_qh : g_vh;
    __nv_bfloat16* Yl = (p == 0) ? g_kl : (p == 1) ? g_ql : g_vl;
    const __nv_bfloat16* WtH = g_wt_hi + (size_t)p * HH * EE;
    const __nv_bfloat16* WtL = g_wt_lo + (size_t)p * HH * EE;

    const uint32_t aoff = (uint32_t)((lane & 15) * 80 + (lane >> 4) * 16);
    const uint32_t boff = (uint32_t)((((lane & 7) | ((lane & 16) >> 1)) * 80) + (((lane >> 3) & 1) * 16));

    float acc[2][8][4];
    #pragma unroll
    for (int mb = 0; mb < 2; mb++)
        #pragma unroll
        for (int j = 0; j < 8; j++)
            #pragma unroll
            for (int i = 0; i < 4; i++) acc[mb][j][i] = 0.f;

    // A: fp32 -> split bf16 (manual); B: pure copy (cp.async)
    auto load_tile = [&](int kt, int buf) {
        char* base = sm + buf * P_BUF;
        uint32_t ubase = sbase + buf * P_BUF;
        #pragma unroll
        for (int i = 0; i < 2; i++) {           // B tiles: 128 rows x 4 chunks of 16B
            int linear = i * 256 + t;           // 0..511
            int c4  = linear & 3;
            int row = linear >> 2;              // 0..127
            cp16(ubase + PB_H + row * 80 + c4 * 16, &WtH[(size_t)row * EE + kt * 32 + c4 * 8]);
            cp16(ubase + PB_L + row * 80 + c4 * 16, &WtL[(size_t)row * EE + kt * 32 + c4 * 8]);
        }
        CP_COMMIT();
        #pragma unroll
        for (int i = 0; i < 4; i++) {           // A tiles: load+convert+STS
            int linear = i * 256 + t;
            int c4  = linear & 7;
            int row = linear >> 3;
            float4 f = *(const float4*)&X[(size_t)(m0 + row) * EE + kt * 32 + c4 * 4];
            __nv_bfloat162 h0 = __floats2bfloat162_rn(f.x, f.y);
            __nv_bfloat162 h1 = __floats2bfloat162_rn(f.z, f.w);
            __nv_bfloat162 l0 = __floats2bfloat162_rn(f.x - __bfloat162float(h0.x),
                                                      f.y - __bfloat162float(h0.y));
            __nv_bfloat162 l1 = __floats2bfloat162_rn(f.z - __bfloat162float(h1.x),
                                                      f.w - __bfloat162float(h1.y));
            uint2 uh; uh.x = *(uint32_t*)&h0; uh.y = *(uint32_t*)&h1;
            uint2 ul; ul.x = *(uint32_t*)&l0; ul.y = *(uint32_t*)&l1;
            *(uint2*)(base + PA_H + row * 80 + c4 * 8) = uh;
            *(uint2*)(base + PA_L + row * 80 + c4 * 8) = ul;
        }
    };

    load_tile(0, 0);

    for (int kt = 0; kt < 32; kt++) {
        const int cur = kt & 1;
        const uint32_t sb = sbase + cur * P_BUF;
        CP_WAIT0();
        __syncthreads();

        #pragma unroll
        for (int h = 0; h < 2; h++) {
            const uint32_t kb = h * 32;
            uint32_t ah[2][4], al[2][4];
            #pragma unroll
            for (int mb = 0; mb < 2; mb++) {
                uint32_t ra = (wm * 32 + mb * 16) * 80 + aoff + kb;
                ldsm4(ah[mb], sb + PA_H + ra);
                ldsm4(al[mb], sb + PA_L + ra);
            }
            #pragma unroll
            for (int jp = 0; jp < 4; jp++) {
                uint32_t bh4[4], bl4[4];
                uint32_t rb = (wn * 64 + jp * 16) * 80 + boff + kb;
                ldsm4(bh4, sb + PB_H + rb);
                ldsm4(bl4, sb + PB_L + rb);
                #pragma unroll
                for (int mb = 0; mb < 2; mb++) {
                    mma16816(acc[mb][2*jp],   ah[mb], bh4[0], bh4[1]);
                    mma16816(acc[mb][2*jp],   ah[mb], bl4[0], bl4[1]);
                    mma16816(acc[mb][2*jp],   al[mb], bh4[0], bh4[1]);
                    mma16816(acc[mb][2*jp+1], ah[mb], bh4[2], bh4[3]);
                    mma16816(acc[mb][2*jp+1], ah[mb], bl4[2], bl4[3]);
                    mma16816(acc[mb][2*jp+1], al[mb], bh4[2], bh4[3]);
                }
            }
        }
        if (kt < 31) load_tile(kt + 1, cur ^ 1);
    }

    // epilogue: acc -> bf16 hi/lo pairs
    const int g  = lane >> 2;
    const int q4 = lane & 3;
    #pragma unroll
    for (int mb = 0; mb < 2; mb++) {
        #pragma unroll
        for (int j = 0; j < 8; j++) {
            int gr  = m0 + wm * 32 + mb * 16 + g;
            int col = wn * 64 + j * 8 + q4 * 2;
            float c0 = acc[mb][j][0], c1 = acc[mb][j][1];
            float c2 = acc[mb][j][2], c3 = acc[mb][j][3];
            __nv_bfloat162 h01 = __floats2bfloat162_rn(c0, c1);
            __nv_bfloat162 h23 = __floats2bfloat162_rn(c2, c3);
            __nv_bfloat162 l01 = __floats2bfloat162_rn(c0 - __bfloat162float(h01.x),
                                                       c1 - __bfloat162float(h01.y));
            __nv_bfloat162 l23 = __floats2bfloat162_rn(c2 - __bfloat162float(h23.x),
                                                       c3 - __bfloat162float(h23.y));
            *(uint32_t*)&Yh[(size_t)gr * HH + col]       = *(uint32_t*)&h01;
            *(uint32_t*)&Yl[(size_t)gr * HH + col]       = *(uint32_t*)&l01;
            *(uint32_t*)&Yh[(size_t)(gr + 8) * HH + col] = *(uint32_t*)&h23;
            *(uint32_t*)&Yl[(size_t)(gr + 8) * HH + col] = *(uint32_t*)&l23;
        }
    }
}

// ---------------------------------------------------------------------------
// flash_hmma: causal flash attention, split-bf16 HMMA, split-KV warp groups.
// 256 threads = 2 groups x 4 warps. BQ=64, BKV=32.
// Group g processes KV tiles kb ≡ g (mod 2) with its own (m,l,O) state;
// states merged at the end via softmax-merge identity through smem.
// ---------------------------------------------------------------------------
#define FQ_H 0
#define FQ_L 17408
#define FKV  34816          // + grp*34816
#define KH_O 0
#define KL_O 8704
#define VH_O 17408
#define VL_O 26112
#define FLASH_SMEM 104448

__global__ __launch_bounds__(256, 2) void flash_hmma(float* __restrict__ out)
{
    extern __shared__ char sm[];
    const uint32_t sbase = smem_u32(sm);
    const int t    = threadIdx.x;
    const int lane = t & 31;
    const int wid  = t >> 5;
    const int grp  = wid >> 2;        // KV group 0/1
    const int wg   = wid & 3;         // warp within group -> 16 query rows
    const int gt   = t & 127;         // thread within group
    const int b    = blockIdx.y;
    const int qb   = (gridDim.x - 1) - blockIdx.x;   // big-work CTAs first
    const int q0   = qb * 64;
    const size_t bT = (size_t)b * TT;

    const uint32_t aoff = (uint32_t)((lane & 15) * 272 + (lane >> 4) * 16);
    const uint32_t boff = (uint32_t)((((lane & 7) | ((lane & 16) >> 1)) * 272) + (((lane >> 3) & 1) * 16));

    // ---- load Q tile (all 256 threads, cp.async) ----
    {
        const __nv_bfloat16* qh = g_qh + (bT + q0) * HH;
        const __nv_bfloat16* ql = g_ql + (bT + q0) * HH;
        #pragma unroll
        for (int i = 0; i < 4; i++) {
            int linear = i * 256 + t;     // 1024 16B-chunks per array
            int row = linear >> 4;
            int col = linear & 15;
            uint32_t so = row * 272 + col * 16;
            cp16(sbase + FQ_H + so, &qh[(size_t)row * HH + col * 8]);
            cp16(sbase + FQ_L + so, &ql[(size_t)row * HH + col * 8]);
        }
        CP_COMMIT(); CP_WAIT0();
    }
    __syncthreads();

    float o[16][4];
    #pragma unroll
    for (int j = 0; j < 16; j++)
        #pragma unroll
        for (int i = 0; i < 4; i++) o[j][i] = 0.f;
    float m0 = -1e30f, m1 = -1e30f, l0 = 0.f, l1 = 0.f;

    const float scale_l2 = 0.088388347648318447f * 1.4426950408889634f;  // /sqrt(128)*log2e
    const int g   = lane >> 2;
    const int q4  = lane & 3;
    const int rg0 = q0 + wg * 16 + g;

    const uint32_t kvb = sbase + FKV + grp * 34816;
    const int nkb = 2 * qb + 2;
    const int barid = grp + 1;

    for (int kb = grp; kb < nkb; kb += 2) {
        // ---- load this group's KV tile (128 threads, cp.async) ----
        {
            const size_t krow = bT + (size_t)kb * 32;
            #pragma unroll
            for (int i = 0; i < 4; i++) {
                int linear = i * 128 + gt;    // 512 chunks per array
                int row = linear >> 4;
                int col = linear & 15;
                uint32_t so = row * 272 + col * 16;
                size_t go = (krow + row) * HH + col * 8;
                cp16(kvb + KH_O + so, g_kh + go);
                cp16(kvb + KL_O + so, g_kl + go);
                cp16(kvb + VH_O + so, g_vh + go);
                cp16(kvb + VL_O + so, g_vl + go);
            }
            CP_COMMIT(); CP_WAIT0();
        }
        BAR_GRP(barid);

        // ---- S = Q K^T (split, 3 terms), 32 KV cols ----
        float s[4][4];
        #pragma unroll
        for (int j = 0; j < 4; j++)
            #pragma unroll
            for (int i = 0; i < 4; i++) s[j][i] = 0.f;

        #pragma unroll
        for (int k16 = 0; k16 < 8; k16++) {
            uint32_t qa_h[4], qa_l[4];
            uint32_t qr = wg * 16 * 272 + aoff + k16 * 32;
            ldsm4(qa_h, sbase + FQ_H + qr);
            ldsm4(qa_l, sbase + FQ_L + qr);
            #pragma unroll
            for (int jp = 0; jp < 2; jp++) {
                uint32_t kh4[4], kl4[4];
                uint32_t kr = jp * 16 * 272 + boff + k16 * 32;
                ldsm4(kh4, kvb + KH_O + kr);
                ldsm4(kl4, kvb + KL_O + kr);
                mma16816(s[2*jp],   qa_h, kh4[0], kh4[1]);
                mma16816(s[2*jp],   qa_h, kl4[0], kl4[1]);
                mma16816(s[2*jp],   qa_l, kh4[0], kh4[1]);
                mma16816(s[2*jp+1], qa_h, kh4[2], kh4[3]);
                mma16816(s[2*jp+1], qa_h, kl4[2], kl4[3]);
                mma16816(s[2*jp+1], qa_l, kh4[2], kh4[3]);
            }
        }

        // ---- scale (log2 domain) + causal mask ----
        #pragma unroll
        for (int j = 0; j < 4; j++)
            #pragma unroll
            for (int i = 0; i < 4; i++) s[j][i] *= scale_l2;
        const int kv0 = kb * 32;
        if (kv0 + 31 > rg0) {
            int cbase = kv0 + q4 * 2;
            #pragma unroll
            for (int j = 0; j < 4; j++) {
                int c0 = cbase + j * 8;
                if (c0     > rg0)     s[j][0] = -1e30f;
                if (c0 + 1 > rg0)     s[j][1] = -1e30f;
                if (c0     > rg0 + 8) s[j][2] = -1e30f;
                if (c0 + 1 > rg0 + 8) s[j][3] = -1e30f;
            }
        }

        // ---- online softmax (rows g, g+8), exp2 domain ----
        float mx0 = -1e30f, mx1 = -1e30f;
        #pragma unroll
        for (int j = 0; j < 4; j++) {
            mx0 = fmaxf(mx0, fmaxf(s[j][0], s[j][1]));
            mx1 = fmaxf(mx1, fmaxf(s[j][2], s[j][3]));
        }
        mx0 = fmaxf(mx0, __shfl_xor_sync(0xffffffffu, mx0, 1));
        mx0 = fmaxf(mx0, __shfl_xor_sync(0xffffffffu, mx0, 2));
        mx1 = fmaxf(mx1, __shfl_xor_sync(0xffffffffu, mx1, 1));
        mx1 = fmaxf(mx1, __shfl_xor_sync(0xffffffffu, mx1, 2));
        float m0n = fmaxf(m0, mx0), m1n = fmaxf(m1, mx1);
        float a0 = exp2f(m0 - m0n), a1 = exp2f(m1 - m1n);
        m0 = m0n; m1 = m1n;

        // all-masked-safe exponent base: if a row has seen nothing but mask,
        // m?n = -1e30 and esub forces p = exp2f(-huge) = 0 (not exp2f(0)=1).
        float esub0 = fmaxf(m0n, -1e20f);
        float esub1 = fmaxf(m1n, -1e20f);

        uint32_t ph01[4], ph23[4], pl01[4], pl23[4];
        float sum0 = 0.f, sum1 = 0.f;
        #pragma unroll
        for (int j = 0; j < 4; j++) {
            float p0 = exp2f(s[j][0] - esub0);
            float p1 = exp2f(s[j][1] - esub0);
            float p2 = exp2f(s[j][2] - esub1);
            float p3 = exp2f(s[j][3] - esub1);
            sum0 += p0 + p1; sum1 += p2 + p3;
            __nv_bfloat162 h01 = __floats2bfloat162_rn(p0, p1);
            __nv_bfloat162 h23 = __floats2bfloat162_rn(p2, p3);
            ph01[j] = *(uint32_t*)&h01;
            ph23[j] = *(uint32_t*)&h23;
            pl01[j] = pack_bf16(p0 - __bfloat162float(h01.x), p1 - __bfloat162float(h01.y));
            pl23[j] = pack_bf16(p2 - __bfloat162float(h23.x), p3 - __bfloat162float(h23.y));
        }
        sum0 += __shfl_xor_sync(0xffffffffu, sum0, 1);
        sum0 += __shfl_xor_sync(0xffffffffu, sum0, 2);
        sum1 += __shfl_xor_sync(0xffffffffu, sum1, 1);
        sum1 += __shfl_xor_sync(0xffffffffu, sum1, 2);
        l0 = l0 * a0 + sum0;
        l1 = l1 * a1 + sum1;

        #pragma unroll
        for (int j = 0; j < 16; j++) {
            o[j][0] *= a0; o[j][1] *= a0;
            o[j][2] *= a1; o[j][3] *= a1;
        }

        // ---- O += P V (split, 3 terms) ----
        #pragma unroll
        for (int ks = 0; ks < 2; ks++) {
            uint32_t pah[4] = { ph01[2*ks], ph23[2*ks], ph01[2*ks+1], ph23[2*ks+1] };
            uint32_t pal[4] = { pl01[2*ks], pl23[2*ks], pl01[2*ks+1], pl23[2*ks+1] };
            #pragma unroll
            for (int hp = 0; hp < 8; hp++) {
                uint32_t vh4[4], vl4[4];
                uint32_t vr = ks * 16 * 272 + aoff + hp * 32;
                ldsm4t(vh4, kvb + VH_O + vr);
                ldsm4t(vl4, kvb + VL_O + vr);
                mma16816(o[2*hp],   pah, vh4[0], vh4[1]);
                mma16816(o[2*hp],   pah, vl4[0], vl4[1]);
                mma16816(o[2*hp],   pal, vh4[0], vh4[1]);
                mma16816(o[2*hp+1], pah, vh4[2], vh4[3]);
                mma16816(o[2*hp+1], pah, vl4[2], vl4[3]);
                mma16816(o[2*hp+1], pal, vh4[2], vh4[3]);
            }
        }
        BAR_GRP(barid);   // group done reading buffer before next overwrite
    }

    // ---- merge group states (group1 -> smem -> group0) ----
    __syncthreads();
    float* mrg = (float*)(sm + FKV);
    const int slot = (wg * 32 + lane) * 69;
    if (grp == 1) {
        float* d = mrg + slot;
        #pragma unroll
        for (int j = 0; j < 16; j++) {
            d[j*4+0] = o[j][0]; d[j*4+1] = o[j][1];
            d[j*4+2] = o[j][2]; d[j*4+3] = o[j][3];
        }
        d[64] = m0; d[65] = m1; d[66] = l0; d[67] = l1;
    }
    __syncthreads();
    if (grp == 0) {
        const float* s2 = mrg + slot;
        float mB0 = s2[64], mB1 = s2[65], lB0 = s2[66], lB1 = s2[67];
        float mS0 = fmaxf(m0, mB0), mS1 = fmaxf(m1, mB1);
        float wA0 = exp2f(m0 - mS0), wB0 = exp2f(mB0 - mS0);
        float wA1 = exp2f(m1 - mS1), wB1 = exp2f(mB1 - mS1);
        float inv0 = 1.f / (l0 * wA0 + lB0 * wB0);
        float inv1 = 1.f / (l1 * wA1 + lB1 * wB1);
        #pragma unroll
        for (int j = 0; j < 16; j++) {
            int col = j * 8 + q4 * 2;
            float2 v0, v1;
            v0.x = (o[j][0] * wA0 + s2[j*4+0] * wB0) * inv0;
            v0.y = (o[j][1] * wA0 + s2[j*4+1] * wB0) * inv0;
            v1.x = (o[j][2] * wA1 + s2[j*4+2] * wB1) * inv1;
            v1.y = (o[j][3] * wA1 + s2[j*4+3] * wB1) * inv1;
            *(float2*)&out[(bT + rg0) * HH + col]     = v0;
            *(float2*)&out[(bT + rg0 + 8) * HH + col] = v1;
        }
    }
}

// ---------------------------------------------------------------------------
extern "C" void kernel_launch(void* const* d_in, const int* in_sizes, int n_in,
                              void* d_out, int out_size)
{
    const float* k  = (const float*)d_in[0];
    const float* q  = (const float*)d_in[1];
    const float* v  = (const float*)d_in[2];
    const float* Wk = (const float*)d_in[3];
    const float* Wq = (const float*)d_in[4];
    const float* Wv = (const float*)d_in[5];
    float* out = (float*)d_out;

    prep_w<<<dim3(EE / 32, 3), 256>>>(Wk, Wq, Wv);

    cudaFuncSetAttribute(proj_hmma, cudaFuncAttributeMaxDynamicSharedMemorySize, PROJ_SMEM);
    proj_hmma<<<dim3(MTOT / 128, 3), 256, PROJ_SMEM>>>(k, q, v);

    cudaFuncSetAttribute(flash_hmma, cudaFuncAttributeMaxDynamicSharedMemorySize, FLASH_SMEM);
    flash_hmma<<<dim3(TT / 64, BB), 256, FLASH_SMEM>>>(out);
}

// round 7
// speedup vs baseline: 3.4756x; 1.1231x over previous
#include <cuda_runtime.h>
#include <cuda_bf16.h>
#include <cstdint>

#define BB 4
#define TT 4096
#define EE 1024
#define HH 128
#define MTOT (BB*TT)

// split-bf16 scratch (device globals = allocation-free)
__device__ __align__(16) __nv_bfloat16 g_qh[(size_t)MTOT*HH];
__device__ __align__(16) __nv_bfloat16 g_ql[(size_t)MTOT*HH];
__device__ __align__(16) __nv_bfloat16 g_kh[(size_t)MTOT*HH];
__device__ __align__(16) __nv_bfloat16 g_kl[(size_t)MTOT*HH];
__device__ __align__(16) __nv_bfloat16 g_vh[(size_t)MTOT*HH];
__device__ __align__(16) __nv_bfloat16 g_vl[(size_t)MTOT*HH];
__device__ __align__(16) __nv_bfloat16 g_wt_hi[3*(size_t)HH*EE];   // W^T split, [p][h][e]
__device__ __align__(16) __nv_bfloat16 g_wt_lo[3*(size_t)HH*EE];

// ---------------------------------------------------------------------------
// helpers
// ---------------------------------------------------------------------------
__device__ __forceinline__ uint32_t smem_u32(const void* p) {
    uint32_t a;
    asm("{ .reg .u64 t; cvta.to.shared.u64 t, %1; cvt.u32.u64 %0, t; }" : "=r"(a) : "l"(p));
    return a;
}
__device__ __forceinline__ void ldsm4(uint32_t* r, uint32_t a) {
    asm volatile("ldmatrix.sync.aligned.m8n8.x4.shared.b16 {%0,%1,%2,%3}, [%4];"
        : "=r"(r[0]), "=r"(r[1]), "=r"(r[2]), "=r"(r[3]) : "r"(a));
}
__device__ __forceinline__ void ldsm4t(uint32_t* r, uint32_t a) {
    asm volatile("ldmatrix.sync.aligned.m8n8.x4.trans.shared.b16 {%0,%1,%2,%3}, [%4];"
        : "=r"(r[0]), "=r"(r[1]), "=r"(r[2]), "=r"(r[3]) : "r"(a));
}
__device__ __forceinline__ void mma16816(float* c, const uint32_t* a, uint32_t b0, uint32_t b1) {
    asm volatile("mma.sync.aligned.m16n8k16.row.col.f32.bf16.bf16.f32 "
        "{%0,%1,%2,%3}, {%4,%5,%6,%7}, {%8,%9}, {%0,%1,%2,%3};"
        : "+f"(c[0]), "+f"(c[1]), "+f"(c[2]), "+f"(c[3])
        : "r"(a[0]), "r"(a[1]), "r"(a[2]), "r"(a[3]), "r"(b0), "r"(b1));
}
__device__ __forceinline__ uint32_t pack_bf16(float a, float b) {
    __nv_bfloat162 h = __floats2bfloat162_rn(a, b);
    return *(uint32_t*)&h;
}
__device__ __forceinline__ void cp16(uint32_t saddr, const void* gptr) {
    asm volatile("cp.async.cg.shared.global [%0], [%1], 16;"
        :: "r"(saddr), "l"(__cvta_generic_to_global(gptr)) : "memory");
}
#define CP_COMMIT() asm volatile("cp.async.commit_group;" ::: "memory")
#define CP_WAIT0()  asm volatile("cp.async.wait_group 0;" ::: "memory")
#define BAR_GRP(id) asm volatile("bar.sync %0, 128;" :: "r"(id) : "memory")

// ---------------------------------------------------------------------------
// prep_w: W [E,H] -> Wt [H,E] split hi/lo, via smem tile transpose (coalesced)
// ---------------------------------------------------------------------------
__global__ __launch_bounds__(256) void prep_w(
    const float* __restrict__ Wk, const float* __restrict__ Wq,
    const float* __restrict__ Wv)
{
    __shared__ float tile[32][129];
    const int p = blockIdx.y;
    const float* W = (p == 0) ? Wk : (p == 1) ? Wq : Wv;
    __nv_bfloat16* oh = g_wt_hi + (size_t)p * HH * EE;
    __nv_bfloat16* ol = g_wt_lo + (size_t)p * HH * EE;
    const int e0 = blockIdx.x * 32;

    #pragma unroll
    for (int i = 0; i < 16; i++) {
        int linear = i * 256 + threadIdx.x;
        int row = linear >> 7;
        int col = linear & 127;
        tile[row][col] = W[(size_t)(e0 + row) * HH + col];
    }
    __syncthreads();

    #pragma unroll
    for (int i = 0; i < 4; i++) {
        int linear = i * 256 + threadIdx.x;
        int h  = linear >> 3;
        int ec = linear & 7;
        __nv_bfloat16 hi4[4], lo4[4];
        #pragma unroll
        for (int r = 0; r < 4; r++) {
            float w = tile[ec * 4 + r][h];
            hi4[r] = __float2bfloat16_rn(w);
            lo4[r] = __float2bfloat16_rn(w - __bfloat162float(hi4[r]));
        }
        *(uint2*)&oh[(size_t)h * EE + e0 + ec * 4] = *(uint2*)hi4;
        *(uint2*)&ol[(size_t)h * EE + e0 + ec * 4] = *(uint2*)lo4;
    }
}

// ---------------------------------------------------------------------------
// proj_hmma: Y = X[16384,1024] @ W[1024,128], split-bf16 HMMA, double-buffered
// with cp.async B-tile prefetch. CTA tile 128x128, 8 warps, BK=32.
// ---------------------------------------------------------------------------
#define PA_H 0
#define PA_L 10240
#define PB_H 20480
#define PB_L 30720
#define P_BUF 40960
#define PROJ_SMEM 81920

__global__ __launch_bounds__(256, 2) void proj_hmma(
    const float* __restrict__ k_in, const float* __restrict__ q_in,
    const float* __restrict__ v_in)
{
    extern __shared__ char sm[];
    const uint32_t sbase = smem_u32(sm);
    const int t    = threadIdx.x;
    const int lane = t & 31;
    const int wid  = t >> 5;
    const int wm   = wid & 3;
    const int wn   = wid >> 2;
    const int p    = blockIdx.y;
    const int m0   = blockIdx.x * 128;

    const float* X = (p == 0) ? k_in : (p == 1) ? q_in : v_in;
    __nv_bfloat16* Yh = (p == 0) ? g_kh : (p == 1) ? g_qh : g_vh;
    __nv_bfloat16* Yl = (p == 0) ? g_kl : (p == 1) ? g_ql : g_vl;
    const __nv_bfloat16* WtH = g_wt_hi + (size_t)p * HH * EE;
    const __nv_bfloat16* WtL = g_wt_lo + (size_t)p * HH * EE;

    const uint32_t aoff = (uint32_t)((lane & 15) * 80 + (lane >> 4) * 16);
    const uint32_t boff = (uint32_t)((((lane & 7) | ((lane & 16) >> 1)) * 80) + (((lane >> 3) & 1) * 16));

    float acc[2][8][4];
    #pragma unroll
    for (int mb = 0; mb < 2; mb++)
        #pragma unroll
        for (int j = 0; j < 8; j++)
            #pragma unroll
            for (int i = 0; i < 4; i++) acc[mb][j][i] = 0.f;

    auto load_tile = [&](int kt, int buf) {
        char* base = sm + buf * P_BUF;
        uint32_t ubase = sbase + buf * P_BUF;
        #pragma unroll
        for (int i = 0; i < 2; i++) {           // B tiles: 128 rows x 4 chunks of 16B
            int linear = i * 256 + t;
            int c4  = linear & 3;
            int row = linear >> 2;
            cp16(ubase + PB_H + row * 80 + c4 * 16, &WtH[(size_t)row * EE + kt * 32 + c4 * 8]);
            cp16(ubase + PB_L + row * 80 + c4 * 16, &WtL[(size_t)row * EE + kt * 32 + c4 * 8]);
        }
        CP_COMMIT();
        #pragma unroll
        for (int i = 0; i < 4; i++) {           // A tiles: load+convert+STS
            int linear = i * 256 + t;
            int c4  = linear & 7;
            int row = linear >> 3;
            float4 f = *(const float4*)&X[(size_t)(m0 + row) * EE + kt * 32 + c4 * 4];
            __nv_bfloat162 h0 = __floats2bfloat162_rn(f.x, f.y);
            __nv_bfloat162 h1 = __floats2bfloat162_rn(f.z, f.w);
            __nv_bfloat162 l0 = __floats2bfloat162_rn(f.x - __bfloat162float(h0.x),
                                                      f.y - __bfloat162float(h0.y));
            __nv_bfloat162 l1 = __floats2bfloat162_rn(f.z - __bfloat162float(h1.x),
                                                      f.w - __bfloat162float(h1.y));
            uint2 uh; uh.x = *(uint32_t*)&h0; uh.y = *(uint32_t*)&h1;
            uint2 ul; ul.x = *(uint32_t*)&l0; ul.y = *(uint32_t*)&l1;
            *(uint2*)(base + PA_H + row * 80 + c4 * 8) = uh;
            *(uint2*)(base + PA_L + row * 80 + c4 * 8) = ul;
        }
    };

    load_tile(0, 0);

    for (int kt = 0; kt < 32; kt++) {
        const int cur = kt & 1;
        const uint32_t sb = sbase + cur * P_BUF;
        CP_WAIT0();
        __syncthreads();

        #pragma unroll
        for (int h = 0; h < 2; h++) {
            const uint32_t kb = h * 32;
            uint32_t ah[2][4], al[2][4];
            #pragma unroll
            for (int mb = 0; mb < 2; mb++) {
                uint32_t ra = (wm * 32 + mb * 16) * 80 + aoff + kb;
                ldsm4(ah[mb], sb + PA_H + ra);
                ldsm4(al[mb], sb + PA_L + ra);
            }
            #pragma unroll
            for (int jp = 0; jp < 4; jp++) {
                uint32_t bh4[4], bl4[4];
                uint32_t rb = (wn * 64 + jp * 16) * 80 + boff + kb;
                ldsm4(bh4, sb + PB_H + rb);
                ldsm4(bl4, sb + PB_L + rb);
                #pragma unroll
                for (int mb = 0; mb < 2; mb++) {
                    mma16816(acc[mb][2*jp],   ah[mb], bh4[0], bh4[1]);
                    mma16816(acc[mb][2*jp],   ah[mb], bl4[0], bl4[1]);
                    mma16816(acc[mb][2*jp],   al[mb], bh4[0], bh4[1]);
                    mma16816(acc[mb][2*jp+1], ah[mb], bh4[2], bh4[3]);
                    mma16816(acc[mb][2*jp+1], ah[mb], bl4[2], bl4[3]);
                    mma16816(acc[mb][2*jp+1], al[mb], bh4[2], bh4[3]);
                }
            }
        }
        if (kt < 31) load_tile(kt + 1, cur ^ 1);
    }

    const int g  = lane >> 2;
    const int q4 = lane & 3;
    #pragma unroll
    for (int mb = 0; mb < 2; mb++) {
        #pragma unroll
        for (int j = 0; j < 8; j++) {
            int gr  = m0 + wm * 32 + mb * 16 + g;
            int col = wn * 64 + j * 8 + q4 * 2;
            float c0 = acc[mb][j][0], c1 = acc[mb][j][1];
            float c2 = acc[mb][j][2], c3 = acc[mb][j][3];
            __nv_bfloat162 h01 = __floats2bfloat162_rn(c0, c1);
            __nv_bfloat162 h23 = __floats2bfloat162_rn(c2, c3);
            __nv_bfloat162 l01 = __floats2bfloat162_rn(c0 - __bfloat162float(h01.x),
                                                       c1 - __bfloat162float(h01.y));
            __nv_bfloat162 l23 = __floats2bfloat162_rn(c2 - __bfloat162float(h23.x),
                                                       c3 - __bfloat162float(h23.y));
            *(uint32_t*)&Yh[(size_t)gr * HH + col]       = *(uint32_t*)&h01;
            *(uint32_t*)&Yl[(size_t)gr * HH + col]       = *(uint32_t*)&l01;
            *(uint32_t*)&Yh[(size_t)(gr + 8) * HH + col] = *(uint32_t*)&h23;
            *(uint32_t*)&Yl[(size_t)(gr + 8) * HH + col] = *(uint32_t*)&l23;
        }
    }
}

// ---------------------------------------------------------------------------
// flash_hmma: causal flash attention, split-bf16 HMMA, split-KV warp groups.
// 256 threads = 2 groups x 4 warps. BQ=64, BKV=32.
// SM-load-balanced bid->(batch,qb) permutation: classic placement puts bid and
// bid+148 on the same SM; pair big+small jobs there, singles get the biggest.
// ---------------------------------------------------------------------------
#define FQ_H 0
#define FQ_L 17408
#define FKV  34816          // + grp*34816
#define KH_O 0
#define KL_O 8704
#define VH_O 17408
#define VL_O 26112
#define FLASH_SMEM 104448

__global__ __launch_bounds__(256, 2) void flash_hmma(float* __restrict__ out)
{
    extern __shared__ char sm[];
    const uint32_t sbase = smem_u32(sm);
    const int t    = threadIdx.x;
    const int lane = t & 31;
    const int wid  = t >> 5;
    const int grp  = wid >> 2;        // KV group 0/1
    const int wg   = wid & 3;         // warp within group -> 16 query rows
    const int gt   = t & 127;         // thread within group

    // ---- SM-load-balanced job assignment ----
    // jobs: (batch, qb), cost = qb+1 in [1..64], 4 batches.
    // bids 108..147 are single-CTA SMs -> 40 biggest jobs (qb 54..63).
    // bids 0..107 pair with bids 148..255 on the same SM -> rank r and 215-r
    // of the remaining 216 jobs (qb 0..53) sorted descending; sums ~55.
    int bid = blockIdx.x;
    int b, qb;
    if (bid >= 108 && bid < 148) {
        int s = bid - 108;
        qb = 63 - (s >> 2);
        b  = s & 3;
    } else {
        int r = (bid < 108) ? bid : (363 - bid);
        qb = 53 - (r >> 2);
        b  = r & 3;
    }

    const int q0   = qb * 64;
    const size_t bT = (size_t)b * TT;

    const uint32_t aoff = (uint32_t)((lane & 15) * 272 + (lane >> 4) * 16);
    const uint32_t boff = (uint32_t)((((lane & 7) | ((lane & 16) >> 1)) * 272) + (((lane >> 3) & 1) * 16));

    // ---- load Q tile (all 256 threads, cp.async) ----
    {
        const __nv_bfloat16* qh = g_qh + (bT + q0) * HH;
        const __nv_bfloat16* ql = g_ql + (bT + q0) * HH;
        #pragma unroll
        for (int i = 0; i < 4; i++) {
            int linear = i * 256 + t;
            int row = linear >> 4;
            int col = linear & 15;
            uint32_t so = row * 272 + col * 16;
            cp16(sbase + FQ_H + so, &qh[(size_t)row * HH + col * 8]);
            cp16(sbase + FQ_L + so, &ql[(size_t)row * HH + col * 8]);
        }
        CP_COMMIT(); CP_WAIT0();
    }
    __syncthreads();

    float o[16][4];
    #pragma unroll
    for (int j = 0; j < 16; j++)
        #pragma unroll
        for (int i = 0; i < 4; i++) o[j][i] = 0.f;
    float m0 = -1e30f, m1 = -1e30f, l0 = 0.f, l1 = 0.f;

    const float scale_l2 = 0.088388347648318447f * 1.4426950408889634f;  // /sqrt(128)*log2e
    const int g   = lane >> 2;
    const int q4  = lane & 3;
    const int rg0 = q0 + wg * 16 + g;

    const uint32_t kvb = sbase + FKV + grp * 34816;
    const int nkb = 2 * qb + 2;
    const int barid = grp + 1;

    for (int kb = grp; kb < nkb; kb += 2) {
        // ---- load this group's KV tile (128 threads, cp.async) ----
        {
            const size_t krow = bT + (size_t)kb * 32;
            #pragma unroll
            for (int i = 0; i < 4; i++) {
                int linear = i * 128 + gt;
                int row = linear >> 4;
                int col = linear & 15;
                uint32_t so = row * 272 + col * 16;
                size_t go = (krow + row) * HH + col * 8;
                cp16(kvb + KH_O + so, g_kh + go);
                cp16(kvb + KL_O + so, g_kl + go);
                cp16(kvb + VH_O + so, g_vh + go);
                cp16(kvb + VL_O + so, g_vl + go);
            }
            CP_COMMIT(); CP_WAIT0();
        }
        BAR_GRP(barid);

        // ---- S = Q K^T (split, 3 terms), 32 KV cols ----
        float s[4][4];
        #pragma unroll
        for (int j = 0; j < 4; j++)
            #pragma unroll
            for (int i = 0; i < 4; i++) s[j][i] = 0.f;

        #pragma unroll
        for (int k16 = 0; k16 < 8; k16++) {
            uint32_t qa_h[4], qa_l[4];
            uint32_t qr = wg * 16 * 272 + aoff + k16 * 32;
            ldsm4(qa_h, sbase + FQ_H + qr);
            ldsm4(qa_l, sbase + FQ_L + qr);
            #pragma unroll
            for (int jp = 0; jp < 2; jp++) {
                uint32_t kh4[4], kl4[4];
                uint32_t kr = jp * 16 * 272 + boff + k16 * 32;
                ldsm4(kh4, kvb + KH_O + kr);
                ldsm4(kl4, kvb + KL_O + kr);
                mma16816(s[2*jp],   qa_h, kh4[0], kh4[1]);
                mma16816(s[2*jp],   qa_h, kl4[0], kl4[1]);
                mma16816(s[2*jp],   qa_l, kh4[0], kh4[1]);
                mma16816(s[2*jp+1], qa_h, kh4[2], kh4[3]);
                mma16816(s[2*jp+1], qa_h, kl4[2], kl4[3]);
                mma16816(s[2*jp+1], qa_l, kh4[2], kh4[3]);
            }
        }

        // ---- scale (log2 domain) + causal mask ----
        #pragma unroll
        for (int j = 0; j < 4; j++)
            #pragma unroll
            for (int i = 0; i < 4; i++) s[j][i] *= scale_l2;
        const int kv0 = kb * 32;
        if (kv0 + 31 > rg0) {
            int cbase = kv0 + q4 * 2;
            #pragma unroll
            for (int j = 0; j < 4; j++) {
                int c0 = cbase + j * 8;
                if (c0     > rg0)     s[j][0] = -1e30f;
                if (c0 + 1 > rg0)     s[j][1] = -1e30f;
                if (c0     > rg0 + 8) s[j][2] = -1e30f;
                if (c0 + 1 > rg0 + 8) s[j][3] = -1e30f;
            }
        }

        // ---- online softmax (rows g, g+8), exp2 domain ----
        float mx0 = -1e30f, mx1 = -1e30f;
        #pragma unroll
        for (int j = 0; j < 4; j++) {
            mx0 = fmaxf(mx0, fmaxf(s[j][0], s[j][1]));
            mx1 = fmaxf(mx1, fmaxf(s[j][2], s[j][3]));
        }
        mx0 = fmaxf(mx0, __shfl_xor_sync(0xffffffffu, mx0, 1));
        mx0 = fmaxf(mx0, __shfl_xor_sync(0xffffffffu, mx0, 2));
        mx1 = fmaxf(mx1, __shfl_xor_sync(0xffffffffu, mx1, 1));
        mx1 = fmaxf(mx1, __shfl_xor_sync(0xffffffffu, mx1, 2));
        float m0n = fmaxf(m0, mx0), m1n = fmaxf(m1, mx1);
        float a0 = exp2f(m0 - m0n), a1 = exp2f(m1 - m1n);
        m0 = m0n; m1 = m1n;

        // all-masked-safe exponent base
        float esub0 = fmaxf(m0n, -1e20f);
        float esub1 = fmaxf(m1n, -1e20f);

        uint32_t ph01[4], ph23[4], pl01[4], pl23[4];
        float sum0 = 0.f, sum1 = 0.f;
        #pragma unroll
        for (int j = 0; j < 4; j++) {
            float p0 = exp2f(s[j][0] - esub0);
            float p1 = exp2f(s[j][1] - esub0);
            float p2 = exp2f(s[j][2] - esub1);
            float p3 = exp2f(s[j][3] - esub1);
            sum0 += p0 + p1; sum1 += p2 + p3;
            __nv_bfloat162 h01 = __floats2bfloat162_rn(p0, p1);
            __nv_bfloat162 h23 = __floats2bfloat162_rn(p2, p3);
            ph01[j] = *(uint32_t*)&h01;
            ph23[j] = *(uint32_t*)&h23;
            pl01[j] = pack_bf16(p0 - __bfloat162float(h01.x), p1 - __bfloat162float(h01.y));
            pl23[j] = pack_bf16(p2 - __bfloat162float(h23.x), p3 - __bfloat162float(h23.y));
        }
        sum0 += __shfl_xor_sync(0xffffffffu, sum0, 1);
        sum0 += __shfl_xor_sync(0xffffffffu, sum0, 2);
        sum1 += __shfl_xor_sync(0xffffffffu, sum1, 1);
        sum1 += __shfl_xor_sync(0xffffffffu, sum1, 2);
        l0 = l0 * a0 + sum0;
        l1 = l1 * a1 + sum1;

        #pragma unroll
        for (int j = 0; j < 16; j++) {
            o[j][0] *= a0; o[j][1] *= a0;
            o[j][2] *= a1; o[j][3] *= a1;
        }

        // ---- O += P V (split, 3 terms) ----
        #pragma unroll
        for (int ks = 0; ks < 2; ks++) {
            uint32_t pah[4] = { ph01[2*ks], ph23[2*ks], ph01[2*ks+1], ph23[2*ks+1] };
            uint32_t pal[4] = { pl01[2*ks], pl23[2*ks], pl01[2*ks+1], pl23[2*ks+1] };
            #pragma unroll
            for (int hp = 0; hp < 8; hp++) {
                uint32_t vh4[4], vl4[4];
                uint32_t vr = ks * 16 * 272 + aoff + hp * 32;
                ldsm4t(vh4, kvb + VH_O + vr);
                ldsm4t(vl4, kvb + VL_O + vr);
                mma16816(o[2*hp],   pah, vh4[0], vh4[1]);
                mma16816(o[2*hp],   pah, vl4[0], vl4[1]);
                mma16816(o[2*hp],   pal, vh4[0], vh4[1]);
                mma16816(o[2*hp+1], pah, vh4[2], vh4[3]);
                mma16816(o[2*hp+1], pah, vl4[2], vl4[3]);
                mma16816(o[2*hp+1], pal, vh4[2], vh4[3]);
            }
        }
        BAR_GRP(barid);   // group done reading buffer before next overwrite
    }

    // ---- merge group states (group1 -> smem -> group0) ----
    __syncthreads();
    float* mrg = (float*)(sm + FKV);
    const int slot = (wg * 32 + lane) * 69;
    if (grp == 1) {
        float* d = mrg + slot;
        #pragma unroll
        for (int j = 0; j < 16; j++) {
            d[j*4+0] = o[j][0]; d[j*4+1] = o[j][1];
            d[j*4+2] = o[j][2]; d[j*4+3] = o[j][3];
        }
        d[64] = m0; d[65] = m1; d[66] = l0; d[67] = l1;
    }
    __syncthreads();
    if (grp == 0) {
        const float* s2 = mrg + slot;
        float mB0 = s2[64], mB1 = s2[65], lB0 = s2[66], lB1 = s2[67];
        float mS0 = fmaxf(m0, mB0), mS1 = fmaxf(m1, mB1);
        float wA0 = exp2f(m0 - mS0), wB0 = exp2f(mB0 - mS0);
        float wA1 = exp2f(m1 - mS1), wB1 = exp2f(mB1 - mS1);
        float inv0 = 1.f / (l0 * wA0 + lB0 * wB0);
        float inv1 = 1.f / (l1 * wA1 + lB1 * wB1);
        #pragma unroll
        for (int j = 0; j < 16; j++) {
            int col = j * 8 + q4 * 2;
            float2 v0, v1;
            v0.x = (o[j][0] * wA0 + s2[j*4+0] * wB0) * inv0;
            v0.y = (o[j][1] * wA0 + s2[j*4+1] * wB0) * inv0;
            v1.x = (o[j][2] * wA1 + s2[j*4+2] * wB1) * inv1;
            v1.y = (o[j][3] * wA1 + s2[j*4+3] * wB1) * inv1;
            *(float2*)&out[(bT + rg0) * HH + col]     = v0;
            *(float2*)&out[(bT + rg0 + 8) * HH + col] = v1;
        }
    }
}

// ---------------------------------------------------------------------------
extern "C" void kernel_launch(void* const* d_in, const int* in_sizes, int n_in,
                              void* d_out, int out_size)
{
    const float* k  = (const float*)d_in[0];
    const float* q  = (const float*)d_in[1];
    const float* v  = (const float*)d_in[2];
    const float* Wk = (const float*)d_in[3];
    const float* Wq = (const float*)d_in[4];
    const float* Wv = (const float*)d_in[5];
    float* out = (float*)d_out;

    prep_w<<<dim3(EE / 32, 3), 256>>>(Wk, Wq, Wv);

    cudaFuncSetAttribute(proj_hmma, cudaFuncAttributeMaxDynamicSharedMemorySize, PROJ_SMEM);
    proj_hmma<<<dim3(MTOT / 128, 3), 256, PROJ_SMEM>>>(k, q, v);

    cudaFuncSetAttribute(flash_hmma, cudaFuncAttributeMaxDynamicSharedMemorySize, FLASH_SMEM);
    flash_hmma<<<256, 256, FLASH_SMEM>>>(out);
}

// round 8
// speedup vs baseline: 4.1063x; 1.1815x over previous
#include <cuda_runtime.h>
#include <cuda_bf16.h>
#include <cuda_fp16.h>
#include <cstdint>

#define BB 4
#define TT 4096
#define EE 1024
#define HH 128
#define MTOT (BB*TT)

// scratch (device globals = allocation-free)
__device__ __align__(16) __nv_bfloat16 g_qh[(size_t)MTOT*HH];
__device__ __align__(16) __nv_bfloat16 g_ql[(size_t)MTOT*HH];
__device__ __align__(16) __nv_bfloat16 g_kh[(size_t)MTOT*HH];
__device__ __align__(16) __nv_bfloat16 g_kl[(size_t)MTOT*HH];
__device__ __align__(16) __half        g_vh[(size_t)MTOT*HH];      // V projected, fp16
__device__ __align__(16) __nv_bfloat16 g_wt_hi[3*(size_t)HH*EE];   // W^T split, [p][h][e]
__device__ __align__(16) __nv_bfloat16 g_wt_lo[3*(size_t)HH*EE];

// ---------------------------------------------------------------------------
// helpers
// ---------------------------------------------------------------------------
__device__ __forceinline__ uint32_t smem_u32(const void* p) {
    uint32_t a;
    asm("{ .reg .u64 t; cvta.to.shared.u64 t, %1; cvt.u32.u64 %0, t; }" : "=r"(a) : "l"(p));
    return a;
}
__device__ __forceinline__ void ldsm4(uint32_t* r, uint32_t a) {
    asm volatile("ldmatrix.sync.aligned.m8n8.x4.shared.b16 {%0,%1,%2,%3}, [%4];"
        : "=r"(r[0]), "=r"(r[1]), "=r"(r[2]), "=r"(r[3]) : "r"(a));
}
__device__ __forceinline__ void ldsm4t(uint32_t* r, uint32_t a) {
    asm volatile("ldmatrix.sync.aligned.m8n8.x4.trans.shared.b16 {%0,%1,%2,%3}, [%4];"
        : "=r"(r[0]), "=r"(r[1]), "=r"(r[2]), "=r"(r[3]) : "r"(a));
}
__device__ __forceinline__ void mma16816(float* c, const uint32_t* a, uint32_t b0, uint32_t b1) {
    asm volatile("mma.sync.aligned.m16n8k16.row.col.f32.bf16.bf16.f32 "
        "{%0,%1,%2,%3}, {%4,%5,%6,%7}, {%8,%9}, {%0,%1,%2,%3};"
        : "+f"(c[0]), "+f"(c[1]), "+f"(c[2]), "+f"(c[3])
        : "r"(a[0]), "r"(a[1]), "r"(a[2]), "r"(a[3]), "r"(b0), "r"(b1));
}
__device__ __forceinline__ void mma16816h(float* c, const uint32_t* a, uint32_t b0, uint32_t b1) {
    asm volatile("mma.sync.aligned.m16n8k16.row.col.f32.f16.f16.f32 "
        "{%0,%1,%2,%3}, {%4,%5,%6,%7}, {%8,%9}, {%0,%1,%2,%3};"
        : "+f"(c[0]), "+f"(c[1]), "+f"(c[2]), "+f"(c[3])
        : "r"(a[0]), "r"(a[1]), "r"(a[2]), "r"(a[3]), "r"(b0), "r"(b1));
}
__device__ __forceinline__ uint32_t pack_half(float a, float b) {
    __half2 h = __floats2half2_rn(a, b);
    return *(uint32_t*)&h;
}
__device__ __forceinline__ void cp16(uint32_t saddr, const void* gptr) {
    asm volatile("cp.async.cg.shared.global [%0], [%1], 16;"
        :: "r"(saddr), "l"(__cvta_generic_to_global(gptr)) : "memory");
}
#define CP_COMMIT() asm volatile("cp.async.commit_group;" ::: "memory")
#define CP_WAIT0()  asm volatile("cp.async.wait_group 0;" ::: "memory")
#define BAR_GRP(id) asm volatile("bar.sync %0, 128;" :: "r"(id) : "memory")

// ---------------------------------------------------------------------------
// prep_w: W [E,H] -> Wt [H,E] split hi/lo, via smem tile transpose (coalesced)
// ---------------------------------------------------------------------------
__global__ __launch_bounds__(256) void prep_w(
    const float* __restrict__ Wk, const float* __restrict__ Wq,
    const float* __restrict__ Wv)
{
    __shared__ float tile[32][129];
    const int p = blockIdx.y;
    const float* W = (p == 0) ? Wk : (p == 1) ? Wq : Wv;
    __nv_bfloat16* oh = g_wt_hi + (size_t)p * HH * EE;
    __nv_bfloat16* ol = g_wt_lo + (size_t)p * HH * EE;
    const int e0 = blockIdx.x * 32;

    #pragma unroll
    for (int i = 0; i < 16; i++) {
        int linear = i * 256 + threadIdx.x;
        int row = linear >> 7;
        int col = linear & 127;
        tile[row][col] = W[(size_t)(e0 + row) * HH + col];
    }
    __syncthreads();

    #pragma unroll
    for (int i = 0; i < 4; i++) {
        int linear = i * 256 + threadIdx.x;
        int h  = linear >> 3;
        int ec = linear & 7;
        __nv_bfloat16 hi4[4], lo4[4];
        #pragma unroll
        for (int r = 0; r < 4; r++) {
            float w = tile[ec * 4 + r][h];
            hi4[r] = __float2bfloat16_rn(w);
            lo4[r] = __float2bfloat16_rn(w - __bfloat162float(hi4[r]));
        }
        *(uint2*)&oh[(size_t)h * EE + e0 + ec * 4] = *(uint2*)hi4;
        *(uint2*)&ol[(size_t)h * EE + e0 + ec * 4] = *(uint2*)lo4;
    }
}

// ---------------------------------------------------------------------------
// proj_hmma: Y = X[16384,1024] @ W[1024,128], split-bf16 HMMA, double-buffered.
// K/Q outputs: bf16 hi/lo pairs. V output: fp16 (feeds fp16 2-term PV).
// ---------------------------------------------------------------------------
#define PA_H 0
#define PA_L 10240
#define PB_H 20480
#define PB_L 30720
#define P_BUF 40960
#define PROJ_SMEM 81920

__global__ __launch_bounds__(256, 2) void proj_hmma(
    const float* __restrict__ k_in, const float* __restrict__ q_in,
    const float* __restrict__ v_in)
{
    extern __shared__ char sm[];
    const uint32_t sbase = smem_u32(sm);
    const int t    = threadIdx.x;
    const int lane = t & 31;
    const int wid  = t >> 5;
    const int wm   = wid & 3;
    const int wn   = wid >> 2;
    const int p    = blockIdx.y;
    const int m0   = blockIdx.x * 128;

    const float* X = (p == 0) ? k_in : (p == 1) ? q_in : v_in;
    const __nv_bfloat16* WtH = g_wt_hi + (size_t)p * HH * EE;
    const __nv_bfloat16* WtL = g_wt_lo + (size_t)p * HH * EE;

    const uint32_t aoff = (uint32_t)((lane & 15) * 80 + (lane >> 4) * 16);
    const uint32_t boff = (uint32_t)((((lane & 7) | ((lane & 16) >> 1)) * 80) + (((lane >> 3) & 1) * 16));

    float acc[2][8][4];
    #pragma unroll
    for (int mb = 0; mb < 2; mb++)
        #pragma unroll
        for (int j = 0; j < 8; j++)
            #pragma unroll
            for (int i = 0; i < 4; i++) acc[mb][j][i] = 0.f;

    auto load_tile = [&](int kt, int buf) {
        char* base = sm + buf * P_BUF;
        uint32_t ubase = sbase + buf * P_BUF;
        #pragma unroll
        for (int i = 0; i < 2; i++) {
            int linear = i * 256 + t;
            int c4  = linear & 3;
            int row = linear >> 2;
            cp16(ubase + PB_H + row * 80 + c4 * 16, &WtH[(size_t)row * EE + kt * 32 + c4 * 8]);
            cp16(ubase + PB_L + row * 80 + c4 * 16, &WtL[(size_t)row * EE + kt * 32 + c4 * 8]);
        }
        CP_COMMIT();
        #pragma unroll
        for (int i = 0; i < 4; i++) {
            int linear = i * 256 + t;
            int c4  = linear & 7;
            int row = linear >> 3;
            float4 f = *(const float4*)&X[(size_t)(m0 + row) * EE + kt * 32 + c4 * 4];
            __nv_bfloat162 h0 = __floats2bfloat162_rn(f.x, f.y);
            __nv_bfloat162 h1 = __floats2bfloat162_rn(f.z, f.w);
            __nv_bfloat162 l0 = __floats2bfloat162_rn(f.x - __bfloat162float(h0.x),
                                                      f.y - __bfloat162float(h0.y));
            __nv_bfloat162 l1 = __floats2bfloat162_rn(f.z - __bfloat162float(h1.x),
                                                      f.w - __bfloat162float(h1.y));
            uint2 uh; uh.x = *(uint32_t*)&h0; uh.y = *(uint32_t*)&h1;
            uint2 ul; ul.x = *(uint32_t*)&l0; ul.y = *(uint32_t*)&l1;
            *(uint2*)(base + PA_H + row * 80 + c4 * 8) = uh;
            *(uint2*)(base + PA_L + row * 80 + c4 * 8) = ul;
        }
    };

    load_tile(0, 0);

    for (int kt = 0; kt < 32; kt++) {
        const int cur = kt & 1;
        const uint32_t sb = sbase + cur * P_BUF;
        CP_WAIT0();
        __syncthreads();

        #pragma unroll
        for (int h = 0; h < 2; h++) {
            const uint32_t kb = h * 32;
            uint32_t ah[2][4], al[2][4];
            #pragma unroll
            for (int mb = 0; mb < 2; mb++) {
                uint32_t ra = (wm * 32 + mb * 16) * 80 + aoff + kb;
                ldsm4(ah[mb], sb + PA_H + ra);
                ldsm4(al[mb], sb + PA_L + ra);
            }
            #pragma unroll
            for (int jp = 0; jp < 4; jp++) {
                uint32_t bh4[4], bl4[4];
                uint32_t rb = (wn * 64 + jp * 16) * 80 + boff + kb;
                ldsm4(bh4, sb + PB_H + rb);
                ldsm4(bl4, sb + PB_L + rb);
                #pragma unroll
                for (int mb = 0; mb < 2; mb++) {
                    mma16816(acc[mb][2*jp],   ah[mb], bh4[0], bh4[1]);
                    mma16816(acc[mb][2*jp],   ah[mb], bl4[0], bl4[1]);
                    mma16816(acc[mb][2*jp],   al[mb], bh4[0], bh4[1]);
                    mma16816(acc[mb][2*jp+1], ah[mb], bh4[2], bh4[3]);
                    mma16816(acc[mb][2*jp+1], ah[mb], bl4[2], bl4[3]);
                    mma16816(acc[mb][2*jp+1], al[mb], bh4[2], bh4[3]);
                }
            }
        }
        if (kt < 31) load_tile(kt + 1, cur ^ 1);
    }

    const int g  = lane >> 2;
    const int q4 = lane & 3;
    if (p == 2) {
        // V output: fp16
        #pragma unroll
        for (int mb = 0; mb < 2; mb++) {
            #pragma unroll
            for (int j = 0; j < 8; j++) {
                int gr  = m0 + wm * 32 + mb * 16 + g;
                int col = wn * 64 + j * 8 + q4 * 2;
                *(uint32_t*)&g_vh[(size_t)gr * HH + col] =
                    pack_half(acc[mb][j][0], acc[mb][j][1]);
                *(uint32_t*)&g_vh[(size_t)(gr + 8) * HH + col] =
                    pack_half(acc[mb][j][2], acc[mb][j][3]);
            }
        }
    } else {
        __nv_bfloat16* Yh = (p == 0) ? g_kh : g_qh;
        __nv_bfloat16* Yl = (p == 0) ? g_kl : g_ql;
        #pragma unroll
        for (int mb = 0; mb < 2; mb++) {
            #pragma unroll
            for (int j = 0; j < 8; j++) {
                int gr  = m0 + wm * 32 + mb * 16 + g;
                int col = wn * 64 + j * 8 + q4 * 2;
                float c0 = acc[mb][j][0], c1 = acc[mb][j][1];
                float c2 = acc[mb][j][2], c3 = acc[mb][j][3];
                __nv_bfloat162 h01 = __floats2bfloat162_rn(c0, c1);
                __nv_bfloat162 h23 = __floats2bfloat162_rn(c2, c3);
                __nv_bfloat162 l01 = __floats2bfloat162_rn(c0 - __bfloat162float(h01.x),
                                                           c1 - __bfloat162float(h01.y));
                __nv_bfloat162 l23 = __floats2bfloat162_rn(c2 - __bfloat162float(h23.x),
                                                           c3 - __bfloat162float(h23.y));
                *(uint32_t*)&Yh[(size_t)gr * HH + col]       = *(uint32_t*)&h01;
                *(uint32_t*)&Yl[(size_t)gr * HH + col]       = *(uint32_t*)&l01;
                *(uint32_t*)&Yh[(size_t)(gr + 8) * HH + col] = *(uint32_t*)&h23;
                *(uint32_t*)&Yl[(size_t)(gr + 8) * HH + col] = *(uint32_t*)&l23;
            }
        }
    }
}

// ---------------------------------------------------------------------------
// flash_hmma: causal flash attention. QK^T: split-bf16 3-term. PV: fp16 2-term.
// 256 threads = 2 KV groups x 4 warps. BQ=64, BKV=32.
// Pipelined: V double-buffered; K single-buffered, prefetched after S phase.
// ---------------------------------------------------------------------------
#define FQ_H 0
#define FQ_L 17408
#define FKV  34816          // + grp*34816
#define KH_O 0
#define KL_O 8704
#define VH0_O 17408
#define VH1_O 26112
#define FLASH_SMEM 104448

__global__ __launch_bounds__(256, 2) void flash_hmma(float* __restrict__ out)
{
    extern __shared__ char sm[];
    const uint32_t sbase = smem_u32(sm);
    const int t    = threadIdx.x;
    const int lane = t & 31;
    const int wid  = t >> 5;
    const int grp  = wid >> 2;
    const int wg   = wid & 3;
    const int gt   = t & 127;

    // SM-load-balanced bid -> (batch, qb): bid and bid+148 share an SM.
    int bid = blockIdx.x;
    int b, qb;
    if (bid >= 108 && bid < 148) {
        int s = bid - 108;
        qb = 63 - (s >> 2);
        b  = s & 3;
    } else {
        int r = (bid < 108) ? bid : (363 - bid);
        qb = 53 - (r >> 2);
        b  = r & 3;
    }

    const int q0   = qb * 64;
    const size_t bT = (size_t)b * TT;

    const uint32_t aoff = (uint32_t)((lane & 15) * 272 + (lane >> 4) * 16);
    const uint32_t boff = (uint32_t)((((lane & 7) | ((lane & 16) >> 1)) * 272) + (((lane >> 3) & 1) * 16));

    // ---- load Q tile (all 256 threads, cp.async) ----
    {
        const __nv_bfloat16* qh = g_qh + (bT + q0) * HH;
        const __nv_bfloat16* ql = g_ql + (bT + q0) * HH;
        #pragma unroll
        for (int i = 0; i < 4; i++) {
            int linear = i * 256 + t;
            int row = linear >> 4;
            int col = linear & 15;
            uint32_t so = row * 272 + col * 16;
            cp16(sbase + FQ_H + so, &qh[(size_t)row * HH + col * 8]);
            cp16(sbase + FQ_L + so, &ql[(size_t)row * HH + col * 8]);
        }
        CP_COMMIT(); CP_WAIT0();
    }
    __syncthreads();

    float o[16][4];
    #pragma unroll
    for (int j = 0; j < 16; j++)
        #pragma unroll
        for (int i = 0; i < 4; i++) o[j][i] = 0.f;
    float m0 = -1e30f, m1 = -1e30f, l0 = 0.f, l1 = 0.f;

    const float scale_l2 = 0.088388347648318447f * 1.4426950408889634f;
    const int g   = lane >> 2;
    const int q4  = lane & 3;
    const int rg0 = q0 + wg * 16 + g;

    const uint32_t kvb = sbase + FKV + grp * 34816;
    const int nkb = 2 * qb + 2;
    const int barid = grp + 1;

    // KV loader: K hi/lo bf16 + V fp16 (into the given V buffer)
    auto load_kv = [&](int kb, uint32_t vofs) {
        const size_t krow = bT + (size_t)kb * 32;
        #pragma unroll
        for (int i = 0; i < 4; i++) {
            int linear = i * 128 + gt;
            int row = linear >> 4;
            int col = linear & 15;
            uint32_t so = row * 272 + col * 16;
            size_t go = (krow + row) * HH + col * 8;
            cp16(kvb + KH_O + so, g_kh + go);
            cp16(kvb + KL_O + so, g_kl + go);
            cp16(kvb + vofs + so, g_vh + go);
        }
    };

    // prologue: first tile
    if (grp < nkb) load_kv(grp, VH0_O);
    CP_COMMIT();

    int vpar = 0;
    for (int kb = grp; kb < nkb; kb += 2) {
        CP_WAIT0();
        BAR_GRP(barid);
        const uint32_t vcur = kvb + (vpar ? VH1_O : VH0_O);

        // ---- S = Q K^T (split-bf16, 3 terms), 32 KV cols ----
        float s[4][4];
        #pragma unroll
        for (int j = 0; j < 4; j++)
            #pragma unroll
            for (int i = 0; i < 4; i++) s[j][i] = 0.f;

        #pragma unroll
        for (int k16 = 0; k16 < 8; k16++) {
            uint32_t qa_h[4], qa_l[4];
            uint32_t qr = wg * 16 * 272 + aoff + k16 * 32;
            ldsm4(qa_h, sbase + FQ_H + qr);
            ldsm4(qa_l, sbase + FQ_L + qr);
            #pragma unroll
            for (int jp = 0; jp < 2; jp++) {
                uint32_t kh4[4], kl4[4];
                uint32_t kr = jp * 16 * 272 + boff + k16 * 32;
                ldsm4(kh4, kvb + KH_O + kr);
                ldsm4(kl4, kvb + KL_O + kr);
                mma16816(s[2*jp],   qa_h, kh4[0], kh4[1]);
                mma16816(s[2*jp],   qa_h, kl4[0], kl4[1]);
                mma16816(s[2*jp],   qa_l, kh4[0], kh4[1]);
                mma16816(s[2*jp+1], qa_h, kh4[2], kh4[3]);
                mma16816(s[2*jp+1], qa_h, kl4[2], kl4[3]);
                mma16816(s[2*jp+1], qa_l, kh4[2], kh4[3]);
            }
        }

        // K buffer reads done -> prefetch next tile (K into same buf, V into other)
        BAR_GRP(barid);
        if (kb + 2 < nkb) load_kv(kb + 2, vpar ? VH0_O : VH1_O);
        CP_COMMIT();

        // ---- scale (log2 domain) + causal mask ----
        #pragma unroll
        for (int j = 0; j < 4; j++)
            #pragma unroll
            for (int i = 0; i < 4; i++) s[j][i] *= scale_l2;
        const int kv0 = kb * 32;
        if (kv0 + 31 > rg0) {
            int cbase = kv0 + q4 * 2;
            #pragma unroll
            for (int j = 0; j < 4; j++) {
                int c0 = cbase + j * 8;
                if (c0     > rg0)     s[j][0] = -1e30f;
                if (c0 + 1 > rg0)     s[j][1] = -1e30f;
                if (c0     > rg0 + 8) s[j][2] = -1e30f;
                if (c0 + 1 > rg0 + 8) s[j][3] = -1e30f;
            }
        }

        // ---- online softmax (rows g, g+8), exp2 domain ----
        float mx0 = -1e30f, mx1 = -1e30f;
        #pragma unroll
        for (int j = 0; j < 4; j++) {
            mx0 = fmaxf(mx0, fmaxf(s[j][0], s[j][1]));
            mx1 = fmaxf(mx1, fmaxf(s[j][2], s[j][3]));
        }
        mx0 = fmaxf(mx0, __shfl_xor_sync(0xffffffffu, mx0, 1));
        mx0 = fmaxf(mx0, __shfl_xor_sync(0xffffffffu, mx0, 2));
        mx1 = fmaxf(mx1, __shfl_xor_sync(0xffffffffu, mx1, 1));
        mx1 = fmaxf(mx1, __shfl_xor_sync(0xffffffffu, mx1, 2));
        float m0n = fmaxf(m0, mx0), m1n = fmaxf(m1, mx1);

        // warp-vote rescale skip: if no lane's max moved, O/l rescale is identity
        bool nochange = (m0n == m0) & (m1n == m1);
        bool skip = __all_sync(0xffffffffu, nochange);
        float a0 = 1.f, a1 = 1.f;
        if (!skip) {
            a0 = exp2f(m0 - m0n);
            a1 = exp2f(m1 - m1n);
            #pragma unroll
            for (int j = 0; j < 16; j++) {
                o[j][0] *= a0; o[j][1] *= a0;
                o[j][2] *= a1; o[j][3] *= a1;
            }
        }
        m0 = m0n; m1 = m1n;

        // all-masked-safe exponent base
        float esub0 = fmaxf(m0n, -1e20f);
        float esub1 = fmaxf(m1n, -1e20f);

        // P -> fp16 hi/lo (2-term PV)
        uint32_t ph01[4], ph23[4], pl01[4], pl23[4];
        float sum0 = 0.f, sum1 = 0.f;
        #pragma unroll
        for (int j = 0; j < 4; j++) {
            float p0 = exp2f(s[j][0] - esub0);
            float p1 = exp2f(s[j][1] - esub0);
            float p2 = exp2f(s[j][2] - esub1);
            float p3 = exp2f(s[j][3] - esub1);
            sum0 += p0 + p1; sum1 += p2 + p3;
            __half2 h01 = __floats2half2_rn(p0, p1);
            __half2 h23 = __floats2half2_rn(p2, p3);
            ph01[j] = *(uint32_t*)&h01;
            ph23[j] = *(uint32_t*)&h23;
            pl01[j] = pack_half(p0 - __low2float(h01), p1 - __high2float(h01));
            pl23[j] = pack_half(p2 - __low2float(h23), p3 - __high2float(h23));
        }
        sum0 += __shfl_xor_sync(0xffffffffu, sum0, 1);
        sum0 += __shfl_xor_sync(0xffffffffu, sum0, 2);
        sum1 += __shfl_xor_sync(0xffffffffu, sum1, 1);
        sum1 += __shfl_xor_sync(0xffffffffu, sum1, 2);
        l0 = l0 * a0 + sum0;
        l1 = l1 * a1 + sum1;

        // ---- O += P V (fp16, 2 terms) ----
        #pragma unroll
        for (int ks = 0; ks < 2; ks++) {
            uint32_t pah[4] = { ph01[2*ks], ph23[2*ks], ph01[2*ks+1], ph23[2*ks+1] };
            uint32_t pal[4] = { pl01[2*ks], pl23[2*ks], pl01[2*ks+1], pl23[2*ks+1] };
            #pragma unroll
            for (int hp = 0; hp < 8; hp++) {
                uint32_t vh4[4];
                uint32_t vr = ks * 16 * 272 + aoff + hp * 32;
                ldsm4t(vh4, vcur + vr);
                mma16816h(o[2*hp],   pah, vh4[0], vh4[1]);
                mma16816h(o[2*hp],   pal, vh4[0], vh4[1]);
                mma16816h(o[2*hp+1], pah, vh4[2], vh4[3]);
                mma16816h(o[2*hp+1], pal, vh4[2], vh4[3]);
            }
        }
        vpar ^= 1;
    }

    // ---- merge group states (group1 -> smem -> group0) ----
    __syncthreads();
    float* mrg = (float*)(sm + FKV);
    const int slot = (wg * 32 + lane) * 69;
    if (grp == 1) {
        float* d = mrg + slot;
        #pragma unroll
        for (int j = 0; j < 16; j++) {
            d[j*4+0] = o[j][0]; d[j*4+1] = o[j][1];
            d[j*4+2] = o[j][2]; d[j*4+3] = o[j][3];
        }
        d[64] = m0; d[65] = m1; d[66] = l0; d[67] = l1;
    }
    __syncthreads();
    if (grp == 0) {
        const float* s2 = mrg + slot;
        float mB0 = s2[64], mB1 = s2[65], lB0 = s2[66], lB1 = s2[67];
        float mS0 = fmaxf(m0, mB0), mS1 = fmaxf(m1, mB1);
        float wA0 = exp2f(m0 - mS0), wB0 = exp2f(mB0 - mS0);
        float wA1 = exp2f(m1 - mS1), wB1 = exp2f(mB1 - mS1);
        float inv0 = 1.f / (l0 * wA0 + lB0 * wB0);
        float inv1 = 1.f / (l1 * wA1 + lB1 * wB1);
        #pragma unroll
        for (int j = 0; j < 16; j++) {
            int col = j * 8 + q4 * 2;
            float2 v0, v1;
            v0.x = (o[j][0] * wA0 + s2[j*4+0] * wB0) * inv0;
            v0.y = (o[j][1] * wA0 + s2[j*4+1] * wB0) * inv0;
            v1.x = (o[j][2] * wA1 + s2[j*4+2] * wB1) * inv1;
            v1.y = (o[j][3] * wA1 + s2[j*4+3] * wB1) * inv1;
            *(float2*)&out[(bT + rg0) * HH + col]     = v0;
            *(float2*)&out[(bT + rg0 + 8) * HH + col] = v1;
        }
    }
}

// ---------------------------------------------------------------------------
extern "C" void kernel_launch(void* const* d_in, const int* in_sizes, int n_in,
                              void* d_out, int out_size)
{
    const float* k  = (const float*)d_in[0];
    const float* q  = (const float*)d_in[1];
    const float* v  = (const float*)d_in[2];
    const float* Wk = (const float*)d_in[3];
    const float* Wq = (const float*)d_in[4];
    const float* Wv = (const float*)d_in[5];
    float* out = (float*)d_out;

    prep_w<<<dim3(EE / 32, 3), 256>>>(Wk, Wq, Wv);

    cudaFuncSetAttribute(proj_hmma, cudaFuncAttributeMaxDynamicSharedMemorySize, PROJ_SMEM);
    proj_hmma<<<dim3(MTOT / 128, 3), 256, PROJ_SMEM>>>(k, q, v);

    cudaFuncSetAttribute(flash_hmma, cudaFuncAttributeMaxDynamicSharedMemorySize, FLASH_SMEM);
    flash_hmma<<<256, 256, FLASH_SMEM>>>(out);
}

// round 9
// speedup vs baseline: 4.5650x; 1.1117x over previous
#include <cuda_runtime.h>
#include <cuda_bf16.h>
#include <cuda_fp16.h>
#include <cstdint>

#define BB 4
#define TT 4096
#define EE 1024
#define HH 128
#define MTOT (BB*TT)

// scratch (device globals = allocation-free)
__device__ __align__(16) __half        g_qhi[(size_t)MTOT*HH];     // Q fp16 hi
__device__ __align__(16) __half        g_qlo[(size_t)MTOT*HH];     // Q fp16 lo
__device__ __align__(16) __half        g_k[(size_t)MTOT*HH];       // K fp16
__device__ __align__(16) __half        g_v[(size_t)MTOT*HH];       // V fp16
__device__ __align__(16) __nv_bfloat16 g_wt_hi[3*(size_t)HH*EE];   // W^T split, [p][h][e]
__device__ __align__(16) __nv_bfloat16 g_wt_lo[3*(size_t)HH*EE];

// ---------------------------------------------------------------------------
// helpers
// ---------------------------------------------------------------------------
__device__ __forceinline__ uint32_t smem_u32(const void* p) {
    uint32_t a;
    asm("{ .reg .u64 t; cvta.to.shared.u64 t, %1; cvt.u32.u64 %0, t; }" : "=r"(a) : "l"(p));
    return a;
}
__device__ __forceinline__ void ldsm4(uint32_t* r, uint32_t a) {
    asm volatile("ldmatrix.sync.aligned.m8n8.x4.shared.b16 {%0,%1,%2,%3}, [%4];"
        : "=r"(r[0]), "=r"(r[1]), "=r"(r[2]), "=r"(r[3]) : "r"(a));
}
__device__ __forceinline__ void ldsm4t(uint32_t* r, uint32_t a) {
    asm volatile("ldmatrix.sync.aligned.m8n8.x4.trans.shared.b16 {%0,%1,%2,%3}, [%4];"
        : "=r"(r[0]), "=r"(r[1]), "=r"(r[2]), "=r"(r[3]) : "r"(a));
}
__device__ __forceinline__ void mma16816(float* c, const uint32_t* a, uint32_t b0, uint32_t b1) {
    asm volatile("mma.sync.aligned.m16n8k16.row.col.f32.bf16.bf16.f32 "
        "{%0,%1,%2,%3}, {%4,%5,%6,%7}, {%8,%9}, {%0,%1,%2,%3};"
        : "+f"(c[0]), "+f"(c[1]), "+f"(c[2]), "+f"(c[3])
        : "r"(a[0]), "r"(a[1]), "r"(a[2]), "r"(a[3]), "r"(b0), "r"(b1));
}
__device__ __forceinline__ void mma16816h(float* c, const uint32_t* a, uint32_t b0, uint32_t b1) {
    asm volatile("mma.sync.aligned.m16n8k16.row.col.f32.f16.f16.f32 "
        "{%0,%1,%2,%3}, {%4,%5,%6,%7}, {%8,%9}, {%0,%1,%2,%3};"
        : "+f"(c[0]), "+f"(c[1]), "+f"(c[2]), "+f"(c[3])
        : "r"(a[0]), "r"(a[1]), "r"(a[2]), "r"(a[3]), "r"(b0), "r"(b1));
}
__device__ __forceinline__ uint32_t pack_half(float a, float b) {
    __half2 h = __floats2half2_rn(a, b);
    return *(uint32_t*)&h;
}
__device__ __forceinline__ void cp16(uint32_t saddr, const void* gptr) {
    asm volatile("cp.async.cg.shared.global [%0], [%1], 16;"
        :: "r"(saddr), "l"(__cvta_generic_to_global(gptr)) : "memory");
}
#define CP_COMMIT() asm volatile("cp.async.commit_group;" ::: "memory")
#define CP_WAIT0()  asm volatile("cp.async.wait_group 0;" ::: "memory")
#define BAR_GRP(id) asm volatile("bar.sync %0, 128;" :: "r"(id) : "memory")

// ---------------------------------------------------------------------------
// prep_w: W [E,H] -> Wt [H,E] split bf16 hi/lo (for the fp32-accurate proj)
// ---------------------------------------------------------------------------
__global__ __launch_bounds__(256) void prep_w(
    const float* __restrict__ Wk, const float* __restrict__ Wq,
    const float* __restrict__ Wv)
{
    __shared__ float tile[32][129];
    const int p = blockIdx.y;
    const float* W = (p == 0) ? Wk : (p == 1) ? Wq : Wv;
    __nv_bfloat16* oh = g_wt_hi + (size_t)p * HH * EE;
    __nv_bfloat16* ol = g_wt_lo + (size_t)p * HH * EE;
    const int e0 = blockIdx.x * 32;

    #pragma unroll
    for (int i = 0; i < 16; i++) {
        int linear = i * 256 + threadIdx.x;
        int row = linear >> 7;
        int col = linear & 127;
        tile[row][col] = W[(size_t)(e0 + row) * HH + col];
    }
    __syncthreads();

    #pragma unroll
    for (int i = 0; i < 4; i++) {
        int linear = i * 256 + threadIdx.x;
        int h  = linear >> 3;
        int ec = linear & 7;
        __nv_bfloat16 hi4[4], lo4[4];
        #pragma unroll
        for (int r = 0; r < 4; r++) {
            float w = tile[ec * 4 + r][h];
            hi4[r] = __float2bfloat16_rn(w);
            lo4[r] = __float2bfloat16_rn(w - __bfloat162float(hi4[r]));
        }
        *(uint2*)&oh[(size_t)h * EE + e0 + ec * 4] = *(uint2*)hi4;
        *(uint2*)&ol[(size_t)h * EE + e0 + ec * 4] = *(uint2*)lo4;
    }
}

// ---------------------------------------------------------------------------
// proj_hmma: Y = X[16384,1024] @ W[1024,128], split-bf16 HMMA, double-buffered.
// Epilogue: Q -> fp16 hi/lo; K, V -> fp16 single.
// ---------------------------------------------------------------------------
#define PA_H 0
#define PA_L 10240
#define PB_H 20480
#define PB_L 30720
#define P_BUF 40960
#define PROJ_SMEM 81920

__global__ __launch_bounds__(256, 2) void proj_hmma(
    const float* __restrict__ k_in, const float* __restrict__ q_in,
    const float* __restrict__ v_in)
{
    extern __shared__ char sm[];
    const uint32_t sbase = smem_u32(sm);
    const int t    = threadIdx.x;
    const int lane = t & 31;
    const int wid  = t >> 5;
    const int wm   = wid & 3;
    const int wn   = wid >> 2;
    const int p    = blockIdx.y;
    const int m0   = blockIdx.x * 128;

    const float* X = (p == 0) ? k_in : (p == 1) ? q_in : v_in;
    const __nv_bfloat16* WtH = g_wt_hi + (size_t)p * HH * EE;
    const __nv_bfloat16* WtL = g_wt_lo + (size_t)p * HH * EE;

    const uint32_t aoff = (uint32_t)((lane & 15) * 80 + (lane >> 4) * 16);
    const uint32_t boff = (uint32_t)((((lane & 7) | ((lane & 16) >> 1)) * 80) + (((lane >> 3) & 1) * 16));

    float acc[2][8][4];
    #pragma unroll
    for (int mb = 0; mb < 2; mb++)
        #pragma unroll
        for (int j = 0; j < 8; j++)
            #pragma unroll
            for (int i = 0; i < 4; i++) acc[mb][j][i] = 0.f;

    auto load_tile = [&](int kt, int buf) {
        char* base = sm + buf * P_BUF;
        uint32_t ubase = sbase + buf * P_BUF;
        #pragma unroll
        for (int i = 0; i < 2; i++) {
            int linear = i * 256 + t;
            int c4  = linear & 3;
            int row = linear >> 2;
            cp16(ubase + PB_H + row * 80 + c4 * 16, &WtH[(size_t)row * EE + kt * 32 + c4 * 8]);
            cp16(ubase + PB_L + row * 80 + c4 * 16, &WtL[(size_t)row * EE + kt * 32 + c4 * 8]);
        }
        CP_COMMIT();
        #pragma unroll
        for (int i = 0; i < 4; i++) {
            int linear = i * 256 + t;
            int c4  = linear & 7;
            int row = linear >> 3;
            float4 f = *(const float4*)&X[(size_t)(m0 + row) * EE + kt * 32 + c4 * 4];
            __nv_bfloat162 h0 = __floats2bfloat162_rn(f.x, f.y);
            __nv_bfloat162 h1 = __floats2bfloat162_rn(f.z, f.w);
            __nv_bfloat162 l0 = __floats2bfloat162_rn(f.x - __bfloat162float(h0.x),
                                                      f.y - __bfloat162float(h0.y));
            __nv_bfloat162 l1 = __floats2bfloat162_rn(f.z - __bfloat162float(h1.x),
                                                      f.w - __bfloat162float(h1.y));
            uint2 uh; uh.x = *(uint32_t*)&h0; uh.y = *(uint32_t*)&h1;
            uint2 ul; ul.x = *(uint32_t*)&l0; ul.y = *(uint32_t*)&l1;
            *(uint2*)(base + PA_H + row * 80 + c4 * 8) = uh;
            *(uint2*)(base + PA_L + row * 80 + c4 * 8) = ul;
        }
    };

    load_tile(0, 0);

    for (int kt = 0; kt < 32; kt++) {
        const int cur = kt & 1;
        const uint32_t sb = sbase + cur * P_BUF;
        CP_WAIT0();
        __syncthreads();

        #pragma unroll
        for (int h = 0; h < 2; h++) {
            const uint32_t kb = h * 32;
            uint32_t ah[2][4], al[2][4];
            #pragma unroll
            for (int mb = 0; mb < 2; mb++) {
                uint32_t ra = (wm * 32 + mb * 16) * 80 + aoff + kb;
                ldsm4(ah[mb], sb + PA_H + ra);
                ldsm4(al[mb], sb + PA_L + ra);
            }
            #pragma unroll
            for (int jp = 0; jp < 4; jp++) {
                uint32_t bh4[4], bl4[4];
                uint32_t rb = (wn * 64 + jp * 16) * 80 + boff + kb;
                ldsm4(bh4, sb + PB_H + rb);
                ldsm4(bl4, sb + PB_L + rb);
                #pragma unroll
                for (int mb = 0; mb < 2; mb++) {
                    mma16816(acc[mb][2*jp],   ah[mb], bh4[0], bh4[1]);
                    mma16816(acc[mb][2*jp],   ah[mb], bl4[0], bl4[1]);
                    mma16816(acc[mb][2*jp],   al[mb], bh4[0], bh4[1]);
                    mma16816(acc[mb][2*jp+1], ah[mb], bh4[2], bh4[3]);
                    mma16816(acc[mb][2*jp+1], ah[mb], bl4[2], bl4[3]);
                    mma16816(acc[mb][2*jp+1], al[mb], bh4[2], bh4[3]);
                }
            }
        }
        if (kt < 31) load_tile(kt + 1, cur ^ 1);
    }

    const int g  = lane >> 2;
    const int q4 = lane & 3;
    if (p == 1) {
        // Q: fp16 hi/lo
        #pragma unroll
        for (int mb = 0; mb < 2; mb++) {
            #pragma unroll
            for (int j = 0; j < 8; j++) {
                int gr  = m0 + wm * 32 + mb * 16 + g;
                int col = wn * 64 + j * 8 + q4 * 2;
                float c0 = acc[mb][j][0], c1 = acc[mb][j][1];
                float c2 = acc[mb][j][2], c3 = acc[mb][j][3];
                __half2 h01 = __floats2half2_rn(c0, c1);
                __half2 h23 = __floats2half2_rn(c2, c3);
                *(uint32_t*)&g_qhi[(size_t)gr * HH + col]       = *(uint32_t*)&h01;
                *(uint32_t*)&g_qlo[(size_t)gr * HH + col]       =
                    pack_half(c0 - __low2float(h01), c1 - __high2float(h01));
                *(uint32_t*)&g_qhi[(size_t)(gr + 8) * HH + col] = *(uint32_t*)&h23;
                *(uint32_t*)&g_qlo[(size_t)(gr + 8) * HH + col] =
                    pack_half(c2 - __low2float(h23), c3 - __high2float(h23));
            }
        }
    } else {
        __half* Y = (p == 0) ? g_k : g_v;
        #pragma unroll
        for (int mb = 0; mb < 2; mb++) {
            #pragma unroll
            for (int j = 0; j < 8; j++) {
                int gr  = m0 + wm * 32 + mb * 16 + g;
                int col = wn * 64 + j * 8 + q4 * 2;
                *(uint32_t*)&Y[(size_t)gr * HH + col] =
                    pack_half(acc[mb][j][0], acc[mb][j][1]);
                *(uint32_t*)&Y[(size_t)(gr + 8) * HH + col] =
                    pack_half(acc[mb][j][2], acc[mb][j][3]);
            }
        }
    }
}

// ---------------------------------------------------------------------------
// flash_hmma: causal flash attention, all-fp16 MMA.
// QK^T: Q hi/lo x K single (2 terms). PV: P hi/lo x V single (2 terms).
// 256 threads = 2 KV groups x 4 warps. BQ=64, BKV=32.
// K and V both double-buffered; prefetch spans the whole iteration.
// ---------------------------------------------------------------------------
#define FQ_H 0
#define FQ_L 17408
#define FKV  34816          // + grp*34816
#define KBUF 0              // + par*8704
#define VBUF 17408          // + par*8704
#define FLASH_SMEM 104448

__global__ __launch_bounds__(256, 2) void flash_hmma(float* __restrict__ out)
{
    extern __shared__ char sm[];
    const uint32_t sbase = smem_u32(sm);
    const int t    = threadIdx.x;
    const int lane = t & 31;
    const int wid  = t >> 5;
    const int grp  = wid >> 2;
    const int wg   = wid & 3;
    const int gt   = t & 127;

    // SM-load-balanced bid -> (batch, qb): bid and bid+148 share an SM.
    int bid = blockIdx.x;
    int b, qb;
    if (bid >= 108 && bid < 148) {
        int s = bid - 108;
        qb = 63 - (s >> 2);
        b  = s & 3;
    } else {
        int r = (bid < 108) ? bid : (363 - bid);
        qb = 53 - (r >> 2);
        b  = r & 3;
    }

    const int q0   = qb * 64;
    const size_t bT = (size_t)b * TT;

    const uint32_t aoff = (uint32_t)((lane & 15) * 272 + (lane >> 4) * 16);
    const uint32_t boff = (uint32_t)((((lane & 7) | ((lane & 16) >> 1)) * 272) + (((lane >> 3) & 1) * 16));

    // ---- load Q tile (fp16 hi/lo, all 256 threads, cp.async) ----
    {
        const __half* qh = g_qhi + (bT + q0) * HH;
        const __half* ql = g_qlo + (bT + q0) * HH;
        #pragma unroll
        for (int i = 0; i < 4; i++) {
            int linear = i * 256 + t;
            int row = linear >> 4;
            int col = linear & 15;
            uint32_t so = row * 272 + col * 16;
            cp16(sbase + FQ_H + so, &qh[(size_t)row * HH + col * 8]);
            cp16(sbase + FQ_L + so, &ql[(size_t)row * HH + col * 8]);
        }
        CP_COMMIT(); CP_WAIT0();
    }
    __syncthreads();

    float o[16][4];
    #pragma unroll
    for (int j = 0; j < 16; j++)
        #pragma unroll
        for (int i = 0; i < 4; i++) o[j][i] = 0.f;
    float m0 = -1e30f, m1 = -1e30f, l0 = 0.f, l1 = 0.f;

    const float scale_l2 = 0.088388347648318447f * 1.4426950408889634f;
    const int g   = lane >> 2;
    const int q4  = lane & 3;
    const int rg0 = q0 + wg * 16 + g;

    const uint32_t kvb = sbase + FKV + grp * 34816;
    const int nkb = 2 * qb + 2;
    const int barid = grp + 1;

    // KV loader: K fp16 + V fp16 into parity buffers
    auto load_kv = [&](int kb, int par) {
        const size_t krow = bT + (size_t)kb * 32;
        uint32_t kd = kvb + KBUF + par * 8704;
        uint32_t vd = kvb + VBUF + par * 8704;
        #pragma unroll
        for (int i = 0; i < 4; i++) {
            int linear = i * 128 + gt;
            int row = linear >> 4;
            int col = linear & 15;
            uint32_t so = row * 272 + col * 16;
            size_t go = (krow + row) * HH + col * 8;
            cp16(kd + so, g_k + go);
            cp16(vd + so, g_v + go);
        }
    };

    // prologue
    if (grp < nkb) load_kv(grp, 0);
    CP_COMMIT();

    int par = 0;
    for (int kb = grp; kb < nkb; kb += 2, par ^= 1) {
        CP_WAIT0();
        BAR_GRP(barid);      // tile kb visible group-wide; prev buffers free

        // prefetch next tile immediately — latency covered by whole iteration
        if (kb + 2 < nkb) load_kv(kb + 2, par ^ 1);
        CP_COMMIT();

        const uint32_t kcur = kvb + KBUF + par * 8704;
        const uint32_t vcur = kvb + VBUF + par * 8704;

        // ---- S = Q K^T (fp16, 2 terms), 32 KV cols ----
        float s[4][4];
        #pragma unroll
        for (int j = 0; j < 4; j++)
            #pragma unroll
            for (int i = 0; i < 4; i++) s[j][i] = 0.f;

        #pragma unroll
        for (int k16 = 0; k16 < 8; k16++) {
            uint32_t qa_h[4], qa_l[4];
            uint32_t qr = wg * 16 * 272 + aoff + k16 * 32;
            ldsm4(qa_h, sbase + FQ_H + qr);
            ldsm4(qa_l, sbase + FQ_L + qr);
            #pragma unroll
            for (int jp = 0; jp < 2; jp++) {
                uint32_t k4[4];
                uint32_t kr = jp * 16 * 272 + boff + k16 * 32;
                ldsm4(k4, kcur + kr);
                mma16816h(s[2*jp],   qa_h, k4[0], k4[1]);
                mma16816h(s[2*jp],   qa_l, k4[0], k4[1]);
                mma16816h(s[2*jp+1], qa_h, k4[2], k4[3]);
                mma16816h(s[2*jp+1], qa_l, k4[2], k4[3]);
            }
        }

        // ---- scale (log2 domain) + causal mask ----
        #pragma unroll
        for (int j = 0; j < 4; j++)
            #pragma unroll
            for (int i = 0; i < 4; i++) s[j][i] *= scale_l2;
        const int kv0 = kb * 32;
        if (kv0 + 31 > rg0) {
            int cbase = kv0 + q4 * 2;
            #pragma unroll
            for (int j = 0; j < 4; j++) {
                int c0 = cbase + j * 8;
                if (c0     > rg0)     s[j][0] = -1e30f;
                if (c0 + 1 > rg0)     s[j][1] = -1e30f;
                if (c0     > rg0 + 8) s[j][2] = -1e30f;
                if (c0 + 1 > rg0 + 8) s[j][3] = -1e30f;
            }
        }

        // ---- online softmax (rows g, g+8), exp2 domain ----
        float mx0 = -1e30f, mx1 = -1e30f;
        #pragma unroll
        for (int j = 0; j < 4; j++) {
            mx0 = fmaxf(mx0, fmaxf(s[j][0], s[j][1]));
            mx1 = fmaxf(mx1, fmaxf(s[j][2], s[j][3]));
        }
        mx0 = fmaxf(mx0, __shfl_xor_sync(0xffffffffu, mx0, 1));
        mx0 = fmaxf(mx0, __shfl_xor_sync(0xffffffffu, mx0, 2));
        mx1 = fmaxf(mx1, __shfl_xor_sync(0xffffffffu, mx1, 1));
        mx1 = fmaxf(mx1, __shfl_xor_sync(0xffffffffu, mx1, 2));
        float m0n = fmaxf(m0, mx0), m1n = fmaxf(m1, mx1);

        // warp-vote rescale skip
        bool nochange = (m0n == m0) & (m1n == m1);
        bool skip = __all_sync(0xffffffffu, nochange);
        float a0 = 1.f, a1 = 1.f;
        if (!skip) {
            a0 = exp2f(m0 - m0n);
            a1 = exp2f(m1 - m1n);
            #pragma unroll
            for (int j = 0; j < 16; j++) {
                o[j][0] *= a0; o[j][1] *= a0;
                o[j][2] *= a1; o[j][3] *= a1;
            }
        }
        m0 = m0n; m1 = m1n;

        // all-masked-safe exponent base
        float esub0 = fmaxf(m0n, -1e20f);
        float esub1 = fmaxf(m1n, -1e20f);

        // P -> fp16 hi/lo (2-term PV)
        uint32_t ph01[4], ph23[4], pl01[4], pl23[4];
        float sum0 = 0.f, sum1 = 0.f;
        #pragma unroll
        for (int j = 0; j < 4; j++) {
            float p0 = exp2f(s[j][0] - esub0);
            float p1 = exp2f(s[j][1] - esub0);
            float p2 = exp2f(s[j][2] - esub1);
            float p3 = exp2f(s[j][3] - esub1);
            sum0 += p0 + p1; sum1 += p2 + p3;
            __half2 h01 = __floats2half2_rn(p0, p1);
            __half2 h23 = __floats2half2_rn(p2, p3);
            ph01[j] = *(uint32_t*)&h01;
            ph23[j] = *(uint32_t*)&h23;
            pl01[j] = pack_half(p0 - __low2float(h01), p1 - __high2float(h01));
            pl23[j] = pack_half(p2 - __low2float(h23), p3 - __high2float(h23));
        }
        sum0 += __shfl_xor_sync(0xffffffffu, sum0, 1);
        sum0 += __shfl_xor_sync(0xffffffffu, sum0, 2);
        sum1 += __shfl_xor_sync(0xffffffffu, sum1, 1);
        sum1 += __shfl_xor_sync(0xffffffffu, sum1, 2);
        l0 = l0 * a0 + sum0;
        l1 = l1 * a1 + sum1;

        // ---- O += P V (fp16, 2 terms) ----
        #pragma unroll
        for (int ks = 0; ks < 2; ks++) {
            uint32_t pah[4] = { ph01[2*ks], ph23[2*ks], ph01[2*ks+1], ph23[2*ks+1] };
            uint32_t pal[4] = { pl01[2*ks], pl23[2*ks], pl01[2*ks+1], pl23[2*ks+1] };
            #pragma unroll
            for (int hp = 0; hp < 8; hp++) {
                uint32_t vh4[4];
                uint32_t vr = ks * 16 * 272 + aoff + hp * 32;
                ldsm4t(vh4, vcur + vr);
                mma16816h(o[2*hp],   pah, vh4[0], vh4[1]);
                mma16816h(o[2*hp],   pal, vh4[0], vh4[1]);
                mma16816h(o[2*hp+1], pah, vh4[2], vh4[3]);
                mma16816h(o[2*hp+1], pal, vh4[2], vh4[3]);
            }
        }
    }

    // ---- merge group states (group1 -> smem -> group0) ----
    __syncthreads();
    float* mrg = (float*)(sm + FKV);
    const int slot = (wg * 32 + lane) * 69;
    if (grp == 1) {
        float* d = mrg + slot;
        #pragma unroll
        for (int j = 0; j < 16; j++) {
            d[j*4+0] = o[j][0]; d[j*4+1] = o[j][1];
            d[j*4+2] = o[j][2]; d[j*4+3] = o[j][3];
        }
        d[64] = m0; d[65] = m1; d[66] = l0; d[67] = l1;
    }
    __syncthreads();
    if (grp == 0) {
        const float* s2 = mrg + slot;
        float mB0 = s2[64], mB1 = s2[65], lB0 = s2[66], lB1 = s2[67];
        float mS0 = fmaxf(m0, mB0), mS1 = fmaxf(m1, mB1);
        float wA0 = exp2f(m0 - mS0), wB0 = exp2f(mB0 - mS0);
        float wA1 = exp2f(m1 - mS1), wB1 = exp2f(mB1 - mS1);
        float inv0 = 1.f / (l0 * wA0 + lB0 * wB0);
        float inv1 = 1.f / (l1 * wA1 + lB1 * wB1);
        #pragma unroll
        for (int j = 0; j < 16; j++) {
            int col = j * 8 + q4 * 2;
            float2 v0, v1;
            v0.x = (o[j][0] * wA0 + s2[j*4+0] * wB0) * inv0;
            v0.y = (o[j][1] * wA0 + s2[j*4+1] * wB0) * inv0;
            v1.x = (o[j][2] * wA1 + s2[j*4+2] * wB1) * inv1;
            v1.y = (o[j][3] * wA1 + s2[j*4+3] * wB1) * inv1;
            *(float2*)&out[(bT + rg0) * HH + col]     = v0;
            *(float2*)&out[(bT + rg0 + 8) * HH + col] = v1;
        }
    }
}

// ---------------------------------------------------------------------------
extern "C" void kernel_launch(void* const* d_in, const int* in_sizes, int n_in,
                              void* d_out, int out_size)
{
    const float* k  = (const float*)d_in[0];
    const float* q  = (const float*)d_in[1];
    const float* v  = (const float*)d_in[2];
    const float* Wk = (const float*)d_in[3];
    const float* Wq = (const float*)d_in[4];
    const float* Wv = (const float*)d_in[5];
    float* out = (float*)d_out;

    prep_w<<<dim3(EE / 32, 3), 256>>>(Wk, Wq, Wv);

    cudaFuncSetAttribute(proj_hmma, cudaFuncAttributeMaxDynamicSharedMemorySize, PROJ_SMEM);
    proj_hmma<<<dim3(MTOT / 128, 3), 256, PROJ_SMEM>>>(k, q, v);

    cudaFuncSetAttribute(flash_hmma, cudaFuncAttributeMaxDynamicSharedMemorySize, FLASH_SMEM);
    flash_hmma<<<256, 256, FLASH_SMEM>>>(out);
}

// round 10
// speedup vs baseline: 5.0314x; 1.1022x over previous
#include <cuda_runtime.h>
#include <cuda_bf16.h>
#include <cuda_fp16.h>
#include <cstdint>

#define BB 4
#define TT 4096
#define EE 1024
#define HH 128
#define MTOT (BB*TT)

// scratch (device globals = allocation-free)
__device__ __align__(16) __half g_qhi[(size_t)MTOT*HH];     // Q fp16 hi
__device__ __align__(16) __half g_qlo[(size_t)MTOT*HH];     // Q fp16 lo
__device__ __align__(16) __half g_k[(size_t)MTOT*HH];       // K fp16
__device__ __align__(16) __half g_v[(size_t)MTOT*HH];       // V fp16
__device__ __align__(16) __half g_wt[3*(size_t)HH*EE];      // W^T fp16, [p][h][e]

// ---------------------------------------------------------------------------
// helpers
// ---------------------------------------------------------------------------
__device__ __forceinline__ uint32_t smem_u32(const void* p) {
    uint32_t a;
    asm("{ .reg .u64 t; cvta.to.shared.u64 t, %1; cvt.u32.u64 %0, t; }" : "=r"(a) : "l"(p));
    return a;
}
__device__ __forceinline__ void ldsm4(uint32_t* r, uint32_t a) {
    asm volatile("ldmatrix.sync.aligned.m8n8.x4.shared.b16 {%0,%1,%2,%3}, [%4];"
        : "=r"(r[0]), "=r"(r[1]), "=r"(r[2]), "=r"(r[3]) : "r"(a));
}
__device__ __forceinline__ void ldsm4t(uint32_t* r, uint32_t a) {
    asm volatile("ldmatrix.sync.aligned.m8n8.x4.trans.shared.b16 {%0,%1,%2,%3}, [%4];"
        : "=r"(r[0]), "=r"(r[1]), "=r"(r[2]), "=r"(r[3]) : "r"(a));
}
__device__ __forceinline__ void mma16816h(float* c, const uint32_t* a, uint32_t b0, uint32_t b1) {
    asm volatile("mma.sync.aligned.m16n8k16.row.col.f32.f16.f16.f32 "
        "{%0,%1,%2,%3}, {%4,%5,%6,%7}, {%8,%9}, {%0,%1,%2,%3};"
        : "+f"(c[0]), "+f"(c[1]), "+f"(c[2]), "+f"(c[3])
        : "r"(a[0]), "r"(a[1]), "r"(a[2]), "r"(a[3]), "r"(b0), "r"(b1));
}
__device__ __forceinline__ uint32_t pack_half(float a, float b) {
    __half2 h = __floats2half2_rn(a, b);
    return *(uint32_t*)&h;
}
__device__ __forceinline__ void cp16(uint32_t saddr, const void* gptr) {
    asm volatile("cp.async.cg.shared.global [%0], [%1], 16;"
        :: "r"(saddr), "l"(__cvta_generic_to_global(gptr)) : "memory");
}
#define CP_COMMIT() asm volatile("cp.async.commit_group;" ::: "memory")
#define CP_WAIT0()  asm volatile("cp.async.wait_group 0;" ::: "memory")
#define BAR_GRP(id) asm volatile("bar.sync %0, 128;" :: "r"(id) : "memory")

// ---------------------------------------------------------------------------
// prep_w: W [E,H] -> Wt [H,E] fp16, via smem tile transpose (coalesced)
// ---------------------------------------------------------------------------
__global__ __launch_bounds__(256) void prep_w(
    const float* __restrict__ Wk, const float* __restrict__ Wq,
    const float* __restrict__ Wv)
{
    __shared__ float tile[32][129];
    const int p = blockIdx.y;
    const float* W = (p == 0) ? Wk : (p == 1) ? Wq : Wv;
    __half* ow = g_wt + (size_t)p * HH * EE;
    const int e0 = blockIdx.x * 32;

    #pragma unroll
    for (int i = 0; i < 16; i++) {
        int linear = i * 256 + threadIdx.x;
        int row = linear >> 7;
        int col = linear & 127;
        tile[row][col] = W[(size_t)(e0 + row) * HH + col];
    }
    __syncthreads();

    #pragma unroll
    for (int i = 0; i < 4; i++) {
        int linear = i * 256 + threadIdx.x;
        int h  = linear >> 3;
        int ec = linear & 7;
        __half h4[4];
        #pragma unroll
        for (int r = 0; r < 4; r++)
            h4[r] = __float2half_rn(tile[ec * 4 + r][h]);
        *(uint2*)&ow[(size_t)h * EE + e0 + ec * 4] = *(uint2*)h4;
    }
}

// ---------------------------------------------------------------------------
// proj_hmma: Y = X[16384,1024] @ W[1024,128], 2-term fp16 HMMA
// (X split fp16 hi/lo, W single fp16), double-buffered with cp.async.
// Epilogue: Q -> fp16 hi/lo; K, V -> fp16 single.
// ---------------------------------------------------------------------------
#define PA_H 0
#define PA_L 10240
#define PB   20480
#define P_BUF 30720
#define PROJ_SMEM 61440

__global__ __launch_bounds__(256, 2) void proj_hmma(
    const float* __restrict__ k_in, const float* __restrict__ q_in,
    const float* __restrict__ v_in)
{
    extern __shared__ char sm[];
    const uint32_t sbase = smem_u32(sm);
    const int t    = threadIdx.x;
    const int lane = t & 31;
    const int wid  = t >> 5;
    const int wm   = wid & 3;
    const int wn   = wid >> 2;
    const int p    = blockIdx.y;
    const int m0   = blockIdx.x * 128;

    const float* X = (p == 0) ? k_in : (p == 1) ? q_in : v_in;
    const __half* Wt = g_wt + (size_t)p * HH * EE;

    const uint32_t aoff = (uint32_t)((lane & 15) * 80 + (lane >> 4) * 16);
    const uint32_t boff = (uint32_t)((((lane & 7) | ((lane & 16) >> 1)) * 80) + (((lane >> 3) & 1) * 16));

    float acc[2][8][4];
    #pragma unroll
    for (int mb = 0; mb < 2; mb++)
        #pragma unroll
        for (int j = 0; j < 8; j++)
            #pragma unroll
            for (int i = 0; i < 4; i++) acc[mb][j][i] = 0.f;

    auto load_tile = [&](int kt, int buf) {
        char* base = sm + buf * P_BUF;
        uint32_t ubase = sbase + buf * P_BUF;
        #pragma unroll
        for (int i = 0; i < 2; i++) {       // B tile: 128 rows x 4 chunks of 16B
            int linear = i * 256 + t;
            int c4  = linear & 3;
            int row = linear >> 2;
            cp16(ubase + PB + row * 80 + c4 * 16, &Wt[(size_t)row * EE + kt * 32 + c4 * 8]);
        }
        CP_COMMIT();
        #pragma unroll
        for (int i = 0; i < 4; i++) {       // A tile: fp32 -> fp16 hi/lo
            int linear = i * 256 + t;
            int c4  = linear & 7;
            int row = linear >> 3;
            float4 f = *(const float4*)&X[(size_t)(m0 + row) * EE + kt * 32 + c4 * 4];
            __half2 h0 = __floats2half2_rn(f.x, f.y);
            __half2 h1 = __floats2half2_rn(f.z, f.w);
            uint2 uh; uh.x = *(uint32_t*)&h0; uh.y = *(uint32_t*)&h1;
            uint2 ul;
            ul.x = pack_half(f.x - __low2float(h0), f.y - __high2float(h0));
            ul.y = pack_half(f.z - __low2float(h1), f.w - __high2float(h1));
            *(uint2*)(base + PA_H + row * 80 + c4 * 8) = uh;
            *(uint2*)(base + PA_L + row * 80 + c4 * 8) = ul;
        }
    };

    load_tile(0, 0);

    for (int kt = 0; kt < 32; kt++) {
        const int cur = kt & 1;
        const uint32_t sb = sbase + cur * P_BUF;
        CP_WAIT0();
        __syncthreads();

        #pragma unroll
        for (int h = 0; h < 2; h++) {
            const uint32_t kb = h * 32;
            uint32_t ah[2][4], al[2][4];
            #pragma unroll
            for (int mb = 0; mb < 2; mb++) {
                uint32_t ra = (wm * 32 + mb * 16) * 80 + aoff + kb;
                ldsm4(ah[mb], sb + PA_H + ra);
                ldsm4(al[mb], sb + PA_L + ra);
            }
            #pragma unroll
            for (int jp = 0; jp < 4; jp++) {
                uint32_t b4[4];
                uint32_t rb = (wn * 64 + jp * 16) * 80 + boff + kb;
                ldsm4(b4, sb + PB + rb);
                #pragma unroll
                for (int mb = 0; mb < 2; mb++) {
                    mma16816h(acc[mb][2*jp],   ah[mb], b4[0], b4[1]);
                    mma16816h(acc[mb][2*jp],   al[mb], b4[0], b4[1]);
                    mma16816h(acc[mb][2*jp+1], ah[mb], b4[2], b4[3]);
                    mma16816h(acc[mb][2*jp+1], al[mb], b4[2], b4[3]);
                }
            }
        }
        if (kt < 31) load_tile(kt + 1, cur ^ 1);
    }

    const int g  = lane >> 2;
    const int q4 = lane & 3;
    if (p == 1) {
        // Q: fp16 hi/lo
        #pragma unroll
        for (int mb = 0; mb < 2; mb++) {
            #pragma unroll
            for (int j = 0; j < 8; j++) {
                int gr  = m0 + wm * 32 + mb * 16 + g;
                int col = wn * 64 + j * 8 + q4 * 2;
                float c0 = acc[mb][j][0], c1 = acc[mb][j][1];
                float c2 = acc[mb][j][2], c3 = acc[mb][j][3];
                __half2 h01 = __floats2half2_rn(c0, c1);
                __half2 h23 = __floats2half2_rn(c2, c3);
                *(uint32_t*)&g_qhi[(size_t)gr * HH + col]       = *(uint32_t*)&h01;
                *(uint32_t*)&g_qlo[(size_t)gr * HH + col]       =
                    pack_half(c0 - __low2float(h01), c1 - __high2float(h01));
                *(uint32_t*)&g_qhi[(size_t)(gr + 8) * HH + col] = *(uint32_t*)&h23;
                *(uint32_t*)&g_qlo[(size_t)(gr + 8) * HH + col] =
                    pack_half(c2 - __low2float(h23), c3 - __high2float(h23));
            }
        }
    } else {
        __half* Y = (p == 0) ? g_k : g_v;
        #pragma unroll
        for (int mb = 0; mb < 2; mb++) {
            #pragma unroll
            for (int j = 0; j < 8; j++) {
                int gr  = m0 + wm * 32 + mb * 16 + g;
                int col = wn * 64 + j * 8 + q4 * 2;
                *(uint32_t*)&Y[(size_t)gr * HH + col] =
                    pack_half(acc[mb][j][0], acc[mb][j][1]);
                *(uint32_t*)&Y[(size_t)(gr + 8) * HH + col] =
                    pack_half(acc[mb][j][2], acc[mb][j][3]);
            }
        }
    }
}

// ---------------------------------------------------------------------------
// flash_hmma: causal flash attention, all-fp16 MMA (unchanged from round 9).
// QK^T: Q hi/lo x K (2 terms). PV: P hi/lo x V (2 terms).
// 256 threads = 2 KV groups x 4 warps. BQ=64, BKV=32. K/V double-buffered.
// ---------------------------------------------------------------------------
#define FQ_H 0
#define FQ_L 17408
#define FKV  34816          // + grp*34816
#define KBUF 0              // + par*8704
#define VBUF 17408          // + par*8704
#define FLASH_SMEM 104448

__global__ __launch_bounds__(256, 2) void flash_hmma(float* __restrict__ out)
{
    extern __shared__ char sm[];
    const uint32_t sbase = smem_u32(sm);
    const int t    = threadIdx.x;
    const int lane = t & 31;
    const int wid  = t >> 5;
    const int grp  = wid >> 2;
    const int wg   = wid & 3;
    const int gt   = t & 127;

    // SM-load-balanced bid -> (batch, qb): bid and bid+148 share an SM.
    int bid = blockIdx.x;
    int b, qb;
    if (bid >= 108 && bid < 148) {
        int s = bid - 108;
        qb = 63 - (s >> 2);
        b  = s & 3;
    } else {
        int r = (bid < 108) ? bid : (363 - bid);
        qb = 53 - (r >> 2);
        b  = r & 3;
    }

    const int q0   = qb * 64;
    const size_t bT = (size_t)b * TT;

    const uint32_t aoff = (uint32_t)((lane & 15) * 272 + (lane >> 4) * 16);
    const uint32_t boff = (uint32_t)((((lane & 7) | ((lane & 16) >> 1)) * 272) + (((lane >> 3) & 1) * 16));

    // ---- load Q tile (fp16 hi/lo, all 256 threads, cp.async) ----
    {
        const __half* qh = g_qhi + (bT + q0) * HH;
        const __half* ql = g_qlo + (bT + q0) * HH;
        #pragma unroll
        for (int i = 0; i < 4; i++) {
            int linear = i * 256 + t;
            int row = linear >> 4;
            int col = linear & 15;
            uint32_t so = row * 272 + col * 16;
            cp16(sbase + FQ_H + so, &qh[(size_t)row * HH + col * 8]);
            cp16(sbase + FQ_L + so, &ql[(size_t)row * HH + col * 8]);
        }
        CP_COMMIT(); CP_WAIT0();
    }
    __syncthreads();

    float o[16][4];
    #pragma unroll
    for (int j = 0; j < 16; j++)
        #pragma unroll
        for (int i = 0; i < 4; i++) o[j][i] = 0.f;
    float m0 = -1e30f, m1 = -1e30f, l0 = 0.f, l1 = 0.f;

    const float scale_l2 = 0.088388347648318447f * 1.4426950408889634f;
    const int g   = lane >> 2;
    const int q4  = lane & 3;
    const int rg0 = q0 + wg * 16 + g;

    const uint32_t kvb = sbase + FKV + grp * 34816;
    const int nkb = 2 * qb + 2;
    const int barid = grp + 1;

    auto load_kv = [&](int kb, int par) {
        const size_t krow = bT + (size_t)kb * 32;
        uint32_t kd = kvb + KBUF + par * 8704;
        uint32_t vd = kvb + VBUF + par * 8704;
        #pragma unroll
        for (int i = 0; i < 4; i++) {
            int linear = i * 128 + gt;
            int row = linear >> 4;
            int col = linear & 15;
            uint32_t so = row * 272 + col * 16;
            size_t go = (krow + row) * HH + col * 8;
            cp16(kd + so, g_k + go);
            cp16(vd + so, g_v + go);
        }
    };

    if (grp < nkb) load_kv(grp, 0);
    CP_COMMIT();

    int par = 0;
    for (int kb = grp; kb < nkb; kb += 2, par ^= 1) {
        CP_WAIT0();
        BAR_GRP(barid);

        if (kb + 2 < nkb) load_kv(kb + 2, par ^ 1);
        CP_COMMIT();

        const uint32_t kcur = kvb + KBUF + par * 8704;
        const uint32_t vcur = kvb + VBUF + par * 8704;

        // ---- S = Q K^T (fp16, 2 terms), 32 KV cols ----
        float s[4][4];
        #pragma unroll
        for (int j = 0; j < 4; j++)
            #pragma unroll
            for (int i = 0; i < 4; i++) s[j][i] = 0.f;

        #pragma unroll
        for (int k16 = 0; k16 < 8; k16++) {
            uint32_t qa_h[4], qa_l[4];
            uint32_t qr = wg * 16 * 272 + aoff + k16 * 32;
            ldsm4(qa_h, sbase + FQ_H + qr);
            ldsm4(qa_l, sbase + FQ_L + qr);
            #pragma unroll
            for (int jp = 0; jp < 2; jp++) {
                uint32_t k4[4];
                uint32_t kr = jp * 16 * 272 + boff + k16 * 32;
                ldsm4(k4, kcur + kr);
                mma16816h(s[2*jp],   qa_h, k4[0], k4[1]);
                mma16816h(s[2*jp],   qa_l, k4[0], k4[1]);
                mma16816h(s[2*jp+1], qa_h, k4[2], k4[3]);
                mma16816h(s[2*jp+1], qa_l, k4[2], k4[3]);
            }
        }

        // ---- scale (log2 domain) + causal mask ----
        #pragma unroll
        for (int j = 0; j < 4; j++)
            #pragma unroll
            for (int i = 0; i < 4; i++) s[j][i] *= scale_l2;
        const int kv0 = kb * 32;
        if (kv0 + 31 > rg0) {
            int cbase = kv0 + q4 * 2;
            #pragma unroll
            for (int j = 0; j < 4; j++) {
                int c0 = cbase + j * 8;
                if (c0     > rg0)     s[j][0] = -1e30f;
                if (c0 + 1 > rg0)     s[j][1] = -1e30f;
                if (c0     > rg0 + 8) s[j][2] = -1e30f;
                if (c0 + 1 > rg0 + 8) s[j][3] = -1e30f;
            }
        }

        // ---- online softmax (rows g, g+8), exp2 domain ----
        float mx0 = -1e30f, mx1 = -1e30f;
        #pragma unroll
        for (int j = 0; j < 4; j++) {
            mx0 = fmaxf(mx0, fmaxf(s[j][0], s[j][1]));
            mx1 = fmaxf(mx1, fmaxf(s[j][2], s[j][3]));
        }
        mx0 = fmaxf(mx0, __shfl_xor_sync(0xffffffffu, mx0, 1));
        mx0 = fmaxf(mx0, __shfl_xor_sync(0xffffffffu, mx0, 2));
        mx1 = fmaxf(mx1, __shfl_xor_sync(0xffffffffu, mx1, 1));
        mx1 = fmaxf(mx1, __shfl_xor_sync(0xffffffffu, mx1, 2));
        float m0n = fmaxf(m0, mx0), m1n = fmaxf(m1, mx1);

        bool nochange = (m0n == m0) & (m1n == m1);
        bool skip = __all_sync(0xffffffffu, nochange);
        float a0 = 1.f, a1 = 1.f;
        if (!skip) {
            a0 = exp2f(m0 - m0n);
            a1 = exp2f(m1 - m1n);
            #pragma unroll
            for (int j = 0; j < 16; j++) {
                o[j][0] *= a0; o[j][1] *= a0;
                o[j][2] *= a1; o[j][3] *= a1;
            }
        }
        m0 = m0n; m1 = m1n;

        float esub0 = fmaxf(m0n, -1e20f);
        float esub1 = fmaxf(m1n, -1e20f);

        uint32_t ph01[4], ph23[4], pl01[4], pl23[4];
        float sum0 = 0.f, sum1 = 0.f;
        #pragma unroll
        for (int j = 0; j < 4; j++) {
            float p0 = exp2f(s[j][0] - esub0);
            float p1 = exp2f(s[j][1] - esub0);
            float p2 = exp2f(s[j][2] - esub1);
            float p3 = exp2f(s[j][3] - esub1);
            sum0 += p0 + p1; sum1 += p2 + p3;
            __half2 h01 = __floats2half2_rn(p0, p1);
            __half2 h23 = __floats2half2_rn(p2, p3);
            ph01[j] = *(uint32_t*)&h01;
            ph23[j] = *(uint32_t*)&h23;
            pl01[j] = pack_half(p0 - __low2float(h01), p1 - __high2float(h01));
            pl23[j] = pack_half(p2 - __low2float(h23), p3 - __high2float(h23));
        }
        sum0 += __shfl_xor_sync(0xffffffffu, sum0, 1);
        sum0 += __shfl_xor_sync(0xffffffffu, sum0, 2);
        sum1 += __shfl_xor_sync(0xffffffffu, sum1, 1);
        sum1 += __shfl_xor_sync(0xffffffffu, sum1, 2);
        l0 = l0 * a0 + sum0;
        l1 = l1 * a1 + sum1;

        // ---- O += P V (fp16, 2 terms) ----
        #pragma unroll
        for (int ks = 0; ks < 2; ks++) {
            uint32_t pah[4] = { ph01[2*ks], ph23[2*ks], ph01[2*ks+1], ph23[2*ks+1] };
            uint32_t pal[4] = { pl01[2*ks], pl23[2*ks], pl01[2*ks+1], pl23[2*ks+1] };
            #pragma unroll
            for (int hp = 0; hp < 8; hp++) {
                uint32_t vh4[4];
                uint32_t vr = ks * 16 * 272 + aoff + hp * 32;
                ldsm4t(vh4, vcur + vr);
                mma16816h(o[2*hp],   pah, vh4[0], vh4[1]);
                mma16816h(o[2*hp],   pal, vh4[0], vh4[1]);
                mma16816h(o[2*hp+1], pah, vh4[2], vh4[3]);
                mma16816h(o[2*hp+1], pal, vh4[2], vh4[3]);
            }
        }
    }

    // ---- merge group states (group1 -> smem -> group0) ----
    __syncthreads();
    float* mrg = (float*)(sm + FKV);
    const int slot = (wg * 32 + lane) * 69;
    if (grp == 1) {
        float* d = mrg + slot;
        #pragma unroll
        for (int j = 0; j < 16; j++) {
            d[j*4+0] = o[j][0]; d[j*4+1] = o[j][1];
            d[j*4+2] = o[j][2]; d[j*4+3] = o[j][3];
        }
        d[64] = m0; d[65] = m1; d[66] = l0; d[67] = l1;
    }
    __syncthreads();
    if (grp == 0) {
        const float* s2 = mrg + slot;
        float mB0 = s2[64], mB1 = s2[65], lB0 = s2[66], lB1 = s2[67];
        float mS0 = fmaxf(m0, mB0), mS1 = fmaxf(m1, mB1);
        float wA0 = exp2f(m0 - mS0), wB0 = exp2f(mB0 - mS0);
        float wA1 = exp2f(m1 - mS1), wB1 = exp2f(mB1 - mS1);
        float inv0 = 1.f / (l0 * wA0 + lB0 * wB0);
        float inv1 = 1.f / (l1 * wA1 + lB1 * wB1);
        #pragma unroll
        for (int j = 0; j < 16; j++) {
            int col = j * 8 + q4 * 2;
            float2 v0, v1;
            v0.x = (o[j][0] * wA0 + s2[j*4+0] * wB0) * inv0;
            v0.y = (o[j][1] * wA0 + s2[j*4+1] * wB0) * inv0;
            v1.x = (o[j][2] * wA1 + s2[j*4+2] * wB1) * inv1;
            v1.y = (o[j][3] * wA1 + s2[j*4+3] * wB1) * inv1;
            *(float2*)&out[(bT + rg0) * HH + col]     = v0;
            *(float2*)&out[(bT + rg0 + 8) * HH + col] = v1;
        }
    }
}

// ---------------------------------------------------------------------------
extern "C" void kernel_launch(void* const* d_in, const int* in_sizes, int n_in,
                              void* d_out, int out_size)
{
    const float* k  = (const float*)d_in[0];
    const float* q  = (const float*)d_in[1];
    const float* v  = (const float*)d_in[2];
    const float* Wk = (const float*)d_in[3];
    const float* Wq = (const float*)d_in[4];
    const float* Wv = (const float*)d_in[5];
    float* out = (float*)d_out;

    prep_w<<<dim3(EE / 32, 3), 256>>>(Wk, Wq, Wv);

    cudaFuncSetAttribute(proj_hmma, cudaFuncAttributeMaxDynamicSharedMemorySize, PROJ_SMEM);
    proj_hmma<<<dim3(MTOT / 128, 3), 256, PROJ_SMEM>>>(k, q, v);

    cudaFuncSetAttribute(flash_hmma, cudaFuncAttributeMaxDynamicSharedMemorySize, FLASH_SMEM);
    flash_hmma<<<256, 256, FLASH_SMEM>>>(out);
}

// round 11
// speedup vs baseline: 5.8547x; 1.1636x over previous
#include <cuda_runtime.h>
#include <cuda_fp16.h>
#include <cstdint>

#define BB 4
#define TT 4096
#define EE 1024
#define HH 128
#define MTOT (BB*TT)

// scratch (device globals = allocation-free)
__device__ __align__(16) __half g_q[(size_t)MTOT*HH];       // Q fp16
__device__ __align__(16) __half g_k[(size_t)MTOT*HH];       // K fp16
__device__ __align__(16) __half g_v[(size_t)MTOT*HH];       // V fp16
__device__ __align__(16) __half g_wt[3*(size_t)HH*EE];      // W^T fp16, [p][h][e]

// ---------------------------------------------------------------------------
// helpers
// ---------------------------------------------------------------------------
__device__ __forceinline__ uint32_t smem_u32(const void* p) {
    uint32_t a;
    asm("{ .reg .u64 t; cvta.to.shared.u64 t, %1; cvt.u32.u64 %0, t; }" : "=r"(a) : "l"(p));
    return a;
}
__device__ __forceinline__ void ldsm4(uint32_t* r, uint32_t a) {
    asm volatile("ldmatrix.sync.aligned.m8n8.x4.shared.b16 {%0,%1,%2,%3}, [%4];"
        : "=r"(r[0]), "=r"(r[1]), "=r"(r[2]), "=r"(r[3]) : "r"(a));
}
__device__ __forceinline__ void ldsm4t(uint32_t* r, uint32_t a) {
    asm volatile("ldmatrix.sync.aligned.m8n8.x4.trans.shared.b16 {%0,%1,%2,%3}, [%4];"
        : "=r"(r[0]), "=r"(r[1]), "=r"(r[2]), "=r"(r[3]) : "r"(a));
}
__device__ __forceinline__ void mma16816h(float* c, const uint32_t* a, uint32_t b0, uint32_t b1) {
    asm volatile("mma.sync.aligned.m16n8k16.row.col.f32.f16.f16.f32 "
        "{%0,%1,%2,%3}, {%4,%5,%6,%7}, {%8,%9}, {%0,%1,%2,%3};"
        : "+f"(c[0]), "+f"(c[1]), "+f"(c[2]), "+f"(c[3])
        : "r"(a[0]), "r"(a[1]), "r"(a[2]), "r"(a[3]), "r"(b0), "r"(b1));
}
__device__ __forceinline__ uint32_t pack_half(float a, float b) {
    __half2 h = __floats2half2_rn(a, b);
    return *(uint32_t*)&h;
}
__device__ __forceinline__ void cp16(uint32_t saddr, const void* gptr) {
    asm volatile("cp.async.cg.shared.global [%0], [%1], 16;"
        :: "r"(saddr), "l"(__cvta_generic_to_global(gptr)) : "memory");
}
#define CP_COMMIT() asm volatile("cp.async.commit_group;" ::: "memory")
#define CP_WAIT0()  asm volatile("cp.async.wait_group 0;" ::: "memory")
#define BAR_GRP(id) asm volatile("bar.sync %0, 128;" :: "r"(id) : "memory")

// ---------------------------------------------------------------------------
// prep_w: W [E,H] -> Wt [H,E] fp16, via smem tile transpose (coalesced)
// ---------------------------------------------------------------------------
__global__ __launch_bounds__(256) void prep_w(
    const float* __restrict__ Wk, const float* __restrict__ Wq,
    const float* __restrict__ Wv)
{
    __shared__ float tile[32][129];
    const int p = blockIdx.y;
    const float* W = (p == 0) ? Wk : (p == 1) ? Wq : Wv;
    __half* ow = g_wt + (size_t)p * HH * EE;
    const int e0 = blockIdx.x * 32;

    #pragma unroll
    for (int i = 0; i < 16; i++) {
        int linear = i * 256 + threadIdx.x;
        int row = linear >> 7;
        int col = linear & 127;
        tile[row][col] = W[(size_t)(e0 + row) * HH + col];
    }
    __syncthreads();

    #pragma unroll
    for (int i = 0; i < 4; i++) {
        int linear = i * 256 + threadIdx.x;
        int h  = linear >> 3;
        int ec = linear & 7;
        __half h4[4];
        #pragma unroll
        for (int r = 0; r < 4; r++)
            h4[r] = __float2half_rn(tile[ec * 4 + r][h]);
        *(uint2*)&ow[(size_t)h * EE + e0 + ec * 4] = *(uint2*)h4;
    }
}

// ---------------------------------------------------------------------------
// proj_hmma: Y = X[16384,1024] @ W[1024,128], 2-term fp16 HMMA
// (X split fp16 hi/lo, W single fp16), double-buffered with cp.async.
// Epilogue: Q/K/V all single fp16.
// ---------------------------------------------------------------------------
#define PA_H 0
#define PA_L 10240
#define PB   20480
#define P_BUF 30720
#define PROJ_SMEM 61440

__global__ __launch_bounds__(256, 2) void proj_hmma(
    const float* __restrict__ k_in, const float* __restrict__ q_in,
    const float* __restrict__ v_in)
{
    extern __shared__ char sm[];
    const uint32_t sbase = smem_u32(sm);
    const int t    = threadIdx.x;
    const int lane = t & 31;
    const int wid  = t >> 5;
    const int wm   = wid & 3;
    const int wn   = wid >> 2;
    const int p    = blockIdx.y;
    const int m0   = blockIdx.x * 128;

    const float* X = (p == 0) ? k_in : (p == 1) ? q_in : v_in;
    __half* Y = (p == 0) ? g_k : (p == 1) ? g_q : g_v;
    const __half* Wt = g_wt + (size_t)p * HH * EE;

    const uint32_t aoff = (uint32_t)((lane & 15) * 80 + (lane >> 4) * 16);
    const uint32_t boff = (uint32_t)((((lane & 7) | ((lane & 16) >> 1)) * 80) + (((lane >> 3) & 1) * 16));

    float acc[2][8][4];
    #pragma unroll
    for (int mb = 0; mb < 2; mb++)
        #pragma unroll
        for (int j = 0; j < 8; j++)
            #pragma unroll
            for (int i = 0; i < 4; i++) acc[mb][j][i] = 0.f;

    auto load_tile = [&](int kt, int buf) {
        char* base = sm + buf * P_BUF;
        uint32_t ubase = sbase + buf * P_BUF;
        #pragma unroll
        for (int i = 0; i < 2; i++) {       // B tile: 128 rows x 4 chunks of 16B
            int linear = i * 256 + t;
            int c4  = linear & 3;
            int row = linear >> 2;
            cp16(ubase + PB + row * 80 + c4 * 16, &Wt[(size_t)row * EE + kt * 32 + c4 * 8]);
        }
        CP_COMMIT();
        #pragma unroll
        for (int i = 0; i < 4; i++) {       // A tile: fp32 -> fp16 hi/lo
            int linear = i * 256 + t;
            int c4  = linear & 7;
            int row = linear >> 3;
            float4 f = *(const float4*)&X[(size_t)(m0 + row) * EE + kt * 32 + c4 * 4];
            __half2 h0 = __floats2half2_rn(f.x, f.y);
            __half2 h1 = __floats2half2_rn(f.z, f.w);
            uint2 uh; uh.x = *(uint32_t*)&h0; uh.y = *(uint32_t*)&h1;
            uint2 ul;
            ul.x = pack_half(f.x - __low2float(h0), f.y - __high2float(h0));
            ul.y = pack_half(f.z - __low2float(h1), f.w - __high2float(h1));
            *(uint2*)(base + PA_H + row * 80 + c4 * 8) = uh;
            *(uint2*)(base + PA_L + row * 80 + c4 * 8) = ul;
        }
    };

    load_tile(0, 0);

    for (int kt = 0; kt < 32; kt++) {
        const int cur = kt & 1;
        const uint32_t sb = sbase + cur * P_BUF;
        CP_WAIT0();
        __syncthreads();

        #pragma unroll
        for (int h = 0; h < 2; h++) {
            const uint32_t kb = h * 32;
            uint32_t ah[2][4], al[2][4];
            #pragma unroll
            for (int mb = 0; mb < 2; mb++) {
                uint32_t ra = (wm * 32 + mb * 16) * 80 + aoff + kb;
                ldsm4(ah[mb], sb + PA_H + ra);
                ldsm4(al[mb], sb + PA_L + ra);
            }
            #pragma unroll
            for (int jp = 0; jp < 4; jp++) {
                uint32_t b4[4];
                uint32_t rb = (wn * 64 + jp * 16) * 80 + boff + kb;
                ldsm4(b4, sb + PB + rb);
                #pragma unroll
                for (int mb = 0; mb < 2; mb++) {
                    mma16816h(acc[mb][2*jp],   ah[mb], b4[0], b4[1]);
                    mma16816h(acc[mb][2*jp],   al[mb], b4[0], b4[1]);
                    mma16816h(acc[mb][2*jp+1], ah[mb], b4[2], b4[3]);
                    mma16816h(acc[mb][2*jp+1], al[mb], b4[2], b4[3]);
                }
            }
        }
        if (kt < 31) load_tile(kt + 1, cur ^ 1);
    }

    const int g  = lane >> 2;
    const int q4 = lane & 3;
    #pragma unroll
    for (int mb = 0; mb < 2; mb++) {
        #pragma unroll
        for (int j = 0; j < 8; j++) {
            int gr  = m0 + wm * 32 + mb * 16 + g;
            int col = wn * 64 + j * 8 + q4 * 2;
            *(uint32_t*)&Y[(size_t)gr * HH + col] =
                pack_half(acc[mb][j][0], acc[mb][j][1]);
            *(uint32_t*)&Y[(size_t)(gr + 8) * HH + col] =
                pack_half(acc[mb][j][2], acc[mb][j][3]);
        }
    }
}

// ---------------------------------------------------------------------------
// flash_hmma: causal flash attention, single-fp16 MMA operands throughout.
// QK^T: Q x K (1 term). PV: P x V (1 term).
// 256 threads = 2 KV groups x 4 warps. BQ=64, BKV=32. K/V double-buffered.
// ---------------------------------------------------------------------------
#define FQ   0
#define FKV  17408          // + grp*34816
#define KBUF 0              // + par*8704
#define VBUF 17408          // + par*8704
#define FLASH_SMEM 87040

__global__ __launch_bounds__(256, 2) void flash_hmma(float* __restrict__ out)
{
    extern __shared__ char sm[];
    const uint32_t sbase = smem_u32(sm);
    const int t    = threadIdx.x;
    const int lane = t & 31;
    const int wid  = t >> 5;
    const int grp  = wid >> 2;
    const int wg   = wid & 3;
    const int gt   = t & 127;

    // SM-load-balanced bid -> (batch, qb): bid and bid+148 share an SM.
    int bid = blockIdx.x;
    int b, qb;
    if (bid >= 108 && bid < 148) {
        int s = bid - 108;
        qb = 63 - (s >> 2);
        b  = s & 3;
    } else {
        int r = (bid < 108) ? bid : (363 - bid);
        qb = 53 - (r >> 2);
        b  = r & 3;
    }

    const int q0   = qb * 64;
    const size_t bT = (size_t)b * TT;

    const uint32_t aoff = (uint32_t)((lane & 15) * 272 + (lane >> 4) * 16);
    const uint32_t boff = (uint32_t)((((lane & 7) | ((lane & 16) >> 1)) * 272) + (((lane >> 3) & 1) * 16));

    // ---- load Q tile (fp16, all 256 threads, cp.async) ----
    {
        const __half* qg = g_q + (bT + q0) * HH;
        #pragma unroll
        for (int i = 0; i < 4; i++) {
            int linear = i * 256 + t;
            int row = linear >> 4;
            int col = linear & 15;
            if (i < 4) { // 1024 chunks total; 4*256 = 1024
                cp16(sbase + FQ + row * 272 + col * 16, &qg[(size_t)row * HH + col * 8]);
            }
        }
        CP_COMMIT(); CP_WAIT0();
    }
    __syncthreads();

    float o[16][4];
    #pragma unroll
    for (int j = 0; j < 16; j++)
        #pragma unroll
        for (int i = 0; i < 4; i++) o[j][i] = 0.f;
    float m0 = -1e30f, m1 = -1e30f, l0 = 0.f, l1 = 0.f;

    const float scale_l2 = 0.088388347648318447f * 1.4426950408889634f;
    const int g   = lane >> 2;
    const int q4  = lane & 3;
    const int rg0 = q0 + wg * 16 + g;

    const uint32_t kvb = sbase + FKV + grp * 34816;
    const int nkb = 2 * qb + 2;
    const int barid = grp + 1;

    auto load_kv = [&](int kb, int par) {
        const size_t krow = bT + (size_t)kb * 32;
        uint32_t kd = kvb + KBUF + par * 8704;
        uint32_t vd = kvb + VBUF + par * 8704;
        #pragma unroll
        for (int i = 0; i < 4; i++) {
            int linear = i * 128 + gt;
            int row = linear >> 4;
            int col = linear & 15;
            uint32_t so = row * 272 + col * 16;
            size_t go = (krow + row) * HH + col * 8;
            cp16(kd + so, g_k + go);
            cp16(vd + so, g_v + go);
        }
    };

    if (grp < nkb) load_kv(grp, 0);
    CP_COMMIT();

    int par = 0;
    for (int kb = grp; kb < nkb; kb += 2, par ^= 1) {
        CP_WAIT0();
        BAR_GRP(barid);

        if (kb + 2 < nkb) load_kv(kb + 2, par ^ 1);
        CP_COMMIT();

        const uint32_t kcur = kvb + KBUF + par * 8704;
        const uint32_t vcur = kvb + VBUF + par * 8704;

        // ---- S = Q K^T (fp16), 32 KV cols ----
        float s[4][4];
        #pragma unroll
        for (int j = 0; j < 4; j++)
            #pragma unroll
            for (int i = 0; i < 4; i++) s[j][i] = 0.f;

        #pragma unroll
        for (int k16 = 0; k16 < 8; k16++) {
            uint32_t qa[4];
            uint32_t qr = wg * 16 * 272 + aoff + k16 * 32;
            ldsm4(qa, sbase + FQ + qr);
            #pragma unroll
            for (int jp = 0; jp < 2; jp++) {
                uint32_t k4[4];
                uint32_t kr = jp * 16 * 272 + boff + k16 * 32;
                ldsm4(k4, kcur + kr);
                mma16816h(s[2*jp],   qa, k4[0], k4[1]);
                mma16816h(s[2*jp+1], qa, k4[2], k4[3]);
            }
        }

        // ---- scale (log2 domain) + causal mask ----
        #pragma unroll
        for (int j = 0; j < 4; j++)
            #pragma unroll
            for (int i = 0; i < 4; i++) s[j][i] *= scale_l2;
        const int kv0 = kb * 32;
        if (kv0 + 31 > rg0) {
            int cbase = kv0 + q4 * 2;
            #pragma unroll
            for (int j = 0; j < 4; j++) {
                int c0 = cbase + j * 8;
                if (c0     > rg0)     s[j][0] = -1e30f;
                if (c0 + 1 > rg0)     s[j][1] = -1e30f;
                if (c0     > rg0 + 8) s[j][2] = -1e30f;
                if (c0 + 1 > rg0 + 8) s[j][3] = -1e30f;
            }
        }

        // ---- online softmax (rows g, g+8), exp2 domain ----
        float mx0 = -1e30f, mx1 = -1e30f;
        #pragma unroll
        for (int j = 0; j < 4; j++) {
            mx0 = fmaxf(mx0, fmaxf(s[j][0], s[j][1]));
            mx1 = fmaxf(mx1, fmaxf(s[j][2], s[j][3]));
        }
        mx0 = fmaxf(mx0, __shfl_xor_sync(0xffffffffu, mx0, 1));
        mx0 = fmaxf(mx0, __shfl_xor_sync(0xffffffffu, mx0, 2));
        mx1 = fmaxf(mx1, __shfl_xor_sync(0xffffffffu, mx1, 1));
        mx1 = fmaxf(mx1, __shfl_xor_sync(0xffffffffu, mx1, 2));
        float m0n = fmaxf(m0, mx0), m1n = fmaxf(m1, mx1);

        bool nochange = (m0n == m0) & (m1n == m1);
        bool skip = __all_sync(0xffffffffu, nochange);
        float a0 = 1.f, a1 = 1.f;
        if (!skip) {
            a0 = exp2f(m0 - m0n);
            a1 = exp2f(m1 - m1n);
            #pragma unroll
            for (int j = 0; j < 16; j++) {
                o[j][0] *= a0; o[j][1] *= a0;
                o[j][2] *= a1; o[j][3] *= a1;
            }
        }
        m0 = m0n; m1 = m1n;

        float esub0 = fmaxf(m0n, -1e20f);
        float esub1 = fmaxf(m1n, -1e20f);

        // P -> single fp16
        uint32_t ph01[4], ph23[4];
        float sum0 = 0.f, sum1 = 0.f;
        #pragma unroll
        for (int j = 0; j < 4; j++) {
            float p0 = exp2f(s[j][0] - esub0);
            float p1 = exp2f(s[j][1] - esub0);
            float p2 = exp2f(s[j][2] - esub1);
            float p3 = exp2f(s[j][3] - esub1);
            sum0 += p0 + p1; sum1 += p2 + p3;
            ph01[j] = pack_half(p0, p1);
            ph23[j] = pack_half(p2, p3);
        }
        sum0 += __shfl_xor_sync(0xffffffffu, sum0, 1);
        sum0 += __shfl_xor_sync(0xffffffffu, sum0, 2);
        sum1 += __shfl_xor_sync(0xffffffffu, sum1, 1);
        sum1 += __shfl_xor_sync(0xffffffffu, sum1, 2);
        l0 = l0 * a0 + sum0;
        l1 = l1 * a1 + sum1;

        // ---- O += P V (fp16) ----
        #pragma unroll
        for (int ks = 0; ks < 2; ks++) {
            uint32_t pa[4] = { ph01[2*ks], ph23[2*ks], ph01[2*ks+1], ph23[2*ks+1] };
            #pragma unroll
            for (int hp = 0; hp < 8; hp++) {
                uint32_t vh4[4];
                uint32_t vr = ks * 16 * 272 + aoff + hp * 32;
                ldsm4t(vh4, vcur + vr);
                mma16816h(o[2*hp],   pa, vh4[0], vh4[1]);
                mma16816h(o[2*hp+1], pa, vh4[2], vh4[3]);
            }
        }
    }

    // ---- merge group states (group1 -> smem -> group0) ----
    __syncthreads();
    float* mrg = (float*)(sm + FKV);
    const int slot = (wg * 32 + lane) * 69;
    if (grp == 1) {
        float* d = mrg + slot;
        #pragma unroll
        for (int j = 0; j < 16; j++) {
            d[j*4+0] = o[j][0]; d[j*4+1] = o[j][1];
            d[j*4+2] = o[j][2]; d[j*4+3] = o[j][3];
        }
        d[64] = m0; d[65] = m1; d[66] = l0; d[67] = l1;
    }
    __syncthreads();
    if (grp == 0) {
        const float* s2 = mrg + slot;
        float mB0 = s2[64], mB1 = s2[65], lB0 = s2[66], lB1 = s2[67];
        float mS0 = fmaxf(m0, mB0), mS1 = fmaxf(m1, mB1);
        float wA0 = exp2f(m0 - mS0), wB0 = exp2f(mB0 - mS0);
        float wA1 = exp2f(m1 - mS1), wB1 = exp2f(mB1 - mS1);
        float inv0 = 1.f / (l0 * wA0 + lB0 * wB0);
        float inv1 = 1.f / (l1 * wA1 + lB1 * wB1);
        #pragma unroll
        for (int j = 0; j < 16; j++) {
            int col = j * 8 + q4 * 2;
            float2 v0, v1;
            v0.x = (o[j][0] * wA0 + s2[j*4+0] * wB0) * inv0;
            v0.y = (o[j][1] * wA0 + s2[j*4+1] * wB0) * inv0;
            v1.x = (o[j][2] * wA1 + s2[j*4+2] * wB1) * inv1;
            v1.y = (o[j][3] * wA1 + s2[j*4+3] * wB1) * inv1;
            *(float2*)&out[(bT + rg0) * HH + col]     = v0;
            *(float2*)&out[(bT + rg0 + 8) * HH + col] = v1;
        }
    }
}

// ---------------------------------------------------------------------------
extern "C" void kernel_launch(void* const* d_in, const int* in_sizes, int n_in,
                              void* d_out, int out_size)
{
    const float* k  = (const float*)d_in[0];
    const float* q  = (const float*)d_in[1];
    const float* v  = (const float*)d_in[2];
    const float* Wk = (const float*)d_in[3];
    const float* Wq = (const float*)d_in[4];
    const float* Wv = (const float*)d_in[5];
    float* out = (float*)d_out;

    prep_w<<<dim3(EE / 32, 3), 256>>>(Wk, Wq, Wv);

    cudaFuncSetAttribute(proj_hmma, cudaFuncAttributeMaxDynamicSharedMemorySize, PROJ_SMEM);
    proj_hmma<<<dim3(MTOT / 128, 3), 256, PROJ_SMEM>>>(k, q, v);

    cudaFuncSetAttribute(flash_hmma, cudaFuncAttributeMaxDynamicSharedMemorySize, FLASH_SMEM);
    flash_hmma<<<256, 256, FLASH_SMEM>>>(out);
}

// round 12
// speedup vs baseline: 6.4259x; 1.0976x over previous
#include <cuda_runtime.h>
#include <cuda_fp16.h>
#include <cstdint>

#define BB 4
#define TT 4096
#define EE 1024
#define HH 128
#define MTOT (BB*TT)

// scratch (device globals = allocation-free)
__device__ __align__(16) __half g_q[(size_t)MTOT*HH];       // Q fp16
__device__ __align__(16) __half g_k[(size_t)MTOT*HH];       // K fp16
__device__ __align__(16) __half g_v[(size_t)MTOT*HH];       // V fp16
__device__ __align__(16) __half g_wt[3*(size_t)HH*EE];      // W^T fp16, [p][h][e]

// ---------------------------------------------------------------------------
// helpers
// ---------------------------------------------------------------------------
__device__ __forceinline__ uint32_t smem_u32(const void* p) {
    uint32_t a;
    asm("{ .reg .u64 t; cvta.to.shared.u64 t, %1; cvt.u32.u64 %0, t; }" : "=r"(a) : "l"(p));
    return a;
}
__device__ __forceinline__ void ldsm4(uint32_t* r, uint32_t a) {
    asm volatile("ldmatrix.sync.aligned.m8n8.x4.shared.b16 {%0,%1,%2,%3}, [%4];"
        : "=r"(r[0]), "=r"(r[1]), "=r"(r[2]), "=r"(r[3]) : "r"(a));
}
__device__ __forceinline__ void ldsm4t(uint32_t* r, uint32_t a) {
    asm volatile("ldmatrix.sync.aligned.m8n8.x4.trans.shared.b16 {%0,%1,%2,%3}, [%4];"
        : "=r"(r[0]), "=r"(r[1]), "=r"(r[2]), "=r"(r[3]) : "r"(a));
}
__device__ __forceinline__ void mma16816h(float* c, const uint32_t* a, uint32_t b0, uint32_t b1) {
    asm volatile("mma.sync.aligned.m16n8k16.row.col.f32.f16.f16.f32 "
        "{%0,%1,%2,%3}, {%4,%5,%6,%7}, {%8,%9}, {%0,%1,%2,%3};"
        : "+f"(c[0]), "+f"(c[1]), "+f"(c[2]), "+f"(c[3])
        : "r"(a[0]), "r"(a[1]), "r"(a[2]), "r"(a[3]), "r"(b0), "r"(b1));
}
__device__ __forceinline__ uint32_t pack_half(float a, float b) {
    __half2 h = __floats2half2_rn(a, b);
    return *(uint32_t*)&h;
}
__device__ __forceinline__ void cp16(uint32_t saddr, const void* gptr) {
    asm volatile("cp.async.cg.shared.global [%0], [%1], 16;"
        :: "r"(saddr), "l"(__cvta_generic_to_global(gptr)) : "memory");
}
#define CP_COMMIT() asm volatile("cp.async.commit_group;" ::: "memory")
#define CP_WAIT0()  asm volatile("cp.async.wait_group 0;" ::: "memory")
#define BAR_GRP(id) asm volatile("bar.sync %0, 128;" :: "r"(id) : "memory")

// ---------------------------------------------------------------------------
// prep_w: W [E,H] -> Wt [H,E] fp16, via smem tile transpose (coalesced)
// ---------------------------------------------------------------------------
__global__ __launch_bounds__(256) void prep_w(
    const float* __restrict__ Wk, const float* __restrict__ Wq,
    const float* __restrict__ Wv)
{
    __shared__ float tile[32][129];
    const int p = blockIdx.y;
    const float* W = (p == 0) ? Wk : (p == 1) ? Wq : Wv;
    __half* ow = g_wt + (size_t)p * HH * EE;
    const int e0 = blockIdx.x * 32;

    #pragma unroll
    for (int i = 0; i < 16; i++) {
        int linear = i * 256 + threadIdx.x;
        int row = linear >> 7;
        int col = linear & 127;
        tile[row][col] = W[(size_t)(e0 + row) * HH + col];
    }
    __syncthreads();

    #pragma unroll
    for (int i = 0; i < 4; i++) {
        int linear = i * 256 + threadIdx.x;
        int h  = linear >> 3;
        int ec = linear & 7;
        __half h4[4];
        #pragma unroll
        for (int r = 0; r < 4; r++)
            h4[r] = __float2half_rn(tile[ec * 4 + r][h]);
        *(uint2*)&ow[(size_t)h * EE + e0 + ec * 4] = *(uint2*)h4;
    }
}

// ---------------------------------------------------------------------------
// proj_hmma: Y = X[16384,1024] @ W[1024,128], single-term fp16 HMMA
// (X fp16, W fp16), double-buffered with cp.async. Q/K/V out: fp16.
// ---------------------------------------------------------------------------
#define PA   0
#define PB   10240
#define P_BUF 20480
#define PROJ_SMEM 40960

__global__ __launch_bounds__(256, 2) void proj_hmma(
    const float* __restrict__ k_in, const float* __restrict__ q_in,
    const float* __restrict__ v_in)
{
    extern __shared__ char sm[];
    const uint32_t sbase = smem_u32(sm);
    const int t    = threadIdx.x;
    const int lane = t & 31;
    const int wid  = t >> 5;
    const int wm   = wid & 3;
    const int wn   = wid >> 2;
    const int p    = blockIdx.y;
    const int m0   = blockIdx.x * 128;

    const float* X = (p == 0) ? k_in : (p == 1) ? q_in : v_in;
    __half* Y = (p == 0) ? g_k : (p == 1) ? g_q : g_v;
    const __half* Wt = g_wt + (size_t)p * HH * EE;

    const uint32_t aoff = (uint32_t)((lane & 15) * 80 + (lane >> 4) * 16);
    const uint32_t boff = (uint32_t)((((lane & 7) | ((lane & 16) >> 1)) * 80) + (((lane >> 3) & 1) * 16));

    float acc[2][8][4];
    #pragma unroll
    for (int mb = 0; mb < 2; mb++)
        #pragma unroll
        for (int j = 0; j < 8; j++)
            #pragma unroll
            for (int i = 0; i < 4; i++) acc[mb][j][i] = 0.f;

    auto load_tile = [&](int kt, int buf) {
        char* base = sm + buf * P_BUF;
        uint32_t ubase = sbase + buf * P_BUF;
        #pragma unroll
        for (int i = 0; i < 2; i++) {       // B tile: 128 rows x 4 chunks of 16B
            int linear = i * 256 + t;
            int c4  = linear & 3;
            int row = linear >> 2;
            cp16(ubase + PB + row * 80 + c4 * 16, &Wt[(size_t)row * EE + kt * 32 + c4 * 8]);
        }
        CP_COMMIT();
        #pragma unroll
        for (int i = 0; i < 4; i++) {       // A tile: fp32 -> fp16
            int linear = i * 256 + t;
            int c4  = linear & 7;
            int row = linear >> 3;
            float4 f = *(const float4*)&X[(size_t)(m0 + row) * EE + kt * 32 + c4 * 4];
            uint2 uh;
            uh.x = pack_half(f.x, f.y);
            uh.y = pack_half(f.z, f.w);
            *(uint2*)(base + PA + row * 80 + c4 * 8) = uh;
        }
    };

    load_tile(0, 0);

    for (int kt = 0; kt < 32; kt++) {
        const int cur = kt & 1;
        const uint32_t sb = sbase + cur * P_BUF;
        CP_WAIT0();
        __syncthreads();

        #pragma unroll
        for (int h = 0; h < 2; h++) {
            const uint32_t kb = h * 32;
            uint32_t ah[2][4];
            #pragma unroll
            for (int mb = 0; mb < 2; mb++) {
                uint32_t ra = (wm * 32 + mb * 16) * 80 + aoff + kb;
                ldsm4(ah[mb], sb + PA + ra);
            }
            #pragma unroll
            for (int jp = 0; jp < 4; jp++) {
                uint32_t b4[4];
                uint32_t rb = (wn * 64 + jp * 16) * 80 + boff + kb;
                ldsm4(b4, sb + PB + rb);
                #pragma unroll
                for (int mb = 0; mb < 2; mb++) {
                    mma16816h(acc[mb][2*jp],   ah[mb], b4[0], b4[1]);
                    mma16816h(acc[mb][2*jp+1], ah[mb], b4[2], b4[3]);
                }
            }
        }
        if (kt < 31) load_tile(kt + 1, cur ^ 1);
    }

    const int g  = lane >> 2;
    const int q4 = lane & 3;
    #pragma unroll
    for (int mb = 0; mb < 2; mb++) {
        #pragma unroll
        for (int j = 0; j < 8; j++) {
            int gr  = m0 + wm * 32 + mb * 16 + g;
            int col = wn * 64 + j * 8 + q4 * 2;
            *(uint32_t*)&Y[(size_t)gr * HH + col] =
                pack_half(acc[mb][j][0], acc[mb][j][1]);
            *(uint32_t*)&Y[(size_t)(gr + 8) * HH + col] =
                pack_half(acc[mb][j][2], acc[mb][j][3]);
        }
    }
}

// ---------------------------------------------------------------------------
// flash_hmma: causal flash attention, single-fp16 MMA operands throughout.
// (unchanged from round 11)
// ---------------------------------------------------------------------------
#define FQ   0
#define FKV  17408          // + grp*34816
#define KBUF 0              // + par*8704
#define VBUF 17408          // + par*8704
#define FLASH_SMEM 87040

__global__ __launch_bounds__(256, 2) void flash_hmma(float* __restrict__ out)
{
    extern __shared__ char sm[];
    const uint32_t sbase = smem_u32(sm);
    const int t    = threadIdx.x;
    const int lane = t & 31;
    const int wid  = t >> 5;
    const int grp  = wid >> 2;
    const int wg   = wid & 3;
    const int gt   = t & 127;

    // SM-load-balanced bid -> (batch, qb): bid and bid+148 share an SM.
    int bid = blockIdx.x;
    int b, qb;
    if (bid >= 108 && bid < 148) {
        int s = bid - 108;
        qb = 63 - (s >> 2);
        b  = s & 3;
    } else {
        int r = (bid < 108) ? bid : (363 - bid);
        qb = 53 - (r >> 2);
        b  = r & 3;
    }

    const int q0   = qb * 64;
    const size_t bT = (size_t)b * TT;

    const uint32_t aoff = (uint32_t)((lane & 15) * 272 + (lane >> 4) * 16);
    const uint32_t boff = (uint32_t)((((lane & 7) | ((lane & 16) >> 1)) * 272) + (((lane >> 3) & 1) * 16));

    // ---- load Q tile (fp16, all 256 threads, cp.async) ----
    {
        const __half* qg = g_q + (bT + q0) * HH;
        #pragma unroll
        for (int i = 0; i < 4; i++) {
            int linear = i * 256 + t;
            int row = linear >> 4;
            int col = linear & 15;
            cp16(sbase + FQ + row * 272 + col * 16, &qg[(size_t)row * HH + col * 8]);
        }
        CP_COMMIT(); CP_WAIT0();
    }
    __syncthreads();

    float o[16][4];
    #pragma unroll
    for (int j = 0; j < 16; j++)
        #pragma unroll
        for (int i = 0; i < 4; i++) o[j][i] = 0.f;
    float m0 = -1e30f, m1 = -1e30f, l0 = 0.f, l1 = 0.f;

    const float scale_l2 = 0.088388347648318447f * 1.4426950408889634f;
    const int g   = lane >> 2;
    const int q4  = lane & 3;
    const int rg0 = q0 + wg * 16 + g;

    const uint32_t kvb = sbase + FKV + grp * 34816;
    const int nkb = 2 * qb + 2;
    const int barid = grp + 1;

    auto load_kv = [&](int kb, int par) {
        const size_t krow = bT + (size_t)kb * 32;
        uint32_t kd = kvb + KBUF + par * 8704;
        uint32_t vd = kvb + VBUF + par * 8704;
        #pragma unroll
        for (int i = 0; i < 4; i++) {
            int linear = i * 128 + gt;
            int row = linear >> 4;
            int col = linear & 15;
            uint32_t so = row * 272 + col * 16;
            size_t go = (krow + row) * HH + col * 8;
            cp16(kd + so, g_k + go);
            cp16(vd + so, g_v + go);
        }
    };

    if (grp < nkb) load_kv(grp, 0);
    CP_COMMIT();

    int par = 0;
    for (int kb = grp; kb < nkb; kb += 2, par ^= 1) {
        CP_WAIT0();
        BAR_GRP(barid);

        if (kb + 2 < nkb) load_kv(kb + 2, par ^ 1);
        CP_COMMIT();

        const uint32_t kcur = kvb + KBUF + par * 8704;
        const uint32_t vcur = kvb + VBUF + par * 8704;

        // ---- S = Q K^T (fp16), 32 KV cols ----
        float s[4][4];
        #pragma unroll
        for (int j = 0; j < 4; j++)
            #pragma unroll
            for (int i = 0; i < 4; i++) s[j][i] = 0.f;

        #pragma unroll
        for (int k16 = 0; k16 < 8; k16++) {
            uint32_t qa[4];
            uint32_t qr = wg * 16 * 272 + aoff + k16 * 32;
            ldsm4(qa, sbase + FQ + qr);
            #pragma unroll
            for (int jp = 0; jp < 2; jp++) {
                uint32_t k4[4];
                uint32_t kr = jp * 16 * 272 + boff + k16 * 32;
                ldsm4(k4, kcur + kr);
                mma16816h(s[2*jp],   qa, k4[0], k4[1]);
                mma16816h(s[2*jp+1], qa, k4[2], k4[3]);
            }
        }

        // ---- scale (log2 domain) + causal mask ----
        #pragma unroll
        for (int j = 0; j < 4; j++)
            #pragma unroll
            for (int i = 0; i < 4; i++) s[j][i] *= scale_l2;
        const int kv0 = kb * 32;
        if (kv0 + 31 > rg0) {
            int cbase = kv0 + q4 * 2;
            #pragma unroll
            for (int j = 0; j < 4; j++) {
                int c0 = cbase + j * 8;
                if (c0     > rg0)     s[j][0] = -1e30f;
                if (c0 + 1 > rg0)     s[j][1] = -1e30f;
                if (c0     > rg0 + 8) s[j][2] = -1e30f;
                if (c0 + 1 > rg0 + 8) s[j][3] = -1e30f;
            }
        }

        // ---- online softmax (rows g, g+8), exp2 domain ----
        float mx0 = -1e30f, mx1 = -1e30f;
        #pragma unroll
        for (int j = 0; j < 4; j++) {
            mx0 = fmaxf(mx0, fmaxf(s[j][0], s[j][1]));
            mx1 = fmaxf(mx1, fmaxf(s[j][2], s[j][3]));
        }
        mx0 = fmaxf(mx0, __shfl_xor_sync(0xffffffffu, mx0, 1));
        mx0 = fmaxf(mx0, __shfl_xor_sync(0xffffffffu, mx0, 2));
        mx1 = fmaxf(mx1, __shfl_xor_sync(0xffffffffu, mx1, 1));
        mx1 = fmaxf(mx1, __shfl_xor_sync(0xffffffffu, mx1, 2));
        float m0n = fmaxf(m0, mx0), m1n = fmaxf(m1, mx1);

        bool nochange = (m0n == m0) & (m1n == m1);
        bool skip = __all_sync(0xffffffffu, nochange);
        float a0 = 1.f, a1 = 1.f;
        if (!skip) {
            a0 = exp2f(m0 - m0n);
            a1 = exp2f(m1 - m1n);
            #pragma unroll
            for (int j = 0; j < 16; j++) {
                o[j][0] *= a0; o[j][1] *= a0;
                o[j][2] *= a1; o[j][3] *= a1;
            }
        }
        m0 = m0n; m1 = m1n;

        float esub0 = fmaxf(m0n, -1e20f);
        float esub1 = fmaxf(m1n, -1e20f);

        // P -> single fp16
        uint32_t ph01[4], ph23[4];
        float sum0 = 0.f, sum1 = 0.f;
        #pragma unroll
        for (int j = 0; j < 4; j++) {
            float p0 = exp2f(s[j][0] - esub0);
            float p1 = exp2f(s[j][1] - esub0);
            float p2 = exp2f(s[j][2] - esub1);
            float p3 = exp2f(s[j][3] - esub1);
            sum0 += p0 + p1; sum1 += p2 + p3;
            ph01[j] = pack_half(p0, p1);
            ph23[j] = pack_half(p2, p3);
        }
        sum0 += __shfl_xor_sync(0xffffffffu, sum0, 1);
        sum0 += __shfl_xor_sync(0xffffffffu, sum0, 2);
        sum1 += __shfl_xor_sync(0xffffffffu, sum1, 1);
        sum1 += __shfl_xor_sync(0xffffffffu, sum1, 2);
        l0 = l0 * a0 + sum0;
        l1 = l1 * a1 + sum1;

        // ---- O += P V (fp16) ----
        #pragma unroll
        for (int ks = 0; ks < 2; ks++) {
            uint32_t pa[4] = { ph01[2*ks], ph23[2*ks], ph01[2*ks+1], ph23[2*ks+1] };
            #pragma unroll
            for (int hp = 0; hp < 8; hp++) {
                uint32_t vh4[4];
                uint32_t vr = ks * 16 * 272 + aoff + hp * 32;
                ldsm4t(vh4, vcur + vr);
                mma16816h(o[2*hp],   pa, vh4[0], vh4[1]);
                mma16816h(o[2*hp+1], pa, vh4[2], vh4[3]);
            }
        }
    }

    // ---- merge group states (group1 -> smem -> group0) ----
    __syncthreads();
    float* mrg = (float*)(sm + FKV);
    const int slot = (wg * 32 + lane) * 69;
    if (grp == 1) {
        float* d = mrg + slot;
        #pragma unroll
        for (int j = 0; j < 16; j++) {
            d[j*4+0] = o[j][0]; d[j*4+1] = o[j][1];
            d[j*4+2] = o[j][2]; d[j*4+3] = o[j][3];
        }
        d[64] = m0; d[65] = m1; d[66] = l0; d[67] = l1;
    }
    __syncthreads();
    if (grp == 0) {
        const float* s2 = mrg + slot;
        float mB0 = s2[64], mB1 = s2[65], lB0 = s2[66], lB1 = s2[67];
        float mS0 = fmaxf(m0, mB0), mS1 = fmaxf(m1, mB1);
        float wA0 = exp2f(m0 - mS0), wB0 = exp2f(mB0 - mS0);
        float wA1 = exp2f(m1 - mS1), wB1 = exp2f(mB1 - mS1);
        float inv0 = 1.f / (l0 * wA0 + lB0 * wB0);
        float inv1 = 1.f / (l1 * wA1 + lB1 * wB1);
        #pragma unroll
        for (int j = 0; j < 16; j++) {
            int col = j * 8 + q4 * 2;
            float2 v0, v1;
            v0.x = (o[j][0] * wA0 + s2[j*4+0] * wB0) * inv0;
            v0.y = (o[j][1] * wA0 + s2[j*4+1] * wB0) * inv0;
            v1.x = (o[j][2] * wA1 + s2[j*4+2] * wB1) * inv1;
            v1.y = (o[j][3] * wA1 + s2[j*4+3] * wB1) * inv1;
            *(float2*)&out[(bT + rg0) * HH + col]     = v0;
            *(float2*)&out[(bT + rg0 + 8) * HH + col] = v1;
        }
    }
}

// ---------------------------------------------------------------------------
extern "C" void kernel_launch(void* const* d_in, const int* in_sizes, int n_in,
                              void* d_out, int out_size)
{
    const float* k  = (const float*)d_in[0];
    const float* q  = (const float*)d_in[1];
    const float* v  = (const float*)d_in[2];
    const float* Wk = (const float*)d_in[3];
    const float* Wq = (const float*)d_in[4];
    const float* Wv = (const float*)d_in[5];
    float* out = (float*)d_out;

    prep_w<<<dim3(EE / 32, 3), 256>>>(Wk, Wq, Wv);

    cudaFuncSetAttribute(proj_hmma, cudaFuncAttributeMaxDynamicSharedMemorySize, PROJ_SMEM);
    proj_hmma<<<dim3(MTOT / 128, 3), 256, PROJ_SMEM>>>(k, q, v);

    cudaFuncSetAttribute(flash_hmma, cudaFuncAttributeMaxDynamicSharedMemorySize, FLASH_SMEM);
    flash_hmma<<<256, 256, FLASH_SMEM>>>(out);
}

// round 13
// speedup vs baseline: 7.1435x; 1.1117x over previous
#include <cuda_runtime.h>
#include <cuda_fp16.h>
#include <cstdint>

#define BB 4
#define TT 4096
#define EE 1024
#define HH 128
#define MTOT (BB*TT)

// scratch (device globals = allocation-free)
__device__ __align__(16) __half g_q[(size_t)MTOT*HH];       // Q fp16
__device__ __align__(16) __half g_k[(size_t)MTOT*HH];       // K fp16
__device__ __align__(16) __half g_v[(size_t)MTOT*HH];       // V fp16
__device__ __align__(16) __half g_wt[3*(size_t)HH*EE];      // W^T fp16, [p][h][e]

// ---------------------------------------------------------------------------
// helpers
// ---------------------------------------------------------------------------
__device__ __forceinline__ uint32_t smem_u32(const void* p) {
    uint32_t a;
    asm("{ .reg .u64 t; cvta.to.shared.u64 t, %1; cvt.u32.u64 %0, t; }" : "=r"(a) : "l"(p));
    return a;
}
__device__ __forceinline__ void ldsm4(uint32_t* r, uint32_t a) {
    asm volatile("ldmatrix.sync.aligned.m8n8.x4.shared.b16 {%0,%1,%2,%3}, [%4];"
        : "=r"(r[0]), "=r"(r[1]), "=r"(r[2]), "=r"(r[3]) : "r"(a));
}
__device__ __forceinline__ void ldsm4t(uint32_t* r, uint32_t a) {
    asm volatile("ldmatrix.sync.aligned.m8n8.x4.trans.shared.b16 {%0,%1,%2,%3}, [%4];"
        : "=r"(r[0]), "=r"(r[1]), "=r"(r[2]), "=r"(r[3]) : "r"(a));
}
__device__ __forceinline__ void mma16816h(float* c, const uint32_t* a, uint32_t b0, uint32_t b1) {
    asm volatile("mma.sync.aligned.m16n8k16.row.col.f32.f16.f16.f32 "
        "{%0,%1,%2,%3}, {%4,%5,%6,%7}, {%8,%9}, {%0,%1,%2,%3};"
        : "+f"(c[0]), "+f"(c[1]), "+f"(c[2]), "+f"(c[3])
        : "r"(a[0]), "r"(a[1]), "r"(a[2]), "r"(a[3]), "r"(b0), "r"(b1));
}
__device__ __forceinline__ uint32_t pack_half(float a, float b) {
    __half2 h = __floats2half2_rn(a, b);
    return *(uint32_t*)&h;
}
__device__ __forceinline__ float ex2(float x) {
    float r;
    asm("ex2.approx.ftz.f32 %0, %1;" : "=f"(r) : "f"(x));
    return r;
}
__device__ __forceinline__ void cp16(uint32_t saddr, const void* gptr) {
    asm volatile("cp.async.cg.shared.global [%0], [%1], 16;"
        :: "r"(saddr), "l"(__cvta_generic_to_global(gptr)) : "memory");
}
#define CP_COMMIT() asm volatile("cp.async.commit_group;" ::: "memory")
#define CP_WAIT0()  asm volatile("cp.async.wait_group 0;" ::: "memory")
#define BAR_GRP(id) asm volatile("bar.sync %0, 128;" :: "r"(id) : "memory")

// ---------------------------------------------------------------------------
// prep_w: W [E,H] -> Wt [H,E] fp16, via smem tile transpose (coalesced)
// ---------------------------------------------------------------------------
__global__ __launch_bounds__(256) void prep_w(
    const float* __restrict__ Wk, const float* __restrict__ Wq,
    const float* __restrict__ Wv)
{
    __shared__ float tile[32][129];
    const int p = blockIdx.y;
    const float* W = (p == 0) ? Wk : (p == 1) ? Wq : Wv;
    __half* ow = g_wt + (size_t)p * HH * EE;
    const int e0 = blockIdx.x * 32;

    #pragma unroll
    for (int i = 0; i < 16; i++) {
        int linear = i * 256 + threadIdx.x;
        int row = linear >> 7;
        int col = linear & 127;
        tile[row][col] = W[(size_t)(e0 + row) * HH + col];
    }
    __syncthreads();

    #pragma unroll
    for (int i = 0; i < 4; i++) {
        int linear = i * 256 + threadIdx.x;
        int h  = linear >> 3;
        int ec = linear & 7;
        __half h4[4];
        #pragma unroll
        for (int r = 0; r < 4; r++)
            h4[r] = __float2half_rn(tile[ec * 4 + r][h]);
        *(uint2*)&ow[(size_t)h * EE + e0 + ec * 4] = *(uint2*)h4;
    }
}

// ---------------------------------------------------------------------------
// proj_hmma: Y = X[16384,1024] @ W[1024,128], fp16 HMMA.
// FULLY ASYNC loads: A tile copied as raw fp32 via cp.async, converted
// smem->smem (each thread converts exactly the chunks it copied, so only
// cp.async.wait_group is needed before converting). One barrier per k-iter.
// ---------------------------------------------------------------------------
#define PA32 0
#define PA16 18432
#define PB   28672
#define P_BUF 38912
#define PROJ_SMEM 77824

__global__ __launch_bounds__(256, 2) void proj_hmma(
    const float* __restrict__ k_in, const float* __restrict__ q_in,
    const float* __restrict__ v_in)
{
    extern __shared__ char sm[];
    const uint32_t sbase = smem_u32(sm);
    const int t    = threadIdx.x;
    const int lane = t & 31;
    const int wid  = t >> 5;
    const int wm   = wid & 3;
    const int wn   = wid >> 2;
    const int p    = blockIdx.y;
    const int m0   = blockIdx.x * 128;

    const float* X = (p == 0) ? k_in : (p == 1) ? q_in : v_in;
    __half* Y = (p == 0) ? g_k : (p == 1) ? g_q : g_v;
    const __half* Wt = g_wt + (size_t)p * HH * EE;

    const uint32_t aoff = (uint32_t)((lane & 15) * 80 + (lane >> 4) * 16);
    const uint32_t boff = (uint32_t)((((lane & 7) | ((lane & 16) >> 1)) * 80) + (((lane >> 3) & 1) * 16));

    float acc[2][8][4];
    #pragma unroll
    for (int mb = 0; mb < 2; mb++)
        #pragma unroll
        for (int j = 0; j < 8; j++)
            #pragma unroll
            for (int i = 0; i < 4; i++) acc[mb][j][i] = 0.f;

    // async issue of tile kt into buffer buf: raw fp32 A + fp16 B
    auto issue_tile = [&](int kt, int buf) {
        uint32_t ubase = sbase + buf * P_BUF;
        #pragma unroll
        for (int i = 0; i < 4; i++) {       // A32: 128 rows x 8 chunks of 16B
            int linear = i * 256 + t;
            int c4  = linear & 7;
            int row = linear >> 3;
            cp16(ubase + PA32 + row * 144 + c4 * 16,
                 &X[(size_t)(m0 + row) * EE + kt * 32 + c4 * 4]);
        }
        #pragma unroll
        for (int i = 0; i < 2; i++) {       // B: 128 rows x 4 chunks of 16B
            int linear = i * 256 + t;
            int c4  = linear & 3;
            int row = linear >> 2;
            cp16(ubase + PB + row * 80 + c4 * 16, &Wt[(size_t)row * EE + kt * 32 + c4 * 8]);
        }
        CP_COMMIT();
    };

    // convert A32[buf] -> A16[buf]; each thread handles the chunks it copied
    auto convert_tile = [&](int buf) {
        char* base = sm + buf * P_BUF;
        #pragma unroll
        for (int i = 0; i < 4; i++) {
            int linear = i * 256 + t;
            int c4  = linear & 7;
            int row = linear >> 3;
            float4 f = *(float4*)(base + PA32 + row * 144 + c4 * 16);
            uint2 uh;
            uh.x = pack_half(f.x, f.y);
            uh.y = pack_half(f.z, f.w);
            *(uint2*)(base + PA16 + row * 80 + c4 * 8) = uh;
        }
    };

    issue_tile(0, 0);

    for (int kt = 0; kt < 32; kt++) {
        const int cur = kt & 1;
        const uint32_t sb = sbase + cur * P_BUF;
        CP_WAIT0();                 // own chunks of tile kt visible to this thread
        convert_tile(cur);          // convert own chunks (no barrier needed yet)
        if (kt < 31) issue_tile(kt + 1, cur ^ 1);
        __syncthreads();            // publish A16+B to all warps

        #pragma unroll
        for (int h = 0; h < 2; h++) {
            const uint32_t kb = h * 32;
            uint32_t ah[2][4];
            #pragma unroll
            for (int mb = 0; mb < 2; mb++) {
                uint32_t ra = (wm * 32 + mb * 16) * 80 + aoff + kb;
                ldsm4(ah[mb], sb + PA16 + ra);
            }
            #pragma unroll
            for (int jp = 0; jp < 4; jp++) {
                uint32_t b4[4];
                uint32_t rb = (wn * 64 + jp * 16) * 80 + boff + kb;
                ldsm4(b4, sb + PB + rb);
                #pragma unroll
                for (int mb = 0; mb < 2; mb++) {
                    mma16816h(acc[mb][2*jp],   ah[mb], b4[0], b4[1]);
                    mma16816h(acc[mb][2*jp+1], ah[mb], b4[2], b4[3]);
                }
            }
        }
        __syncthreads();            // all warps done reading buf before overwrite (kt+2)
    }

    const int g  = lane >> 2;
    const int q4 = lane & 3;
    #pragma unroll
    for (int mb = 0; mb < 2; mb++) {
        #pragma unroll
        for (int j = 0; j < 8; j++) {
            int gr  = m0 + wm * 32 + mb * 16 + g;
            int col = wn * 64 + j * 8 + q4 * 2;
            *(uint32_t*)&Y[(size_t)gr * HH + col] =
                pack_half(acc[mb][j][0], acc[mb][j][1]);
            *(uint32_t*)&Y[(size_t)(gr + 8) * HH + col] =
                pack_half(acc[mb][j][2], acc[mb][j][3]);
        }
    }
}

// ---------------------------------------------------------------------------
// flash_hmma: causal flash attention, fp16 MMA; ex2.approx softmax.
// 256 threads = 2 KV groups x 4 warps. BQ=64, BKV=32. K/V double-buffered.
// ---------------------------------------------------------------------------
#define FQ   0
#define FKV  17408          // + grp*34816
#define KBUF 0              // + par*8704
#define VBUF 17408          // + par*8704
#define FLASH_SMEM 87040

__global__ __launch_bounds__(256, 2) void flash_hmma(float* __restrict__ out)
{
    extern __shared__ char sm[];
    const uint32_t sbase = smem_u32(sm);
    const int t    = threadIdx.x;
    const int lane = t & 31;
    const int wid  = t >> 5;
    const int grp  = wid >> 2;
    const int wg   = wid & 3;
    const int gt   = t & 127;

    // SM-load-balanced bid -> (batch, qb): bid and bid+148 share an SM.
    int bid = blockIdx.x;
    int b, qb;
    if (bid >= 108 && bid < 148) {
        int s = bid - 108;
        qb = 63 - (s >> 2);
        b  = s & 3;
    } else {
        int r = (bid < 108) ? bid : (363 - bid);
        qb = 53 - (r >> 2);
        b  = r & 3;
    }

    const int q0   = qb * 64;
    const size_t bT = (size_t)b * TT;

    const uint32_t aoff = (uint32_t)((lane & 15) * 272 + (lane >> 4) * 16);
    const uint32_t boff = (uint32_t)((((lane & 7) | ((lane & 16) >> 1)) * 272) + (((lane >> 3) & 1) * 16));

    // ---- load Q tile (fp16, all 256 threads, cp.async) ----
    {
        const __half* qg = g_q + (bT + q0) * HH;
        #pragma unroll
        for (int i = 0; i < 4; i++) {
            int linear = i * 256 + t;
            int row = linear >> 4;
            int col = linear & 15;
            cp16(sbase + FQ + row * 272 + col * 16, &qg[(size_t)row * HH + col * 8]);
        }
        CP_COMMIT(); CP_WAIT0();
    }
    __syncthreads();

    float o[16][4];
    #pragma unroll
    for (int j = 0; j < 16; j++)
        #pragma unroll
        for (int i = 0; i < 4; i++) o[j][i] = 0.f;
    float m0 = -1e30f, m1 = -1e30f, l0 = 0.f, l1 = 0.f;

    const float scale_l2 = 0.088388347648318447f * 1.4426950408889634f;
    const int g   = lane >> 2;
    const int q4  = lane & 3;
    const int rg0 = q0 + wg * 16 + g;

    const uint32_t kvb = sbase + FKV + grp * 34816;
    const int nkb = 2 * qb + 2;
    const int barid = grp + 1;

    auto load_kv = [&](int kb, int par) {
        const size_t krow = bT + (size_t)kb * 32;
        uint32_t kd = kvb + KBUF + par * 8704;
        uint32_t vd = kvb + VBUF + par * 8704;
        #pragma unroll
        for (int i = 0; i < 4; i++) {
            int linear = i * 128 + gt;
            int row = linear >> 4;
            int col = linear & 15;
            uint32_t so = row * 272 + col * 16;
            size_t go = (krow + row) * HH + col * 8;
            cp16(kd + so, g_k + go);
            cp16(vd + so, g_v + go);
        }
    };

    if (grp < nkb) load_kv(grp, 0);
    CP_COMMIT();

    int par = 0;
    for (int kb = grp; kb < nkb; kb += 2, par ^= 1) {
        CP_WAIT0();
        BAR_GRP(barid);

        if (kb + 2 < nkb) load_kv(kb + 2, par ^ 1);
        CP_COMMIT();

        const uint32_t kcur = kvb + KBUF + par * 8704;
        const uint32_t vcur = kvb + VBUF + par * 8704;

        // ---- S = Q K^T (fp16), 32 KV cols ----
        float s[4][4];
        #pragma unroll
        for (int j = 0; j < 4; j++)
            #pragma unroll
            for (int i = 0; i < 4; i++) s[j][i] = 0.f;

        #pragma unroll
        for (int k16 = 0; k16 < 8; k16++) {
            uint32_t qa[4];
            uint32_t qr = wg * 16 * 272 + aoff + k16 * 32;
            ldsm4(qa, sbase + FQ + qr);
            #pragma unroll
            for (int jp = 0; jp < 2; jp++) {
                uint32_t k4[4];
                uint32_t kr = jp * 16 * 272 + boff + k16 * 32;
                ldsm4(k4, kcur + kr);
                mma16816h(s[2*jp],   qa, k4[0], k4[1]);
                mma16816h(s[2*jp+1], qa, k4[2], k4[3]);
            }
        }

        // ---- scale (log2 domain) + causal mask ----
        #pragma unroll
        for (int j = 0; j < 4; j++)
            #pragma unroll
            for (int i = 0; i < 4; i++) s[j][i] *= scale_l2;
        const int kv0 = kb * 32;
        if (kv0 + 31 > rg0) {
            int cbase = kv0 + q4 * 2;
            #pragma unroll
            for (int j = 0; j < 4; j++) {
                int c0 = cbase + j * 8;
                if (c0     > rg0)     s[j][0] = -1e30f;
                if (c0 + 1 > rg0)     s[j][1] = -1e30f;
                if (c0     > rg0 + 8) s[j][2] = -1e30f;
                if (c0 + 1 > rg0 + 8) s[j][3] = -1e30f;
            }
        }

        // ---- online softmax (rows g, g+8), exp2 domain, MUFU ----
        float mx0 = -1e30f, mx1 = -1e30f;
        #pragma unroll
        for (int j = 0; j < 4; j++) {
            mx0 = fmaxf(mx0, fmaxf(s[j][0], s[j][1]));
            mx1 = fmaxf(mx1, fmaxf(s[j][2], s[j][3]));
        }
        mx0 = fmaxf(mx0, __shfl_xor_sync(0xffffffffu, mx0, 1));
        mx0 = fmaxf(mx0, __shfl_xor_sync(0xffffffffu, mx0, 2));
        mx1 = fmaxf(mx1, __shfl_xor_sync(0xffffffffu, mx1, 1));
        mx1 = fmaxf(mx1, __shfl_xor_sync(0xffffffffu, mx1, 2));
        float m0n = fmaxf(m0, mx0), m1n = fmaxf(m1, mx1);

        bool nochange = (m0n == m0) & (m1n == m1);
        bool skip = __all_sync(0xffffffffu, nochange);
        float a0 = 1.f, a1 = 1.f;
        if (!skip) {
            a0 = ex2(m0 - m0n);
            a1 = ex2(m1 - m1n);
            #pragma unroll
            for (int j = 0; j < 16; j++) {
                o[j][0] *= a0; o[j][1] *= a0;
                o[j][2] *= a1; o[j][3] *= a1;
            }
        }
        m0 = m0n; m1 = m1n;

        float esub0 = fmaxf(m0n, -1e20f);
        float esub1 = fmaxf(m1n, -1e20f);

        // P -> single fp16
        uint32_t ph01[4], ph23[4];
        float sum0 = 0.f, sum1 = 0.f;
        #pragma unroll
        for (int j = 0; j < 4; j++) {
            float p0 = ex2(s[j][0] - esub0);
            float p1 = ex2(s[j][1] - esub0);
            float p2 = ex2(s[j][2] - esub1);
            float p3 = ex2(s[j][3] - esub1);
            sum0 += p0 + p1; sum1 += p2 + p3;
            ph01[j] = pack_half(p0, p1);
            ph23[j] = pack_half(p2, p3);
        }
        sum0 += __shfl_xor_sync(0xffffffffu, sum0, 1);
        sum0 += __shfl_xor_sync(0xffffffffu, sum0, 2);
        sum1 += __shfl_xor_sync(0xffffffffu, sum1, 1);
        sum1 += __shfl_xor_sync(0xffffffffu, sum1, 2);
        l0 = l0 * a0 + sum0;
        l1 = l1 * a1 + sum1;

        // ---- O += P V (fp16) ----
        #pragma unroll
        for (int ks = 0; ks < 2; ks++) {
            uint32_t pa[4] = { ph01[2*ks], ph23[2*ks], ph01[2*ks+1], ph23[2*ks+1] };
            #pragma unroll
            for (int hp = 0; hp < 8; hp++) {
                uint32_t vh4[4];
                uint32_t vr = ks * 16 * 272 + aoff + hp * 32;
                ldsm4t(vh4, vcur + vr);
                mma16816h(o[2*hp],   pa, vh4[0], vh4[1]);
                mma16816h(o[2*hp+1], pa, vh4[2], vh4[3]);
            }
        }
    }

    // ---- merge group states (group1 -> smem -> group0) ----
    __syncthreads();
    float* mrg = (float*)(sm + FKV);
    const int slot = (wg * 32 + lane) * 69;
    if (grp == 1) {
        float* d = mrg + slot;
        #pragma unroll
        for (int j = 0; j < 16; j++) {
            d[j*4+0] = o[j][0]; d[j*4+1] = o[j][1];
            d[j*4+2] = o[j][2]; d[j*4+3] = o[j][3];
        }
        d[64] = m0; d[65] = m1; d[66] = l0; d[67] = l1;
    }
    __syncthreads();
    if (grp == 0) {
        const float* s2 = mrg + slot;
        float mB0 = s2[64], mB1 = s2[65], lB0 = s2[66], lB1 = s2[67];
        float mS0 = fmaxf(m0, mB0), mS1 = fmaxf(m1, mB1);
        float wA0 = ex2(m0 - mS0), wB0 = ex2(mB0 - mS0);
        float wA1 = ex2(m1 - mS1), wB1 = ex2(mB1 - mS1);
        float inv0 = 1.f / (l0 * wA0 + lB0 * wB0);
        float inv1 = 1.f / (l1 * wA1 + lB1 * wB1);
        #pragma unroll
        for (int j = 0; j < 16; j++) {
            int col = j * 8 + q4 * 2;
            float2 v0, v1;
            v0.x = (o[j][0] * wA0 + s2[j*4+0] * wB0) * inv0;
            v0.y = (o[j][1] * wA0 + s2[j*4+1] * wB0) * inv0;
            v1.x = (o[j][2] * wA1 + s2[j*4+2] * wB1) * inv1;
            v1.y = (o[j][3] * wA1 + s2[j*4+3] * wB1) * inv1;
            *(float2*)&out[(bT + rg0) * HH + col]     = v0;
            *(float2*)&out[(bT + rg0 + 8) * HH + col] = v1;
        }
    }
}

// ---------------------------------------------------------------------------
extern "C" void kernel_launch(void* const* d_in, const int* in_sizes, int n_in,
                              void* d_out, int out_size)
{
    const float* k  = (const float*)d_in[0];
    const float* q  = (const float*)d_in[1];
    const float* v  = (const float*)d_in[2];
    const float* Wk = (const float*)d_in[3];
    const float* Wq = (const float*)d_in[4];
    const float* Wv = (const float*)d_in[5];
    float* out = (float*)d_out;

    prep_w<<<dim3(EE / 32, 3), 256>>>(Wk, Wq, Wv);

    cudaFuncSetAttribute(proj_hmma, cudaFuncAttributeMaxDynamicSharedMemorySize, PROJ_SMEM);
    proj_hmma<<<dim3(MTOT / 128, 3), 256, PROJ_SMEM>>>(k, q, v);

    cudaFuncSetAttribute(flash_hmma, cudaFuncAttributeMaxDynamicSharedMemorySize, FLASH_SMEM);
    flash_hmma<<<256, 256, FLASH_SMEM>>>(out);
}